// round 6
// baseline (speedup 1.0000x reference)
#include <cuda_runtime.h>
#include <cuda_bf16.h>
#include <math.h>
#include <stdint.h>

#define T_STEPS 128
#define B_ENV   128
#define HID     512
#define TBTOT   (T_STEPS * B_ENV)
#define ZD      8
#define AD      7
#define FE      128

typedef unsigned long long ull;

// ----------------------------------------------------------------------------
// Scratch (device globals; no allocation allowed)
// ----------------------------------------------------------------------------
__device__ float g_conv[TBTOT * 4096];
__device__ float g_h1[TBTOT * HID];
__device__ float g_h2[TBTOT * HID];
__device__ float g_xg[TBTOT * 2048];
__device__ float g_feat[TBTOT * HID];
__device__ float g_lf[TBTOT * FE];
__device__ ull g_hpA[64 * HID];          // h batch-pair packed [bp][k]
__device__ ull g_hpB[64 * HID];
__device__ ull g_cp[64 * HID];           // c batch-pair packed [bp][j]
__device__ ull g_whp[128 * 16 * 512];    // whh duplicated pairs per block chunk (8MB)
__device__ __nv_bfloat16 g_wfc1_hi[512 * 4096];
__device__ __nv_bfloat16 g_wfc1_lo[512 * 4096];
__device__ __nv_bfloat16 g_wfc2_hi[512 * 512];
__device__ __nv_bfloat16 g_wfc2_lo[512 * 512];
__device__ __nv_bfloat16 g_wih_hi[2048 * 512];
__device__ __nv_bfloat16 g_wih_lo[2048 * 512];
// conv weights, tap-major: [tap][co*16+ci] bf16 hi/lo
__device__ __nv_bfloat16 g_cw1h[25 * 256];
__device__ __nv_bfloat16 g_cw1l[25 * 256];
__device__ __nv_bfloat16 g_cw2h[9 * 256];
__device__ __nv_bfloat16 g_cw2l[9 * 256];
__device__ __nv_bfloat16 g_cw3h[9 * 256];
__device__ __nv_bfloat16 g_cw3l[9 * 256];

// ============================================================================
// Helpers
// ============================================================================
__device__ __forceinline__ uint32_t smem_to_u32(const void* smem_ptr) {
    uint32_t addr;
    asm("{ .reg .u64 tmp; cvta.to.shared.u64 tmp, %1; cvt.u32.u64 %0, tmp; }"
        : "=r"(addr) : "l"(smem_ptr));
    return addr;
}

__device__ __forceinline__ void ldsm4(uint32_t addr, uint32_t* r) {
    asm volatile("ldmatrix.sync.aligned.m8n8.x4.shared.b16 {%0,%1,%2,%3}, [%4];"
        : "=r"(r[0]), "=r"(r[1]), "=r"(r[2]), "=r"(r[3]) : "r"(addr));
}

__device__ __forceinline__ void mma16816(float* d, const uint32_t* a,
                                         const uint32_t* b) {
    asm volatile(
        "mma.sync.aligned.m16n8k16.row.col.f32.bf16.bf16.f32 "
        "{%0,%1,%2,%3}, {%4,%5,%6,%7}, {%8,%9}, {%0,%1,%2,%3};"
        : "+f"(d[0]), "+f"(d[1]), "+f"(d[2]), "+f"(d[3])
        : "r"(a[0]), "r"(a[1]), "r"(a[2]), "r"(a[3]), "r"(b[0]), "r"(b[1]));
}

__device__ __forceinline__ void ffma2(ull& d, ull a, ull b) {
    asm("fma.rn.f32x2 %0, %1, %2, %0;" : "+l"(d) : "l"(a), "l"(b));
}
__device__ __forceinline__ ull mul2(ull a, ull b) {
    ull r;
    asm("mul.rn.f32x2 %0, %1, %2;" : "=l"(r) : "l"(a), "l"(b));
    return r;
}
__device__ __forceinline__ ull fpack(float x, float y) {
    ull r;
    asm("mov.b64 %0, {%1, %2};" : "=l"(r) : "f"(x), "f"(y));
    return r;
}
__device__ __forceinline__ void funpack(ull a, float& x, float& y) {
    asm("mov.b64 {%0, %1}, %2;" : "=f"(x), "=f"(y) : "l"(a));
}

__device__ __forceinline__ void split2(float x, float y, uint32_t& hi, uint32_t& lo) {
    __nv_bfloat16 hx = __float2bfloat16(x), hy = __float2bfloat16(y);
    __nv_bfloat162 h2; h2.x = hx; h2.y = hy;
    hi = reinterpret_cast<uint32_t&>(h2);
    float lx = x - __bfloat162float(hx);
    float ly = y - __bfloat162float(hy);
    __nv_bfloat162 l2 = __floats2bfloat162_rn(lx, ly);
    lo = reinterpret_cast<uint32_t&>(l2);
}

// ----------------------------------------------------------------------------
// Weight prep kernels
// ----------------------------------------------------------------------------
__global__ void wprep(const float* __restrict__ w, __nv_bfloat16* __restrict__ hi,
                      __nv_bfloat16* __restrict__ lo, int total4) {
    int idx = blockIdx.x * blockDim.x + threadIdx.x;
    if (idx >= total4) return;
    float4 a = *(const float4*)(w + (size_t)idx * 4);
    uint32_t h0, h1, l0, l1;
    split2(a.x, a.y, h0, l0);
    split2(a.z, a.w, h1, l1);
    *(uint2*)(hi + (size_t)idx * 4) = make_uint2(h0, h1);
    *(uint2*)(lo + (size_t)idx * 4) = make_uint2(l0, l1);
}

__global__ void wcprep(const float* __restrict__ w, __nv_bfloat16* __restrict__ hi,
                       __nv_bfloat16* __restrict__ lo, int taps) {
    int idx = blockIdx.x * blockDim.x + threadIdx.x;
    if (idx >= taps * 256) return;
    int r = idx & 255;
    int t = idx >> 8;
    float v = w[r * taps + t];
    __nv_bfloat16 hv = __float2bfloat16(v);
    float lv = v - __bfloat162float(hv);
    hi[t * 256 + r] = hv;
    lo[t * 256 + r] = __float2bfloat16(lv);
}

// whh [2048][512] fp32 -> per-block duplicated pairs g_whp[bn][r=g*4+jj][k]
__global__ void whh_pair_prep(const float* __restrict__ whh) {
    int idx = blockIdx.x * blockDim.x + threadIdx.x;   // over 2048*128
    if (idx >= 2048 * 128) return;
    int wr = idx >> 7;
    int k4 = (idx & 127) * 4;
    int g = wr >> 9, j = wr & 511;
    int bn = j >> 2, jj = j & 3;
    int r = g * 4 + jj;
    float4 v = *(const float4*)(whh + (size_t)wr * 512 + k4);
    ull* dst = g_whp + ((size_t)(bn * 16 + r) * 512 + k4);
    dst[0] = fpack(v.x, v.x);
    dst[1] = fpack(v.y, v.y);
    dst[2] = fpack(v.z, v.z);
    dst[3] = fpack(v.w, v.w);
}

// pack h0/c0 into batch-pair layout
__global__ void pack_hc(const float* __restrict__ h0, const float* __restrict__ c0) {
    int i = blockIdx.x * blockDim.x + threadIdx.x;    // over 64*512
    if (i >= 64 * 512) return;
    int bp = i >> 9, k = i & 511;
    g_hpA[i] = fpack(h0[(2 * bp) * 512 + k], h0[(2 * bp + 1) * 512 + k]);
    g_cp[i]  = fpack(c0[(2 * bp) * 512 + k], c0[(2 * bp + 1) * 512 + k]);
}

// ----------------------------------------------------------------------------
// HMMA GEMM (proven): 3-term bf16 split, fp32 accum
// ----------------------------------------------------------------------------
#define SMSTR 80

template <int ACT>
__global__ __launch_bounds__(256) void tgemm(
    const float* __restrict__ A, const __nv_bfloat16* __restrict__ Whi,
    const __nv_bfloat16* __restrict__ Wlo,
    const float* __restrict__ bias, const float* __restrict__ bias2,
    float* __restrict__ C, int M, int N, int K) {
    extern __shared__ uint8_t sm[];
    const uint32_t oAh = 0, oAl = 10240, oBh = 20480, oBl = 30720;
    uint32_t sb = smem_to_u32(sm);
    int tid = threadIdx.x;
    int lane = tid & 31;
    int wid = tid >> 5;
    int wm = wid & 3, wn = wid >> 2;
    int m0 = blockIdx.y * 128, n0 = blockIdx.x * 128;
    const float* Ag = A + (size_t)m0 * K;

    float acc[2][8][4];
#pragma unroll
    for (int i = 0; i < 2; i++)
#pragma unroll
        for (int j = 0; j < 8; j++)
#pragma unroll
            for (int q = 0; q < 4; q++) acc[i][j][q] = 0.f;

    int nslab = K / 32;
    float4 aR[4];
    uint4 bRh[2], bRl[2];

    auto load_slab = [&](int s) {
#pragma unroll
        for (int i = 0; i < 4; i++) {
            int row = (tid >> 3) + 32 * i;
            aR[i] = *(const float4*)(Ag + (size_t)row * K + s * 32 + (tid & 7) * 4);
        }
#pragma unroll
        for (int i = 0; i < 2; i++) {
            int row = (tid >> 2) + 64 * i;
            size_t boff = ((size_t)(n0 + row) * K + s * 32);
            bRh[i] = *(const uint4*)((const uint8_t*)(Whi + boff) + (tid & 3) * 16);
            bRl[i] = *(const uint4*)((const uint8_t*)(Wlo + boff) + (tid & 3) * 16);
        }
    };
    auto store_slab = [&]() {
#pragma unroll
        for (int i = 0; i < 4; i++) {
            int row = (tid >> 3) + 32 * i;
            int col8 = (tid & 7) * 8;
            uint32_t h0, h1, l0, l1;
            split2(aR[i].x, aR[i].y, h0, l0);
            split2(aR[i].z, aR[i].w, h1, l1);
            *(uint2*)(sm + oAh + row * SMSTR + col8) = make_uint2(h0, h1);
            *(uint2*)(sm + oAl + row * SMSTR + col8) = make_uint2(l0, l1);
        }
#pragma unroll
        for (int i = 0; i < 2; i++) {
            int row = (tid >> 2) + 64 * i;
            int c16 = (tid & 3) * 16;
            *(uint4*)(sm + oBh + row * SMSTR + c16) = bRh[i];
            *(uint4*)(sm + oBl + row * SMSTR + c16) = bRl[i];
        }
    };

    load_slab(0);
    store_slab();
    __syncthreads();

    int g = lane >> 3;
    int arow_off = (lane & 7) + (g & 1) * 8;
    int akb_off = (g >> 1) * 16;
    int brow_off = (lane & 7) + (g >> 1) * 8;
    int bkb_off = (g & 1) * 16;

    for (int s = 0; s < nslab; s++) {
        bool more = (s + 1 < nslab);
        if (more) load_slab(s + 1);

#pragma unroll
        for (int kk2 = 0; kk2 < 2; kk2++) {
            int kb = kk2 * 32;
            uint32_t ah[2][4], al[2][4], bh[4][4], bl[4][4];
#pragma unroll
            for (int mi = 0; mi < 2; mi++) {
                uint32_t r = (uint32_t)((wm * 32 + mi * 16 + arow_off) * SMSTR +
                                        kb + akb_off);
                ldsm4(sb + oAh + r, ah[mi]);
                ldsm4(sb + oAl + r, al[mi]);
            }
#pragma unroll
            for (int pi = 0; pi < 4; pi++) {
                uint32_t r = (uint32_t)((wn * 64 + pi * 16 + brow_off) * SMSTR +
                                        kb + bkb_off);
                ldsm4(sb + oBh + r, bh[pi]);
                ldsm4(sb + oBl + r, bl[pi]);
            }
#pragma unroll
            for (int mi = 0; mi < 2; mi++)
#pragma unroll
                for (int pi = 0; pi < 4; pi++)
#pragma unroll
                    for (int half = 0; half < 2; half++) {
                        float* d = acc[mi][pi * 2 + half];
                        mma16816(d, ah[mi], &bh[pi][half * 2]);
                        mma16816(d, ah[mi], &bl[pi][half * 2]);
                        mma16816(d, al[mi], &bh[pi][half * 2]);
                    }
        }
        __syncthreads();
        if (more) {
            store_slab();
            __syncthreads();
        }
    }

    float* ct = (float*)sm;
#pragma unroll
    for (int mi = 0; mi < 2; mi++) {
        int r0 = wm * 32 + mi * 16 + (lane >> 2);
#pragma unroll
        for (int ni = 0; ni < 8; ni++) {
            int c = wn * 64 + ni * 8 + (lane & 3) * 2;
            float b0 = bias[n0 + c], b1 = bias[n0 + c + 1];
            if (bias2) { b0 += bias2[n0 + c]; b1 += bias2[n0 + c + 1]; }
            float v0 = acc[mi][ni][0] + b0;
            float v1 = acc[mi][ni][1] + b1;
            float v2 = acc[mi][ni][2] + b0;
            float v3 = acc[mi][ni][3] + b1;
            if (ACT) {
                v0 = v0 > 0.f ? v0 : 0.01f * v0;
                v1 = v1 > 0.f ? v1 : 0.01f * v1;
                v2 = v2 > 0.f ? v2 : 0.01f * v2;
                v3 = v3 > 0.f ? v3 : 0.01f * v3;
            }
            ct[r0 * 132 + c] = v0;
            ct[r0 * 132 + c + 1] = v1;
            ct[(r0 + 8) * 132 + c] = v2;
            ct[(r0 + 8) * 132 + c + 1] = v3;
        }
    }
    __syncthreads();
    {
        int r8 = tid >> 5;
        int c4 = (tid & 31) * 4;
#pragma unroll
        for (int p = 0; p < 16; p++) {
            int r = p * 8 + r8;
            float4 v = *(const float4*)(ct + r * 132 + c4);
            *(float4*)(C + (size_t)(m0 + r) * N + n0 + c4) = v;
        }
    }
}

// ----------------------------------------------------------------------------
// HMMA conv (unchanged from R5)
// ----------------------------------------------------------------------------
#define PSTR 48
#define IMG_BYTES (400 * PSTR)
#define CW_OFF   (2 * IMG_BYTES)
#define CW_HALF  12800

template <int KS, int P, int LAST>
__device__ __forceinline__ void conv_hmma_layer(
    uint8_t* csm, uint32_t sbase, const __nv_bfloat16* wsrc_h,
    const __nv_bfloat16* wsrc_l, const float* __restrict__ bias,
    float* gout, int tid, int lane, int wid) {
    const int taps = KS * KS;
    {
        const uint4* sh = (const uint4*)wsrc_h;
        const uint4* sl = (const uint4*)wsrc_l;
        uint4* dh = (uint4*)(csm + CW_OFF);
        uint4* dl = (uint4*)(csm + CW_OFF + CW_HALF);
        for (int i = tid; i < taps * 32; i += 256) {
            dh[i] = sh[i];
            dl[i] = sl[i];
        }
    }
    __syncthreads();

    float acc[2][2][4];
#pragma unroll
    for (int a = 0; a < 2; a++)
#pragma unroll
        for (int b = 0; b < 2; b++)
#pragma unroll
            for (int q = 0; q < 4; q++) acc[a][b][q] = 0.f;

    int g = lane >> 3;
    int h0 = wid * 2;
    uint32_t aoff[2];
#pragma unroll
    for (int mi = 0; mi < 2; mi++)
        aoff[mi] = (uint32_t)(((h0 + mi + 2) * 20 + 2 + (lane & 7) + (g & 1) * 8) * PSTR +
                              (g >> 1) * 16);
    uint32_t boff = (uint32_t)(((lane & 7) + (g >> 1) * 8) * 32 + (g & 1) * 16);
    uint32_t wb_h = sbase + CW_OFF;
    uint32_t wb_l = sbase + CW_OFF + CW_HALF;

#pragma unroll
    for (int kh = 0; kh < KS; kh++) {
#pragma unroll
        for (int kw = 0; kw < KS; kw++) {
            int t = kh * KS + kw;
            int shift = ((kh - P) * 20 + (kw - P)) * PSTR;
            uint32_t bh4[4], bl4[4];
            ldsm4(wb_h + t * 512 + boff, bh4);
            ldsm4(wb_l + t * 512 + boff, bl4);
#pragma unroll
            for (int mi = 0; mi < 2; mi++) {
                uint32_t ah[4], al[4];
                ldsm4(sbase + aoff[mi] + shift, ah);
                ldsm4(sbase + IMG_BYTES + aoff[mi] + shift, al);
#pragma unroll
                for (int nh = 0; nh < 2; nh++) {
                    mma16816(acc[mi][nh], ah, &bh4[nh * 2]);
                    mma16816(acc[mi][nh], ah, &bl4[nh * 2]);
                    mma16816(acc[mi][nh], al, &bh4[nh * 2]);
                }
            }
        }
    }
    __syncthreads();

#pragma unroll
    for (int mi = 0; mi < 2; mi++) {
        int h = h0 + mi;
#pragma unroll
        for (int nh = 0; nh < 2; nh++) {
            int co = nh * 8 + (lane & 3) * 2;
            float b0 = bias[co], b1 = bias[co + 1];
#pragma unroll
            for (int rr = 0; rr < 2; rr++) {
                int w = (lane >> 2) + rr * 8;
                float v0 = acc[mi][nh][rr * 2 + 0] + b0;
                float v1 = acc[mi][nh][rr * 2 + 1] + b1;
                v0 = v0 > 0.f ? v0 : 0.01f * v0;
                v1 = v1 > 0.f ? v1 : 0.01f * v1;
                if (LAST) {
                    gout[co * 256 + h * 16 + w] = v0;
                    gout[(co + 1) * 256 + h * 16 + w] = v1;
                } else {
                    uint32_t hp, lp;
                    split2(v0, v1, hp, lp);
                    int pb = ((h + 2) * 20 + (w + 2)) * PSTR + co * 2;
                    *(uint32_t*)(csm + pb) = hp;
                    *(uint32_t*)(csm + IMG_BYTES + pb) = lp;
                }
            }
        }
    }
    __syncthreads();
}

__global__ __launch_bounds__(256) void conv3_mma(
    const float* __restrict__ x,
    const float* __restrict__ b1, const float* __restrict__ b2,
    const float* __restrict__ b3) {
    extern __shared__ uint8_t csm[];
    uint32_t sbase = smem_to_u32(csm);
    int tid = threadIdx.x;
    int lane = tid & 31;
    int wid = tid >> 5;
    int img = blockIdx.x;
    const float* xi = x + (size_t)img * 4096;

    for (int i = tid; i < 2 * IMG_BYTES / 4; i += 256)
        ((uint32_t*)csm)[i] = 0;
    __syncthreads();
    for (int i = tid; i < 4096; i += 256) {
        int ci = i >> 8, p = i & 255;
        int h = p >> 4, w = p & 15;
        float v = xi[i];
        __nv_bfloat16 hv = __float2bfloat16(v);
        float lv = v - __bfloat162float(hv);
        int pb = ((h + 2) * 20 + (w + 2)) * PSTR + ci * 2;
        *(__nv_bfloat16*)(csm + pb) = hv;
        *(__nv_bfloat16*)(csm + IMG_BYTES + pb) = __float2bfloat16(lv);
    }
    __syncthreads();

    float* gout = g_conv + (size_t)img * 4096;
    conv_hmma_layer<5, 2, 0>(csm, sbase, g_cw1h, g_cw1l, b1, gout, tid, lane, wid);
    conv_hmma_layer<3, 1, 0>(csm, sbase, g_cw2h, g_cw2l, b2, gout, tid, lane, wid);
    conv_hmma_layer<3, 1, 1>(csm, sbase, g_cw3h, g_cw3l, b3, gout, tid, lane, wid);
}

// ----------------------------------------------------------------------------
// Scalar SGEMM kept for lofeat (with z one-hot epilogue)
// ----------------------------------------------------------------------------
template <int ACT, int ZMODE>
__global__ __launch_bounds__(256, 2) void sgemm128(
    const float* __restrict__ A, const float* __restrict__ B,
    const float* __restrict__ bias, const float* __restrict__ bias2,
    float* __restrict__ C, int M, int N, int K, int ldb,
    const int* __restrict__ z) {
    __shared__ float As[8 * 132];
    __shared__ float Bs[8 * 132];
    int tid = threadIdx.x;
    int tx = tid & 15, ty = tid >> 4;
    int row0 = blockIdx.y * 128;
    int col0 = blockIdx.x * 128;
    const float* Ag = A + (size_t)row0 * K;
    const float* Bg = B + (size_t)col0 * ldb;
    int lr = tid >> 1;
    int lc = (tid & 1) * 4;

    float acc[8][8];
#pragma unroll
    for (int i = 0; i < 8; i++)
#pragma unroll
        for (int j = 0; j < 8; j++) acc[i][j] = 0.f;

    for (int k0 = 0; k0 < K; k0 += 8) {
        float4 a4 = *(const float4*)(Ag + (size_t)lr * K + k0 + lc);
        float4 b4 = *(const float4*)(Bg + (size_t)lr * ldb + k0 + lc);
        As[(lc + 0) * 132 + lr] = a4.x;
        As[(lc + 1) * 132 + lr] = a4.y;
        As[(lc + 2) * 132 + lr] = a4.z;
        As[(lc + 3) * 132 + lr] = a4.w;
        Bs[(lc + 0) * 132 + lr] = b4.x;
        Bs[(lc + 1) * 132 + lr] = b4.y;
        Bs[(lc + 2) * 132 + lr] = b4.z;
        Bs[(lc + 3) * 132 + lr] = b4.w;
        __syncthreads();
#pragma unroll
        for (int k = 0; k < 8; k++) {
            float4 a0 = *(const float4*)(As + k * 132 + ty * 4);
            float4 a1 = *(const float4*)(As + k * 132 + 64 + ty * 4);
            float4 b0 = *(const float4*)(Bs + k * 132 + tx * 4);
            float4 b1 = *(const float4*)(Bs + k * 132 + 64 + tx * 4);
            float av[8] = {a0.x, a0.y, a0.z, a0.w, a1.x, a1.y, a1.z, a1.w};
            float bv[8] = {b0.x, b0.y, b0.z, b0.w, b1.x, b1.y, b1.z, b1.w};
#pragma unroll
            for (int i = 0; i < 8; i++)
#pragma unroll
                for (int j = 0; j < 8; j++)
                    acc[i][j] = fmaf(av[i], bv[j], acc[i][j]);
        }
        __syncthreads();
    }

#pragma unroll
    for (int i = 0; i < 8; i++) {
        int m = row0 + ((i < 4) ? (ty * 4 + i) : (64 + ty * 4 + i - 4));
        int zi = 0;
        if (ZMODE) zi = 512 + z[m];
#pragma unroll
        for (int j = 0; j < 8; j++) {
            int n = col0 + ((j < 4) ? (tx * 4 + j) : (64 + tx * 4 + j - 4));
            float v = acc[i][j] + bias[n];
            if (bias2) v += bias2[n];
            if (ZMODE) v += B[(size_t)n * ldb + zi];
            if (ACT) v = v > 0.f ? v : 0.01f * v;
            C[(size_t)m * N + n] = v;
        }
    }
}

// ----------------------------------------------------------------------------
// LSTM step v3: f32x2 packed batch pairs, pair layouts end-to-end.
// 128 blocks (4 j each), 256 threads = (bp = tid>>2, jj = tid&3).
// ----------------------------------------------------------------------------
__device__ __forceinline__ float sigm(float x) { return 1.f / (1.f + expf(-x)); }

#define LS_WSTR 516
#define LS_HSTR 34
#define LS_SMEM ((16 * LS_WSTR + 2 * 64 * LS_HSTR + 64) * 8)

__global__ __launch_bounds__(256) void lstm_step3(
    const float* __restrict__ xg, const int* __restrict__ done,
    const ull* __restrict__ hp_in, ull* __restrict__ hp_out,
    float* __restrict__ feat, int t) {
    extern __shared__ ull lsm[];
    ull* s_w  = lsm;                       // 16 x 516
    ull* s_h  = lsm + 16 * LS_WSTR;        // 2 x 64 x 34
    ull* s_mp = s_h + 2 * 64 * LS_HSTR;    // 64

    int tid = threadIdx.x;
    int bn = blockIdx.x;
    int j0 = bn * 4;
    int jj = tid & 3;
    int bp = tid >> 2;

    // masks
    if (tid < 64) {
        int d0 = done[t * 128 + 2 * tid];
        int d1 = done[t * 128 + 2 * tid + 1];
        s_mp[tid] = fpack(1.f - (float)d0, 1.f - (float)d1);
    }
    // resident duplicated weights (uint4 stream, no packing)
    {
        const uint4* src = (const uint4*)(g_whp + (size_t)bn * 16 * 512);
#pragma unroll
        for (int i = 0; i < 16; i++) {
            int i4 = tid + 256 * i;          // 4096 uint4 total
            int r = i4 >> 8, kp = i4 & 255;
            *(uint4*)(s_w + r * LS_WSTR + kp * 2) = src[i4];
        }
    }
    // acc init from xg (includes both biases)
    ull acc[4];
#pragma unroll
    for (int g = 0; g < 4; g++) {
        float x0 = xg[(size_t)(t * 128 + 2 * bp) * 2048 + g * 512 + j0 + jj];
        float x1 = xg[(size_t)(t * 128 + 2 * bp + 1) * 2048 + g * 512 + j0 + jj];
        acc[g] = fpack(x0, x1);
    }
    __syncthreads();   // masks + weights visible

    // staging thread map: (sbp = tid>>2, ch = tid&3), 8 k per thread
    int sbp = tid >> 2, ch = tid & 3;
    auto stage = [&](int s, int buf) {
        ull m = s_mp[sbp];
        const ull* src = hp_in + (size_t)sbp * 512 + s * 32 + ch * 8;
        ull* dst = s_h + buf * 64 * LS_HSTR + sbp * LS_HSTR + ch * 8;
#pragma unroll
        for (int i = 0; i < 4; i++) {
            ulonglong2 v = *(const ulonglong2*)(src + 2 * i);
            v.x = mul2(v.x, m);
            v.y = mul2(v.y, m);
            *(ulonglong2*)(dst + 2 * i) = v;
        }
    };

    stage(0, 0);
    __syncthreads();

    for (int s = 0; s < 16; s++) {
        if (s < 15) stage(s + 1, (s + 1) & 1);
        const ull* hb = s_h + (s & 1) * 64 * LS_HSTR + bp * LS_HSTR;
#pragma unroll
        for (int kq = 0; kq < 8; kq++) {
            ulonglong2 h01 = *(const ulonglong2*)(hb + kq * 4);
            ulonglong2 h23 = *(const ulonglong2*)(hb + kq * 4 + 2);
#pragma unroll
            for (int g = 0; g < 4; g++) {
                const ull* wp = s_w + (g * 4 + jj) * LS_WSTR + s * 32 + kq * 4;
                ulonglong2 w01 = *(const ulonglong2*)wp;
                ulonglong2 w23 = *(const ulonglong2*)(wp + 2);
                ffma2(acc[g], h01.x, w01.x);
                ffma2(acc[g], h01.y, w01.y);
                ffma2(acc[g], h23.x, w23.x);
                ffma2(acc[g], h23.y, w23.y);
            }
        }
        __syncthreads();
    }

    // epilogue: gate nonlinearity per batch component
    int j = j0 + jj;
    ull cold = g_cp[(size_t)bp * 512 + j];
    float c0f, c1f, m0, m1;
    funpack(cold, c0f, c1f);
    funpack(s_mp[bp], m0, m1);
    float i0, i1, f0, f1, g0, g1, o0, o1;
    funpack(acc[0], i0, i1);
    funpack(acc[1], f0, f1);
    funpack(acc[2], g0, g1);
    funpack(acc[3], o0, o1);
    float cn0 = sigm(f0) * (c0f * m0) + sigm(i0) * tanhf(g0);
    float cn1 = sigm(f1) * (c1f * m1) + sigm(i1) * tanhf(g1);
    float hn0 = sigm(o0) * tanhf(cn0);
    float hn1 = sigm(o1) * tanhf(cn1);
    g_cp[(size_t)bp * 512 + j] = fpack(cn0, cn1);
    hp_out[(size_t)bp * 512 + j] = fpack(hn0, hn1);
    feat[(size_t)(t * 128 + 2 * bp) * 512 + j] = hn0;
    feat[(size_t)(t * 128 + 2 * bp + 1) * 512 + j] = hn1;
}

// ----------------------------------------------------------------------------
// Head: warp per row; actor/critic GEMV + log_softmax/entropy/prob pack.
// ----------------------------------------------------------------------------
__global__ __launch_bounds__(256) void head_kernel(
    const float* __restrict__ lf, const float* __restrict__ aw,
    const float* __restrict__ ab, const float* __restrict__ cw,
    const float* __restrict__ cb, const int* __restrict__ action,
    float* __restrict__ out) {
    int warp = (blockIdx.x * blockDim.x + threadIdx.x) >> 5;
    int lane = threadIdx.x & 31;
    if (warp >= TBTOT) return;
    float4 f = *(const float4*)(lf + (size_t)warp * FE + lane * 4);
    float r[8];
#pragma unroll
    for (int a = 0; a < 7; a++) {
        float4 w = *(const float4*)(aw + a * FE + lane * 4);
        r[a] = f.x * w.x + f.y * w.y + f.z * w.z + f.w * w.w;
    }
    {
        float4 w = *(const float4*)(cw + lane * 4);
        r[7] = f.x * w.x + f.y * w.y + f.z * w.z + f.w * w.w;
    }
#pragma unroll
    for (int a = 0; a < 8; a++)
#pragma unroll
        for (int s = 16; s > 0; s >>= 1)
            r[a] += __shfl_xor_sync(0xffffffffu, r[a], s);

    if (lane == 0) {
        float lg[7];
        float mx = -1e30f;
#pragma unroll
        for (int a = 0; a < 7; a++) {
            lg[a] = r[a] + ab[a];
            mx = fmaxf(mx, lg[a]);
        }
        float se = 0.f;
        float e[7];
#pragma unroll
        for (int a = 0; a < 7; a++) {
            e[a] = expf(lg[a] - mx);
            se += e[a];
        }
        float lse = mx + logf(se);
        float inv = 1.f / se;
        float ent = 0.f;
        float* o = out + (size_t)warp * 10;
#pragma unroll
        for (int a = 0; a < 7; a++) {
            float p = e[a] * inv;
            float lp = lg[a] - lse;
            ent -= p * lp;
            o[3 + a] = p;
        }
        int act = action[warp];
        o[0] = lg[act] - lse;
        o[1] = ent;
        o[2] = r[7] + cb[0];
    }
}

// ----------------------------------------------------------------------------
// Launch
// ----------------------------------------------------------------------------
extern "C" void kernel_launch(void* const* d_in, const int* in_sizes, int n_in,
                              void* d_out, int out_size) {
    const float* x    = (const float*)d_in[0];
    const int* done   = (const int*)d_in[1];
    const int* z      = (const int*)d_in[2];
    const int* action = (const int*)d_in[3];
    const float* h0   = (const float*)d_in[4];
    const float* c0   = (const float*)d_in[5];
    const float* c1w = (const float*)d_in[6];  const float* c1b = (const float*)d_in[7];
    const float* c2w = (const float*)d_in[8];  const float* c2b = (const float*)d_in[9];
    const float* c3w = (const float*)d_in[10]; const float* c3b = (const float*)d_in[11];
    const float* fc1w = (const float*)d_in[12]; const float* fc1b = (const float*)d_in[13];
    const float* fc2w = (const float*)d_in[14]; const float* fc2b = (const float*)d_in[15];
    const float* wih = (const float*)d_in[16]; const float* whh = (const float*)d_in[17];
    const float* bih = (const float*)d_in[18]; const float* bhh = (const float*)d_in[19];
    const float* lfw = (const float*)d_in[20]; const float* lfb = (const float*)d_in[21];
    const float* aw = (const float*)d_in[22];  const float* ab = (const float*)d_in[23];
    const float* cw = (const float*)d_in[24];  const float* cb = (const float*)d_in[25];
    float* out = (float*)d_out;

    float *pconv, *ph1, *ph2, *pxg, *pfeat, *plf;
    ull *phpA, *phpB;
    __nv_bfloat16 *pw1h, *pw1l, *pw2h, *pw2l, *pwih_h, *pwih_l;
    __nv_bfloat16 *pc1h, *pc1l, *pc2h, *pc2l, *pc3h, *pc3l;
    cudaGetSymbolAddress((void**)&pconv, g_conv);
    cudaGetSymbolAddress((void**)&ph1, g_h1);
    cudaGetSymbolAddress((void**)&ph2, g_h2);
    cudaGetSymbolAddress((void**)&pxg, g_xg);
    cudaGetSymbolAddress((void**)&pfeat, g_feat);
    cudaGetSymbolAddress((void**)&plf, g_lf);
    cudaGetSymbolAddress((void**)&phpA, g_hpA);
    cudaGetSymbolAddress((void**)&phpB, g_hpB);
    cudaGetSymbolAddress((void**)&pw1h, g_wfc1_hi);
    cudaGetSymbolAddress((void**)&pw1l, g_wfc1_lo);
    cudaGetSymbolAddress((void**)&pw2h, g_wfc2_hi);
    cudaGetSymbolAddress((void**)&pw2l, g_wfc2_lo);
    cudaGetSymbolAddress((void**)&pwih_h, g_wih_hi);
    cudaGetSymbolAddress((void**)&pwih_l, g_wih_lo);
    cudaGetSymbolAddress((void**)&pc1h, g_cw1h);
    cudaGetSymbolAddress((void**)&pc1l, g_cw1l);
    cudaGetSymbolAddress((void**)&pc2h, g_cw2h);
    cudaGetSymbolAddress((void**)&pc2l, g_cw2l);
    cudaGetSymbolAddress((void**)&pc3h, g_cw3h);
    cudaGetSymbolAddress((void**)&pc3l, g_cw3l);

    const int SMEM_TG = 128 * 132 * 4;
    cudaFuncSetAttribute(tgemm<1>, cudaFuncAttributeMaxDynamicSharedMemorySize, SMEM_TG);
    cudaFuncSetAttribute(tgemm<0>, cudaFuncAttributeMaxDynamicSharedMemorySize, SMEM_TG);
    const int SMEM_CONV = 2 * IMG_BYTES + 2 * CW_HALF;
    cudaFuncSetAttribute(conv3_mma, cudaFuncAttributeMaxDynamicSharedMemorySize, SMEM_CONV);
    cudaFuncSetAttribute(lstm_step3, cudaFuncAttributeMaxDynamicSharedMemorySize, LS_SMEM);

    // ---- launch order arranged so launch #6 (profiled) is tgemm fc1 ----
    wcprep<<<25, 256>>>(c1w, pc1h, pc1l, 25);                        // 1
    wcprep<<<9, 256>>>(c2w, pc2h, pc2l, 9);                          // 2
    wcprep<<<9, 256>>>(c3w, pc3h, pc3l, 9);                          // 3
    conv3_mma<<<TBTOT, 256, SMEM_CONV>>>(x, c1b, c2b, c3b);          // 4
    wprep<<<(512 * 1024 + 255) / 256, 256>>>(fc1w, pw1h, pw1l, 512 * 1024);  // 5
    tgemm<1><<<dim3(512 / 128, TBTOT / 128), 256, SMEM_TG>>>(        // 6 <- profiled
        pconv, pw1h, pw1l, fc1b, nullptr, ph1, TBTOT, 512, 4096);

    wprep<<<(512 * 128 + 255) / 256, 256>>>(fc2w, pw2h, pw2l, 512 * 128);
    wprep<<<(2048 * 128 + 255) / 256, 256>>>(wih, pwih_h, pwih_l, 2048 * 128);
    whh_pair_prep<<<(2048 * 128 + 255) / 256, 256>>>(whh);
    pack_hc<<<(64 * 512 + 255) / 256, 256>>>(h0, c0);

    tgemm<1><<<dim3(512 / 128, TBTOT / 128), 256, SMEM_TG>>>(
        ph1, pw2h, pw2l, fc2b, nullptr, ph2, TBTOT, 512, 512);
    tgemm<0><<<dim3(2048 / 128, TBTOT / 128), 256, SMEM_TG>>>(
        ph2, pwih_h, pwih_l, bih, bhh, pxg, TBTOT, 2048, 512);

    // sequential recurrence, ping-pong packed h
    for (int t = 0; t < T_STEPS; t++) {
        ull* hin = (t & 1) ? phpB : phpA;
        ull* hout = (t & 1) ? phpA : phpB;
        lstm_step3<<<128, 256, LS_SMEM>>>(pxg, done, hin, hout, pfeat, t);
    }

    // lofeat: feat(512) + one-hot(z) via epilogue, ldb=520, leaky
    sgemm128<1, 1><<<dim3(FE / 128, TBTOT / 128), 256>>>(
        pfeat, lfw, lfb, nullptr, plf, TBTOT, FE, 512, 520, z);

    // heads + softmax stats
    head_kernel<<<TBTOT / 8, 256>>>(plf, aw, ab, cw, cb, action, out);
}

// round 7
// speedup vs baseline: 1.3200x; 1.3200x over previous
#include <cuda_runtime.h>
#include <cuda_bf16.h>
#include <math.h>
#include <stdint.h>

#define T_STEPS 128
#define B_ENV   128
#define HID     512
#define TBTOT   (T_STEPS * B_ENV)
#define ZD      8
#define AD      7
#define FE      128

// ----------------------------------------------------------------------------
// Scratch (device globals; no allocation allowed)
// ----------------------------------------------------------------------------
__device__ float g_conv[TBTOT * 4096];
__device__ float g_h1[TBTOT * HID];
__device__ float g_h2[TBTOT * HID];
__device__ float g_xg[TBTOT * 2048];
__device__ float g_feat[TBTOT * HID];
__device__ float g_lf[TBTOT * FE];
__device__ float g_cst[B_ENV * HID];
// LSTM h state, bf16 hi/lo split, ping-pong
__device__ __nv_bfloat16 g_hhA[B_ENV * HID];
__device__ __nv_bfloat16 g_hlA[B_ENV * HID];
__device__ __nv_bfloat16 g_hhB[B_ENV * HID];
__device__ __nv_bfloat16 g_hlB[B_ENV * HID];
// W_hh reordered per block: [blk 64][row = g*8+jj (32)][k 512] bf16 hi/lo
__device__ __nv_bfloat16 g_wlh[64 * 32 * 512];
__device__ __nv_bfloat16 g_wll[64 * 32 * 512];
__device__ __nv_bfloat16 g_wfc1_hi[512 * 4096];
__device__ __nv_bfloat16 g_wfc1_lo[512 * 4096];
__device__ __nv_bfloat16 g_wfc2_hi[512 * 512];
__device__ __nv_bfloat16 g_wfc2_lo[512 * 512];
__device__ __nv_bfloat16 g_wih_hi[2048 * 512];
__device__ __nv_bfloat16 g_wih_lo[2048 * 512];
// conv weights, tap-major: [tap][co*16+ci] bf16 hi/lo
__device__ __nv_bfloat16 g_cw1h[25 * 256];
__device__ __nv_bfloat16 g_cw1l[25 * 256];
__device__ __nv_bfloat16 g_cw2h[9 * 256];
__device__ __nv_bfloat16 g_cw2l[9 * 256];
__device__ __nv_bfloat16 g_cw3h[9 * 256];
__device__ __nv_bfloat16 g_cw3l[9 * 256];

// ============================================================================
// Helpers
// ============================================================================
__device__ __forceinline__ uint32_t smem_to_u32(const void* smem_ptr) {
    uint32_t addr;
    asm("{ .reg .u64 tmp; cvta.to.shared.u64 tmp, %1; cvt.u32.u64 %0, tmp; }"
        : "=r"(addr) : "l"(smem_ptr));
    return addr;
}

__device__ __forceinline__ void ldsm4(uint32_t addr, uint32_t* r) {
    asm volatile("ldmatrix.sync.aligned.m8n8.x4.shared.b16 {%0,%1,%2,%3}, [%4];"
        : "=r"(r[0]), "=r"(r[1]), "=r"(r[2]), "=r"(r[3]) : "r"(addr));
}

__device__ __forceinline__ void mma16816(float* d, const uint32_t* a,
                                         const uint32_t* b) {
    asm volatile(
        "mma.sync.aligned.m16n8k16.row.col.f32.bf16.bf16.f32 "
        "{%0,%1,%2,%3}, {%4,%5,%6,%7}, {%8,%9}, {%0,%1,%2,%3};"
        : "+f"(d[0]), "+f"(d[1]), "+f"(d[2]), "+f"(d[3])
        : "r"(a[0]), "r"(a[1]), "r"(a[2]), "r"(a[3]), "r"(b[0]), "r"(b[1]));
}

__device__ __forceinline__ void split2(float x, float y, uint32_t& hi, uint32_t& lo) {
    __nv_bfloat16 hx = __float2bfloat16(x), hy = __float2bfloat16(y);
    __nv_bfloat162 h2; h2.x = hx; h2.y = hy;
    hi = reinterpret_cast<uint32_t&>(h2);
    float lx = x - __bfloat162float(hx);
    float ly = y - __bfloat162float(hy);
    __nv_bfloat162 l2 = __floats2bfloat162_rn(lx, ly);
    lo = reinterpret_cast<uint32_t&>(l2);
}

// ----------------------------------------------------------------------------
// Weight prep kernels
// ----------------------------------------------------------------------------
__global__ void wprep(const float* __restrict__ w, __nv_bfloat16* __restrict__ hi,
                      __nv_bfloat16* __restrict__ lo, int total4) {
    int idx = blockIdx.x * blockDim.x + threadIdx.x;
    if (idx >= total4) return;
    float4 a = *(const float4*)(w + (size_t)idx * 4);
    uint32_t h0, h1, l0, l1;
    split2(a.x, a.y, h0, l0);
    split2(a.z, a.w, h1, l1);
    *(uint2*)(hi + (size_t)idx * 4) = make_uint2(h0, h1);
    *(uint2*)(lo + (size_t)idx * 4) = make_uint2(l0, l1);
}

__global__ void wcprep(const float* __restrict__ w, __nv_bfloat16* __restrict__ hi,
                       __nv_bfloat16* __restrict__ lo, int taps) {
    int idx = blockIdx.x * blockDim.x + threadIdx.x;
    if (idx >= taps * 256) return;
    int r = idx & 255;
    int t = idx >> 8;
    float v = w[r * taps + t];
    __nv_bfloat16 hv = __float2bfloat16(v);
    float lv = v - __bfloat162float(hv);
    hi[t * 256 + r] = hv;
    lo[t * 256 + r] = __float2bfloat16(lv);
}

// whh [2048][512] -> per-block reorder: dst row (blk*32 + g*8 + jj), bf16 hi/lo
__global__ void wlstm_prep(const float* __restrict__ whh) {
    int idx = blockIdx.x * blockDim.x + threadIdx.x;   // over 2048*128
    if (idx >= 2048 * 128) return;
    int row = idx >> 7;
    int k4 = (idx & 127) * 4;
    int g = row >> 9, j = row & 511;
    int blk = j >> 3, jj = j & 7;
    size_t dst = ((size_t)(blk * 32 + g * 8 + jj)) * 512 + k4;
    float4 v = *(const float4*)(whh + (size_t)row * 512 + k4);
    uint32_t h0, h1, l0, l1;
    split2(v.x, v.y, h0, l0);
    split2(v.z, v.w, h1, l1);
    *(uint2*)(g_wlh + dst) = make_uint2(h0, h1);
    *(uint2*)(g_wll + dst) = make_uint2(l0, l1);
}

// pack h0 into bf16 hi/lo
__global__ void pack_h0(const float* __restrict__ h0) {
    int i = blockIdx.x * blockDim.x + threadIdx.x;
    if (i >= B_ENV * HID) return;
    float v = h0[i];
    __nv_bfloat16 hv = __float2bfloat16(v);
    g_hhA[i] = hv;
    g_hlA[i] = __float2bfloat16(v - __bfloat162float(hv));
}

// ----------------------------------------------------------------------------
// HMMA GEMM (proven): 3-term bf16 split, fp32 accum
// ----------------------------------------------------------------------------
#define SMSTR 80

template <int ACT>
__global__ __launch_bounds__(256) void tgemm(
    const float* __restrict__ A, const __nv_bfloat16* __restrict__ Whi,
    const __nv_bfloat16* __restrict__ Wlo,
    const float* __restrict__ bias, const float* __restrict__ bias2,
    float* __restrict__ C, int M, int N, int K) {
    extern __shared__ uint8_t sm[];
    const uint32_t oAh = 0, oAl = 10240, oBh = 20480, oBl = 30720;
    uint32_t sb = smem_to_u32(sm);
    int tid = threadIdx.x;
    int lane = tid & 31;
    int wid = tid >> 5;
    int wm = wid & 3, wn = wid >> 2;
    int m0 = blockIdx.y * 128, n0 = blockIdx.x * 128;
    const float* Ag = A + (size_t)m0 * K;

    float acc[2][8][4];
#pragma unroll
    for (int i = 0; i < 2; i++)
#pragma unroll
        for (int j = 0; j < 8; j++)
#pragma unroll
            for (int q = 0; q < 4; q++) acc[i][j][q] = 0.f;

    int nslab = K / 32;
    float4 aR[4];
    uint4 bRh[2], bRl[2];

    auto load_slab = [&](int s) {
#pragma unroll
        for (int i = 0; i < 4; i++) {
            int row = (tid >> 3) + 32 * i;
            aR[i] = *(const float4*)(Ag + (size_t)row * K + s * 32 + (tid & 7) * 4);
        }
#pragma unroll
        for (int i = 0; i < 2; i++) {
            int row = (tid >> 2) + 64 * i;
            size_t boff = ((size_t)(n0 + row) * K + s * 32);
            bRh[i] = *(const uint4*)((const uint8_t*)(Whi + boff) + (tid & 3) * 16);
            bRl[i] = *(const uint4*)((const uint8_t*)(Wlo + boff) + (tid & 3) * 16);
        }
    };
    auto store_slab = [&]() {
#pragma unroll
        for (int i = 0; i < 4; i++) {
            int row = (tid >> 3) + 32 * i;
            int col8 = (tid & 7) * 8;
            uint32_t h0, h1, l0, l1;
            split2(aR[i].x, aR[i].y, h0, l0);
            split2(aR[i].z, aR[i].w, h1, l1);
            *(uint2*)(sm + oAh + row * SMSTR + col8) = make_uint2(h0, h1);
            *(uint2*)(sm + oAl + row * SMSTR + col8) = make_uint2(l0, l1);
        }
#pragma unroll
        for (int i = 0; i < 2; i++) {
            int row = (tid >> 2) + 64 * i;
            int c16 = (tid & 3) * 16;
            *(uint4*)(sm + oBh + row * SMSTR + c16) = bRh[i];
            *(uint4*)(sm + oBl + row * SMSTR + c16) = bRl[i];
        }
    };

    load_slab(0);
    store_slab();
    __syncthreads();

    int g = lane >> 3;
    int arow_off = (lane & 7) + (g & 1) * 8;
    int akb_off = (g >> 1) * 16;
    int brow_off = (lane & 7) + (g >> 1) * 8;
    int bkb_off = (g & 1) * 16;

    for (int s = 0; s < nslab; s++) {
        bool more = (s + 1 < nslab);
        if (more) load_slab(s + 1);

#pragma unroll
        for (int kk2 = 0; kk2 < 2; kk2++) {
            int kb = kk2 * 32;
            uint32_t ah[2][4], al[2][4], bh[4][4], bl[4][4];
#pragma unroll
            for (int mi = 0; mi < 2; mi++) {
                uint32_t r = (uint32_t)((wm * 32 + mi * 16 + arow_off) * SMSTR +
                                        kb + akb_off);
                ldsm4(sb + oAh + r, ah[mi]);
                ldsm4(sb + oAl + r, al[mi]);
            }
#pragma unroll
            for (int pi = 0; pi < 4; pi++) {
                uint32_t r = (uint32_t)((wn * 64 + pi * 16 + brow_off) * SMSTR +
                                        kb + bkb_off);
                ldsm4(sb + oBh + r, bh[pi]);
                ldsm4(sb + oBl + r, bl[pi]);
            }
#pragma unroll
            for (int mi = 0; mi < 2; mi++)
#pragma unroll
                for (int pi = 0; pi < 4; pi++)
#pragma unroll
                    for (int half = 0; half < 2; half++) {
                        float* d = acc[mi][pi * 2 + half];
                        mma16816(d, ah[mi], &bh[pi][half * 2]);
                        mma16816(d, ah[mi], &bl[pi][half * 2]);
                        mma16816(d, al[mi], &bh[pi][half * 2]);
                    }
        }
        __syncthreads();
        if (more) {
            store_slab();
            __syncthreads();
        }
    }

    float* ct = (float*)sm;
#pragma unroll
    for (int mi = 0; mi < 2; mi++) {
        int r0 = wm * 32 + mi * 16 + (lane >> 2);
#pragma unroll
        for (int ni = 0; ni < 8; ni++) {
            int c = wn * 64 + ni * 8 + (lane & 3) * 2;
            float b0 = bias[n0 + c], b1 = bias[n0 + c + 1];
            if (bias2) { b0 += bias2[n0 + c]; b1 += bias2[n0 + c + 1]; }
            float v0 = acc[mi][ni][0] + b0;
            float v1 = acc[mi][ni][1] + b1;
            float v2 = acc[mi][ni][2] + b0;
            float v3 = acc[mi][ni][3] + b1;
            if (ACT) {
                v0 = v0 > 0.f ? v0 : 0.01f * v0;
                v1 = v1 > 0.f ? v1 : 0.01f * v1;
                v2 = v2 > 0.f ? v2 : 0.01f * v2;
                v3 = v3 > 0.f ? v3 : 0.01f * v3;
            }
            ct[r0 * 132 + c] = v0;
            ct[r0 * 132 + c + 1] = v1;
            ct[(r0 + 8) * 132 + c] = v2;
            ct[(r0 + 8) * 132 + c + 1] = v3;
        }
    }
    __syncthreads();
    {
        int r8 = tid >> 5;
        int c4 = (tid & 31) * 4;
#pragma unroll
        for (int p = 0; p < 16; p++) {
            int r = p * 8 + r8;
            float4 v = *(const float4*)(ct + r * 132 + c4);
            *(float4*)(C + (size_t)(m0 + r) * N + n0 + c4) = v;
        }
    }
}

// ----------------------------------------------------------------------------
// HMMA conv (proven, R5/R6)
// ----------------------------------------------------------------------------
#define PSTR 48
#define IMG_BYTES (400 * PSTR)
#define CW_OFF   (2 * IMG_BYTES)
#define CW_HALF  12800

template <int KS, int P, int LAST>
__device__ __forceinline__ void conv_hmma_layer(
    uint8_t* csm, uint32_t sbase, const __nv_bfloat16* wsrc_h,
    const __nv_bfloat16* wsrc_l, const float* __restrict__ bias,
    float* gout, int tid, int lane, int wid) {
    const int taps = KS * KS;
    {
        const uint4* sh = (const uint4*)wsrc_h;
        const uint4* sl = (const uint4*)wsrc_l;
        uint4* dh = (uint4*)(csm + CW_OFF);
        uint4* dl = (uint4*)(csm + CW_OFF + CW_HALF);
        for (int i = tid; i < taps * 32; i += 256) {
            dh[i] = sh[i];
            dl[i] = sl[i];
        }
    }
    __syncthreads();

    float acc[2][2][4];
#pragma unroll
    for (int a = 0; a < 2; a++)
#pragma unroll
        for (int b = 0; b < 2; b++)
#pragma unroll
            for (int q = 0; q < 4; q++) acc[a][b][q] = 0.f;

    int g = lane >> 3;
    int h0 = wid * 2;
    uint32_t aoff[2];
#pragma unroll
    for (int mi = 0; mi < 2; mi++)
        aoff[mi] = (uint32_t)(((h0 + mi + 2) * 20 + 2 + (lane & 7) + (g & 1) * 8) * PSTR +
                              (g >> 1) * 16);
    uint32_t boff = (uint32_t)(((lane & 7) + (g >> 1) * 8) * 32 + (g & 1) * 16);
    uint32_t wb_h = sbase + CW_OFF;
    uint32_t wb_l = sbase + CW_OFF + CW_HALF;

#pragma unroll
    for (int kh = 0; kh < KS; kh++) {
#pragma unroll
        for (int kw = 0; kw < KS; kw++) {
            int t = kh * KS + kw;
            int shift = ((kh - P) * 20 + (kw - P)) * PSTR;
            uint32_t bh4[4], bl4[4];
            ldsm4(wb_h + t * 512 + boff, bh4);
            ldsm4(wb_l + t * 512 + boff, bl4);
#pragma unroll
            for (int mi = 0; mi < 2; mi++) {
                uint32_t ah[4], al[4];
                ldsm4(sbase + aoff[mi] + shift, ah);
                ldsm4(sbase + IMG_BYTES + aoff[mi] + shift, al);
#pragma unroll
                for (int nh = 0; nh < 2; nh++) {
                    mma16816(acc[mi][nh], ah, &bh4[nh * 2]);
                    mma16816(acc[mi][nh], ah, &bl4[nh * 2]);
                    mma16816(acc[mi][nh], al, &bh4[nh * 2]);
                }
            }
        }
    }
    __syncthreads();

#pragma unroll
    for (int mi = 0; mi < 2; mi++) {
        int h = h0 + mi;
#pragma unroll
        for (int nh = 0; nh < 2; nh++) {
            int co = nh * 8 + (lane & 3) * 2;
            float b0 = bias[co], b1 = bias[co + 1];
#pragma unroll
            for (int rr = 0; rr < 2; rr++) {
                int w = (lane >> 2) + rr * 8;
                float v0 = acc[mi][nh][rr * 2 + 0] + b0;
                float v1 = acc[mi][nh][rr * 2 + 1] + b1;
                v0 = v0 > 0.f ? v0 : 0.01f * v0;
                v1 = v1 > 0.f ? v1 : 0.01f * v1;
                if (LAST) {
                    gout[co * 256 + h * 16 + w] = v0;
                    gout[(co + 1) * 256 + h * 16 + w] = v1;
                } else {
                    uint32_t hp, lp;
                    split2(v0, v1, hp, lp);
                    int pb = ((h + 2) * 20 + (w + 2)) * PSTR + co * 2;
                    *(uint32_t*)(csm + pb) = hp;
                    *(uint32_t*)(csm + IMG_BYTES + pb) = lp;
                }
            }
        }
    }
    __syncthreads();
}

__global__ __launch_bounds__(256) void conv3_mma(
    const float* __restrict__ x,
    const float* __restrict__ b1, const float* __restrict__ b2,
    const float* __restrict__ b3) {
    extern __shared__ uint8_t csm[];
    uint32_t sbase = smem_to_u32(csm);
    int tid = threadIdx.x;
    int lane = tid & 31;
    int wid = tid >> 5;
    int img = blockIdx.x;
    const float* xi = x + (size_t)img * 4096;

    for (int i = tid; i < 2 * IMG_BYTES / 4; i += 256)
        ((uint32_t*)csm)[i] = 0;
    __syncthreads();
    for (int i = tid; i < 4096; i += 256) {
        int ci = i >> 8, p = i & 255;
        int h = p >> 4, w = p & 15;
        float v = xi[i];
        __nv_bfloat16 hv = __float2bfloat16(v);
        float lv = v - __bfloat162float(hv);
        int pb = ((h + 2) * 20 + (w + 2)) * PSTR + ci * 2;
        *(__nv_bfloat16*)(csm + pb) = hv;
        *(__nv_bfloat16*)(csm + IMG_BYTES + pb) = __float2bfloat16(lv);
    }
    __syncthreads();

    float* gout = g_conv + (size_t)img * 4096;
    conv_hmma_layer<5, 2, 0>(csm, sbase, g_cw1h, g_cw1l, b1, gout, tid, lane, wid);
    conv_hmma_layer<3, 1, 0>(csm, sbase, g_cw2h, g_cw2l, b2, gout, tid, lane, wid);
    conv_hmma_layer<3, 1, 1>(csm, sbase, g_cw3h, g_cw3l, b3, gout, tid, lane, wid);
}

// ----------------------------------------------------------------------------
// LSTM step via HMMA: grid 64 blocks, block b owns j-slice b*8..+8 of all 4
// gates (N=32 rows = g*8+jj), M=128 batch, K=512. h carried as bf16 hi/lo.
// ----------------------------------------------------------------------------
__device__ __forceinline__ float sigm(float x) { return 1.f / (1.f + expf(-x)); }

__global__ __launch_bounds__(256) void lstm_mma(
    const float* __restrict__ xg, const int* __restrict__ done,
    const __nv_bfloat16* __restrict__ hih, const __nv_bfloat16* __restrict__ hil,
    __nv_bfloat16* __restrict__ hoh, __nv_bfloat16* __restrict__ hol,
    float* __restrict__ c_st, float* __restrict__ feat, int t) {
    __shared__ uint8_t sA[2 * 128 * SMSTR];   // hi | lo
    __shared__ uint8_t sB[2 * 32 * SMSTR];
    __shared__ float s_m[128];
    uint32_t sbA = smem_to_u32(sA);
    uint32_t sbB = smem_to_u32(sB);
    int tid = threadIdx.x, lane = tid & 31, wid = tid >> 5;
    int blk = blockIdx.x;
    int jb8 = blk * 8;
    const __nv_bfloat16* Wh = g_wlh + (size_t)blk * 32 * 512;
    const __nv_bfloat16* Wl = g_wll + (size_t)blk * 32 * 512;

    if (tid < 128) s_m[tid] = done[t * 128 + tid] ? 0.f : 1.f;

    // acc init from xg (biases already folded by the xg GEMM)
    float acc[4][4];
    int r1 = wid * 16 + (lane >> 2);
    int c0 = (lane & 3) * 2;
#pragma unroll
    for (int g = 0; g < 4; g++)
#pragma unroll
        for (int rr = 0; rr < 2; rr++)
#pragma unroll
            for (int cc = 0; cc < 2; cc++)
                acc[g][rr * 2 + cc] =
                    xg[(size_t)(t * 128 + r1 + rr * 8) * 2048 + g * 512 + jb8 + c0 + cc];
    __syncthreads();

    int gq = lane >> 3;
    uint32_t arow = (uint32_t)((wid * 16 + (lane & 7) + (gq & 1) * 8) * SMSTR +
                               (gq >> 1) * 16);
    uint32_t brow = (uint32_t)(((lane & 7) + (gq >> 1) * 8) * SMSTR + (gq & 1) * 16);

    for (int s = 0; s < 16; s++) {
        // stage A: 128 rows x 32 k, hi+lo, masked (done -> zero row)
#pragma unroll
        for (int q = 0; q < 2; q++) {
            int idx = tid + 256 * q;
            int r = idx >> 2, quar = idx & 3;
            bool zz = (s_m[r] == 0.f);
            uint4 vh = zz ? make_uint4(0, 0, 0, 0)
                          : *(const uint4*)(hih + (size_t)r * 512 + s * 32 + quar * 8);
            uint4 vl = zz ? make_uint4(0, 0, 0, 0)
                          : *(const uint4*)(hil + (size_t)r * 512 + s * 32 + quar * 8);
            *(uint4*)(sA + r * SMSTR + quar * 16) = vh;
            *(uint4*)(sA + 128 * SMSTR + r * SMSTR + quar * 16) = vl;
        }
        // stage B: 32 rows x 32 k, first 128 threads hi, rest lo
        {
            int r = (tid & 127) >> 2, quar = tid & 3;
            const __nv_bfloat16* src = (tid < 128) ? Wh : Wl;
            uint32_t off = (tid < 128) ? 0u : (uint32_t)(32 * SMSTR);
            uint4 v = *(const uint4*)(src + (size_t)r * 512 + s * 32 + quar * 8);
            *(uint4*)(sB + off + r * SMSTR + quar * 16) = v;
        }
        __syncthreads();
#pragma unroll
        for (int kk2 = 0; kk2 < 2; kk2++) {
            int kb = kk2 * 32;
            uint32_t ah[4], al[4], bh[2][4], bl[2][4];
            ldsm4(sbA + arow + kb, ah);
            ldsm4(sbA + 128 * SMSTR + arow + kb, al);
#pragma unroll
            for (int pi = 0; pi < 2; pi++) {
                ldsm4(sbB + brow + pi * 16 * SMSTR + kb, bh[pi]);
                ldsm4(sbB + 32 * SMSTR + brow + pi * 16 * SMSTR + kb, bl[pi]);
            }
#pragma unroll
            for (int pi = 0; pi < 2; pi++)
#pragma unroll
                for (int hf = 0; hf < 2; hf++) {
                    float* d = acc[pi * 2 + hf];
                    mma16816(d, ah, &bh[pi][hf * 2]);
                    mma16816(d, ah, &bl[pi][hf * 2]);
                    mma16816(d, al, &bh[pi][hf * 2]);
                }
        }
        __syncthreads();
    }

    // epilogue: thread-local gate fusion (acc[g] = gate g for its 4 (r,c))
#pragma unroll
    for (int rr = 0; rr < 2; rr++) {
        int r = r1 + rr * 8;
        float m = s_m[r];
#pragma unroll
        for (int cc = 0; cc < 2; cc++) {
            int j = jb8 + c0 + cc;
            float gi = acc[0][rr * 2 + cc];
            float gf = acc[1][rr * 2 + cc];
            float gg = acc[2][rr * 2 + cc];
            float go = acc[3][rr * 2 + cc];
            float cold = c_st[(size_t)r * 512 + j];
            float cn = sigm(gf) * (cold * m) + sigm(gi) * tanhf(gg);
            float hn = sigm(go) * tanhf(cn);
            c_st[(size_t)r * 512 + j] = cn;
            feat[(size_t)(t * 128 + r) * 512 + j] = hn;
            __nv_bfloat16 hh = __float2bfloat16(hn);
            hoh[(size_t)r * 512 + j] = hh;
            hol[(size_t)r * 512 + j] = __float2bfloat16(hn - __bfloat162float(hh));
        }
    }
}

// ----------------------------------------------------------------------------
// Scalar SGEMM kept for lofeat (with z one-hot epilogue)
// ----------------------------------------------------------------------------
template <int ACT, int ZMODE>
__global__ __launch_bounds__(256, 2) void sgemm128(
    const float* __restrict__ A, const float* __restrict__ B,
    const float* __restrict__ bias, const float* __restrict__ bias2,
    float* __restrict__ C, int M, int N, int K, int ldb,
    const int* __restrict__ z) {
    __shared__ float As[8 * 132];
    __shared__ float Bs[8 * 132];
    int tid = threadIdx.x;
    int tx = tid & 15, ty = tid >> 4;
    int row0 = blockIdx.y * 128;
    int col0 = blockIdx.x * 128;
    const float* Ag = A + (size_t)row0 * K;
    const float* Bg = B + (size_t)col0 * ldb;
    int lr = tid >> 1;
    int lc = (tid & 1) * 4;

    float acc[8][8];
#pragma unroll
    for (int i = 0; i < 8; i++)
#pragma unroll
        for (int j = 0; j < 8; j++) acc[i][j] = 0.f;

    for (int k0 = 0; k0 < K; k0 += 8) {
        float4 a4 = *(const float4*)(Ag + (size_t)lr * K + k0 + lc);
        float4 b4 = *(const float4*)(Bg + (size_t)lr * ldb + k0 + lc);
        As[(lc + 0) * 132 + lr] = a4.x;
        As[(lc + 1) * 132 + lr] = a4.y;
        As[(lc + 2) * 132 + lr] = a4.z;
        As[(lc + 3) * 132 + lr] = a4.w;
        Bs[(lc + 0) * 132 + lr] = b4.x;
        Bs[(lc + 1) * 132 + lr] = b4.y;
        Bs[(lc + 2) * 132 + lr] = b4.z;
        Bs[(lc + 3) * 132 + lr] = b4.w;
        __syncthreads();
#pragma unroll
        for (int k = 0; k < 8; k++) {
            float4 a0 = *(const float4*)(As + k * 132 + ty * 4);
            float4 a1 = *(const float4*)(As + k * 132 + 64 + ty * 4);
            float4 b0 = *(const float4*)(Bs + k * 132 + tx * 4);
            float4 b1 = *(const float4*)(Bs + k * 132 + 64 + tx * 4);
            float av[8] = {a0.x, a0.y, a0.z, a0.w, a1.x, a1.y, a1.z, a1.w};
            float bv[8] = {b0.x, b0.y, b0.z, b0.w, b1.x, b1.y, b1.z, b1.w};
#pragma unroll
            for (int i = 0; i < 8; i++)
#pragma unroll
                for (int j = 0; j < 8; j++)
                    acc[i][j] = fmaf(av[i], bv[j], acc[i][j]);
        }
        __syncthreads();
    }

#pragma unroll
    for (int i = 0; i < 8; i++) {
        int m = row0 + ((i < 4) ? (ty * 4 + i) : (64 + ty * 4 + i - 4));
        int zi = 0;
        if (ZMODE) zi = 512 + z[m];
#pragma unroll
        for (int j = 0; j < 8; j++) {
            int n = col0 + ((j < 4) ? (tx * 4 + j) : (64 + tx * 4 + j - 4));
            float v = acc[i][j] + bias[n];
            if (bias2) v += bias2[n];
            if (ZMODE) v += B[(size_t)n * ldb + zi];
            if (ACT) v = v > 0.f ? v : 0.01f * v;
            C[(size_t)m * N + n] = v;
        }
    }
}

// ----------------------------------------------------------------------------
// Head: warp per row; actor/critic GEMV + log_softmax/entropy/prob pack.
// ----------------------------------------------------------------------------
__global__ __launch_bounds__(256) void head_kernel(
    const float* __restrict__ lf, const float* __restrict__ aw,
    const float* __restrict__ ab, const float* __restrict__ cw,
    const float* __restrict__ cb, const int* __restrict__ action,
    float* __restrict__ out) {
    int warp = (blockIdx.x * blockDim.x + threadIdx.x) >> 5;
    int lane = threadIdx.x & 31;
    if (warp >= TBTOT) return;
    float4 f = *(const float4*)(lf + (size_t)warp * FE + lane * 4);
    float r[8];
#pragma unroll
    for (int a = 0; a < 7; a++) {
        float4 w = *(const float4*)(aw + a * FE + lane * 4);
        r[a] = f.x * w.x + f.y * w.y + f.z * w.z + f.w * w.w;
    }
    {
        float4 w = *(const float4*)(cw + lane * 4);
        r[7] = f.x * w.x + f.y * w.y + f.z * w.z + f.w * w.w;
    }
#pragma unroll
    for (int a = 0; a < 8; a++)
#pragma unroll
        for (int s = 16; s > 0; s >>= 1)
            r[a] += __shfl_xor_sync(0xffffffffu, r[a], s);

    if (lane == 0) {
        float lg[7];
        float mx = -1e30f;
#pragma unroll
        for (int a = 0; a < 7; a++) {
            lg[a] = r[a] + ab[a];
            mx = fmaxf(mx, lg[a]);
        }
        float se = 0.f;
        float e[7];
#pragma unroll
        for (int a = 0; a < 7; a++) {
            e[a] = expf(lg[a] - mx);
            se += e[a];
        }
        float lse = mx + logf(se);
        float inv = 1.f / se;
        float ent = 0.f;
        float* o = out + (size_t)warp * 10;
#pragma unroll
        for (int a = 0; a < 7; a++) {
            float p = e[a] * inv;
            float lp = lg[a] - lse;
            ent -= p * lp;
            o[3 + a] = p;
        }
        int act = action[warp];
        o[0] = lg[act] - lse;
        o[1] = ent;
        o[2] = r[7] + cb[0];
    }
}

// ----------------------------------------------------------------------------
// Launch
// ----------------------------------------------------------------------------
extern "C" void kernel_launch(void* const* d_in, const int* in_sizes, int n_in,
                              void* d_out, int out_size) {
    const float* x    = (const float*)d_in[0];
    const int* done   = (const int*)d_in[1];
    const int* z      = (const int*)d_in[2];
    const int* action = (const int*)d_in[3];
    const float* h0   = (const float*)d_in[4];
    const float* c0   = (const float*)d_in[5];
    const float* c1w = (const float*)d_in[6];  const float* c1b = (const float*)d_in[7];
    const float* c2w = (const float*)d_in[8];  const float* c2b = (const float*)d_in[9];
    const float* c3w = (const float*)d_in[10]; const float* c3b = (const float*)d_in[11];
    const float* fc1w = (const float*)d_in[12]; const float* fc1b = (const float*)d_in[13];
    const float* fc2w = (const float*)d_in[14]; const float* fc2b = (const float*)d_in[15];
    const float* wih = (const float*)d_in[16]; const float* whh = (const float*)d_in[17];
    const float* bih = (const float*)d_in[18]; const float* bhh = (const float*)d_in[19];
    const float* lfw = (const float*)d_in[20]; const float* lfb = (const float*)d_in[21];
    const float* aw = (const float*)d_in[22];  const float* ab = (const float*)d_in[23];
    const float* cw = (const float*)d_in[24];  const float* cb = (const float*)d_in[25];
    float* out = (float*)d_out;

    float *pconv, *ph1, *ph2, *pxg, *pfeat, *plf, *pcst;
    __nv_bfloat16 *pw1h, *pw1l, *pw2h, *pw2l, *pwih_h, *pwih_l;
    __nv_bfloat16 *pc1h, *pc1l, *pc2h, *pc2l, *pc3h, *pc3l;
    __nv_bfloat16 *phhA, *phlA, *phhB, *phlB;
    cudaGetSymbolAddress((void**)&pconv, g_conv);
    cudaGetSymbolAddress((void**)&ph1, g_h1);
    cudaGetSymbolAddress((void**)&ph2, g_h2);
    cudaGetSymbolAddress((void**)&pxg, g_xg);
    cudaGetSymbolAddress((void**)&pfeat, g_feat);
    cudaGetSymbolAddress((void**)&plf, g_lf);
    cudaGetSymbolAddress((void**)&pcst, g_cst);
    cudaGetSymbolAddress((void**)&phhA, g_hhA);
    cudaGetSymbolAddress((void**)&phlA, g_hlA);
    cudaGetSymbolAddress((void**)&phhB, g_hhB);
    cudaGetSymbolAddress((void**)&phlB, g_hlB);
    cudaGetSymbolAddress((void**)&pw1h, g_wfc1_hi);
    cudaGetSymbolAddress((void**)&pw1l, g_wfc1_lo);
    cudaGetSymbolAddress((void**)&pw2h, g_wfc2_hi);
    cudaGetSymbolAddress((void**)&pw2l, g_wfc2_lo);
    cudaGetSymbolAddress((void**)&pwih_h, g_wih_hi);
    cudaGetSymbolAddress((void**)&pwih_l, g_wih_lo);
    cudaGetSymbolAddress((void**)&pc1h, g_cw1h);
    cudaGetSymbolAddress((void**)&pc1l, g_cw1l);
    cudaGetSymbolAddress((void**)&pc2h, g_cw2h);
    cudaGetSymbolAddress((void**)&pc2l, g_cw2l);
    cudaGetSymbolAddress((void**)&pc3h, g_cw3h);
    cudaGetSymbolAddress((void**)&pc3l, g_cw3l);

    const int SMEM_TG = 128 * 132 * 4;
    cudaFuncSetAttribute(tgemm<1>, cudaFuncAttributeMaxDynamicSharedMemorySize, SMEM_TG);
    cudaFuncSetAttribute(tgemm<0>, cudaFuncAttributeMaxDynamicSharedMemorySize, SMEM_TG);
    const int SMEM_CONV = 2 * IMG_BYTES + 2 * CW_HALF;
    cudaFuncSetAttribute(conv3_mma, cudaFuncAttributeMaxDynamicSharedMemorySize, SMEM_CONV);

    wcprep<<<25, 256>>>(c1w, pc1h, pc1l, 25);
    wcprep<<<9, 256>>>(c2w, pc2h, pc2l, 9);
    wcprep<<<9, 256>>>(c3w, pc3h, pc3l, 9);
    conv3_mma<<<TBTOT, 256, SMEM_CONV>>>(x, c1b, c2b, c3b);
    wprep<<<(512 * 1024 + 255) / 256, 256>>>(fc1w, pw1h, pw1l, 512 * 1024);
    tgemm<1><<<dim3(512 / 128, TBTOT / 128), 256, SMEM_TG>>>(
        pconv, pw1h, pw1l, fc1b, nullptr, ph1, TBTOT, 512, 4096);

    wprep<<<(512 * 128 + 255) / 256, 256>>>(fc2w, pw2h, pw2l, 512 * 128);
    wprep<<<(2048 * 128 + 255) / 256, 256>>>(wih, pwih_h, pwih_l, 2048 * 128);
    wlstm_prep<<<(2048 * 128 + 255) / 256, 256>>>(whh);
    pack_h0<<<(B_ENV * HID + 255) / 256, 256>>>(h0);
    cudaMemcpyAsync(pcst, c0, (size_t)B_ENV * HID * sizeof(float),
                    cudaMemcpyDeviceToDevice, 0);

    tgemm<1><<<dim3(512 / 128, TBTOT / 128), 256, SMEM_TG>>>(
        ph1, pw2h, pw2l, fc2b, nullptr, ph2, TBTOT, 512, 512);
    tgemm<0><<<dim3(2048 / 128, TBTOT / 128), 256, SMEM_TG>>>(
        ph2, pwih_h, pwih_l, bih, bhh, pxg, TBTOT, 2048, 512);

    // sequential recurrence, ping-pong split h
    for (int t = 0; t < T_STEPS; t++) {
        const __nv_bfloat16* hih = (t & 1) ? phhB : phhA;
        const __nv_bfloat16* hil = (t & 1) ? phlB : phlA;
        __nv_bfloat16* hoh = (t & 1) ? phhA : phhB;
        __nv_bfloat16* hol = (t & 1) ? phlA : phlB;
        lstm_mma<<<64, 256>>>(pxg, done, hih, hil, hoh, hol, pcst, pfeat, t);
    }

    // lofeat: feat(512) + one-hot(z) via epilogue, ldb=520, leaky
    sgemm128<1, 1><<<dim3(FE / 128, TBTOT / 128), 256>>>(
        pfeat, lfw, lfb, nullptr, plf, TBTOT, FE, 512, 520, z);

    // heads + softmax stats
    head_kernel<<<TBTOT / 8, 256>>>(plf, aw, ab, cw, cb, action, out);
}

// round 8
// speedup vs baseline: 1.3394x; 1.0147x over previous
#include <cuda_runtime.h>
#include <cuda_bf16.h>
#include <math.h>
#include <stdint.h>

#define T_STEPS 128
#define B_ENV   128
#define HID     512
#define TBTOT   (T_STEPS * B_ENV)
#define ZD      8
#define AD      7
#define FE      128
#define NB_LSTM 64

// ----------------------------------------------------------------------------
// Scratch (device globals; no allocation allowed)
// ----------------------------------------------------------------------------
__device__ float g_conv[TBTOT * 4096];
__device__ float g_h1[TBTOT * HID];
__device__ float g_h2[TBTOT * HID];
__device__ float g_xg[TBTOT * 2048];
__device__ float g_feat[TBTOT * HID];
__device__ float g_lf[TBTOT * FE];
__device__ float g_cst[B_ENV * HID];
__device__ __nv_bfloat16 g_hhA[B_ENV * HID];
__device__ __nv_bfloat16 g_hlA[B_ENV * HID];
__device__ __nv_bfloat16 g_hhB[B_ENV * HID];
__device__ __nv_bfloat16 g_hlB[B_ENV * HID];
__device__ __nv_bfloat16 g_wlh[64 * 32 * 512];
__device__ __nv_bfloat16 g_wll[64 * 32 * 512];
__device__ __nv_bfloat16 g_wfc1_hi[512 * 4096];
__device__ __nv_bfloat16 g_wfc1_lo[512 * 4096];
__device__ __nv_bfloat16 g_wfc2_hi[512 * 512];
__device__ __nv_bfloat16 g_wfc2_lo[512 * 512];
__device__ __nv_bfloat16 g_wih_hi[2048 * 512];
__device__ __nv_bfloat16 g_wih_lo[2048 * 512];
__device__ __nv_bfloat16 g_cw1h[25 * 256];
__device__ __nv_bfloat16 g_cw1l[25 * 256];
__device__ __nv_bfloat16 g_cw2h[9 * 256];
__device__ __nv_bfloat16 g_cw2l[9 * 256];
__device__ __nv_bfloat16 g_cw3h[9 * 256];
__device__ __nv_bfloat16 g_cw3l[9 * 256];
// grid barrier state
__device__ unsigned int g_bar_cnt;
__device__ volatile unsigned int g_bar_gen;

// ============================================================================
// Helpers
// ============================================================================
__device__ __forceinline__ uint32_t smem_to_u32(const void* smem_ptr) {
    uint32_t addr;
    asm("{ .reg .u64 tmp; cvta.to.shared.u64 tmp, %1; cvt.u32.u64 %0, tmp; }"
        : "=r"(addr) : "l"(smem_ptr));
    return addr;
}

__device__ __forceinline__ void ldsm4(uint32_t addr, uint32_t* r) {
    asm volatile("ldmatrix.sync.aligned.m8n8.x4.shared.b16 {%0,%1,%2,%3}, [%4];"
        : "=r"(r[0]), "=r"(r[1]), "=r"(r[2]), "=r"(r[3]) : "r"(addr));
}

__device__ __forceinline__ void mma16816(float* d, const uint32_t* a,
                                         const uint32_t* b) {
    asm volatile(
        "mma.sync.aligned.m16n8k16.row.col.f32.bf16.bf16.f32 "
        "{%0,%1,%2,%3}, {%4,%5,%6,%7}, {%8,%9}, {%0,%1,%2,%3};"
        : "+f"(d[0]), "+f"(d[1]), "+f"(d[2]), "+f"(d[3])
        : "r"(a[0]), "r"(a[1]), "r"(a[2]), "r"(a[3]), "r"(b[0]), "r"(b[1]));
}

__device__ __forceinline__ void split2(float x, float y, uint32_t& hi, uint32_t& lo) {
    __nv_bfloat16 hx = __float2bfloat16(x), hy = __float2bfloat16(y);
    __nv_bfloat162 h2; h2.x = hx; h2.y = hy;
    hi = reinterpret_cast<uint32_t&>(h2);
    float lx = x - __bfloat162float(hx);
    float ly = y - __bfloat162float(hy);
    __nv_bfloat162 l2 = __floats2bfloat162_rn(lx, ly);
    lo = reinterpret_cast<uint32_t&>(l2);
}

// software grid barrier (all NB_LSTM blocks co-resident by construction)
__device__ __forceinline__ void grid_bar() {
    __syncthreads();
    if (threadIdx.x == 0) {
        unsigned int gen = g_bar_gen;
        __threadfence();
        if (atomicAdd(&g_bar_cnt, 1u) == NB_LSTM - 1) {
            g_bar_cnt = 0;
            __threadfence();
            g_bar_gen = gen + 1;
        } else {
            while (g_bar_gen == gen) { }
            __threadfence();
        }
    }
    __syncthreads();
}

// ----------------------------------------------------------------------------
// Weight prep kernels
// ----------------------------------------------------------------------------
__global__ void wprep(const float* __restrict__ w, __nv_bfloat16* __restrict__ hi,
                      __nv_bfloat16* __restrict__ lo, int total4) {
    int idx = blockIdx.x * blockDim.x + threadIdx.x;
    if (idx >= total4) return;
    float4 a = *(const float4*)(w + (size_t)idx * 4);
    uint32_t h0, h1, l0, l1;
    split2(a.x, a.y, h0, l0);
    split2(a.z, a.w, h1, l1);
    *(uint2*)(hi + (size_t)idx * 4) = make_uint2(h0, h1);
    *(uint2*)(lo + (size_t)idx * 4) = make_uint2(l0, l1);
}

__global__ void wcprep(const float* __restrict__ w, __nv_bfloat16* __restrict__ hi,
                       __nv_bfloat16* __restrict__ lo, int taps) {
    int idx = blockIdx.x * blockDim.x + threadIdx.x;
    if (idx >= taps * 256) return;
    int r = idx & 255;
    int t = idx >> 8;
    float v = w[r * taps + t];
    __nv_bfloat16 hv = __float2bfloat16(v);
    float lv = v - __bfloat162float(hv);
    hi[t * 256 + r] = hv;
    lo[t * 256 + r] = __float2bfloat16(lv);
}

__global__ void wlstm_prep(const float* __restrict__ whh) {
    int idx = blockIdx.x * blockDim.x + threadIdx.x;
    if (idx >= 2048 * 128) return;
    int row = idx >> 7;
    int k4 = (idx & 127) * 4;
    int g = row >> 9, j = row & 511;
    int blk = j >> 3, jj = j & 7;
    size_t dst = ((size_t)(blk * 32 + g * 8 + jj)) * 512 + k4;
    float4 v = *(const float4*)(whh + (size_t)row * 512 + k4);
    uint32_t h0, h1, l0, l1;
    split2(v.x, v.y, h0, l0);
    split2(v.z, v.w, h1, l1);
    *(uint2*)(g_wlh + dst) = make_uint2(h0, h1);
    *(uint2*)(g_wll + dst) = make_uint2(l0, l1);
}

__global__ void pack_h0(const float* __restrict__ h0) {
    int i = blockIdx.x * blockDim.x + threadIdx.x;
    if (i >= B_ENV * HID) return;
    float v = h0[i];
    __nv_bfloat16 hv = __float2bfloat16(v);
    g_hhA[i] = hv;
    g_hlA[i] = __float2bfloat16(v - __bfloat162float(hv));
}

// ----------------------------------------------------------------------------
// HMMA GEMM (proven): 3-term bf16 split, fp32 accum
// ----------------------------------------------------------------------------
#define SMSTR 80

template <int ACT>
__global__ __launch_bounds__(256) void tgemm(
    const float* __restrict__ A, const __nv_bfloat16* __restrict__ Whi,
    const __nv_bfloat16* __restrict__ Wlo,
    const float* __restrict__ bias, const float* __restrict__ bias2,
    float* __restrict__ C, int M, int N, int K) {
    extern __shared__ uint8_t sm[];
    const uint32_t oAh = 0, oAl = 10240, oBh = 20480, oBl = 30720;
    uint32_t sb = smem_to_u32(sm);
    int tid = threadIdx.x;
    int lane = tid & 31;
    int wid = tid >> 5;
    int wm = wid & 3, wn = wid >> 2;
    int m0 = blockIdx.y * 128, n0 = blockIdx.x * 128;
    const float* Ag = A + (size_t)m0 * K;

    float acc[2][8][4];
#pragma unroll
    for (int i = 0; i < 2; i++)
#pragma unroll
        for (int j = 0; j < 8; j++)
#pragma unroll
            for (int q = 0; q < 4; q++) acc[i][j][q] = 0.f;

    int nslab = K / 32;
    float4 aR[4];
    uint4 bRh[2], bRl[2];

    auto load_slab = [&](int s) {
#pragma unroll
        for (int i = 0; i < 4; i++) {
            int row = (tid >> 3) + 32 * i;
            aR[i] = *(const float4*)(Ag + (size_t)row * K + s * 32 + (tid & 7) * 4);
        }
#pragma unroll
        for (int i = 0; i < 2; i++) {
            int row = (tid >> 2) + 64 * i;
            size_t boff = ((size_t)(n0 + row) * K + s * 32);
            bRh[i] = *(const uint4*)((const uint8_t*)(Whi + boff) + (tid & 3) * 16);
            bRl[i] = *(const uint4*)((const uint8_t*)(Wlo + boff) + (tid & 3) * 16);
        }
    };
    auto store_slab = [&]() {
#pragma unroll
        for (int i = 0; i < 4; i++) {
            int row = (tid >> 3) + 32 * i;
            int col8 = (tid & 7) * 8;
            uint32_t h0, h1, l0, l1;
            split2(aR[i].x, aR[i].y, h0, l0);
            split2(aR[i].z, aR[i].w, h1, l1);
            *(uint2*)(sm + oAh + row * SMSTR + col8) = make_uint2(h0, h1);
            *(uint2*)(sm + oAl + row * SMSTR + col8) = make_uint2(l0, l1);
        }
#pragma unroll
        for (int i = 0; i < 2; i++) {
            int row = (tid >> 2) + 64 * i;
            int c16 = (tid & 3) * 16;
            *(uint4*)(sm + oBh + row * SMSTR + c16) = bRh[i];
            *(uint4*)(sm + oBl + row * SMSTR + c16) = bRl[i];
        }
    };

    load_slab(0);
    store_slab();
    __syncthreads();

    int g = lane >> 3;
    int arow_off = (lane & 7) + (g & 1) * 8;
    int akb_off = (g >> 1) * 16;
    int brow_off = (lane & 7) + (g >> 1) * 8;
    int bkb_off = (g & 1) * 16;

    for (int s = 0; s < nslab; s++) {
        bool more = (s + 1 < nslab);
        if (more) load_slab(s + 1);

#pragma unroll
        for (int kk2 = 0; kk2 < 2; kk2++) {
            int kb = kk2 * 32;
            uint32_t ah[2][4], al[2][4], bh[4][4], bl[4][4];
#pragma unroll
            for (int mi = 0; mi < 2; mi++) {
                uint32_t r = (uint32_t)((wm * 32 + mi * 16 + arow_off) * SMSTR +
                                        kb + akb_off);
                ldsm4(sb + oAh + r, ah[mi]);
                ldsm4(sb + oAl + r, al[mi]);
            }
#pragma unroll
            for (int pi = 0; pi < 4; pi++) {
                uint32_t r = (uint32_t)((wn * 64 + pi * 16 + brow_off) * SMSTR +
                                        kb + bkb_off);
                ldsm4(sb + oBh + r, bh[pi]);
                ldsm4(sb + oBl + r, bl[pi]);
            }
#pragma unroll
            for (int mi = 0; mi < 2; mi++)
#pragma unroll
                for (int pi = 0; pi < 4; pi++)
#pragma unroll
                    for (int half = 0; half < 2; half++) {
                        float* d = acc[mi][pi * 2 + half];
                        mma16816(d, ah[mi], &bh[pi][half * 2]);
                        mma16816(d, ah[mi], &bl[pi][half * 2]);
                        mma16816(d, al[mi], &bh[pi][half * 2]);
                    }
        }
        __syncthreads();
        if (more) {
            store_slab();
            __syncthreads();
        }
    }

    float* ct = (float*)sm;
#pragma unroll
    for (int mi = 0; mi < 2; mi++) {
        int r0 = wm * 32 + mi * 16 + (lane >> 2);
#pragma unroll
        for (int ni = 0; ni < 8; ni++) {
            int c = wn * 64 + ni * 8 + (lane & 3) * 2;
            float b0 = bias[n0 + c], b1 = bias[n0 + c + 1];
            if (bias2) { b0 += bias2[n0 + c]; b1 += bias2[n0 + c + 1]; }
            float v0 = acc[mi][ni][0] + b0;
            float v1 = acc[mi][ni][1] + b1;
            float v2 = acc[mi][ni][2] + b0;
            float v3 = acc[mi][ni][3] + b1;
            if (ACT) {
                v0 = v0 > 0.f ? v0 : 0.01f * v0;
                v1 = v1 > 0.f ? v1 : 0.01f * v1;
                v2 = v2 > 0.f ? v2 : 0.01f * v2;
                v3 = v3 > 0.f ? v3 : 0.01f * v3;
            }
            ct[r0 * 132 + c] = v0;
            ct[r0 * 132 + c + 1] = v1;
            ct[(r0 + 8) * 132 + c] = v2;
            ct[(r0 + 8) * 132 + c + 1] = v3;
        }
    }
    __syncthreads();
    {
        int r8 = tid >> 5;
        int c4 = (tid & 31) * 4;
#pragma unroll
        for (int p = 0; p < 16; p++) {
            int r = p * 8 + r8;
            float4 v = *(const float4*)(ct + r * 132 + c4);
            *(float4*)(C + (size_t)(m0 + r) * N + n0 + c4) = v;
        }
    }
}

// ----------------------------------------------------------------------------
// HMMA conv (proven)
// ----------------------------------------------------------------------------
#define PSTR 48
#define IMG_BYTES (400 * PSTR)
#define CW_OFF   (2 * IMG_BYTES)
#define CW_HALF  12800

template <int KS, int P, int LAST>
__device__ __forceinline__ void conv_hmma_layer(
    uint8_t* csm, uint32_t sbase, const __nv_bfloat16* wsrc_h,
    const __nv_bfloat16* wsrc_l, const float* __restrict__ bias,
    float* gout, int tid, int lane, int wid) {
    const int taps = KS * KS;
    {
        const uint4* sh = (const uint4*)wsrc_h;
        const uint4* sl = (const uint4*)wsrc_l;
        uint4* dh = (uint4*)(csm + CW_OFF);
        uint4* dl = (uint4*)(csm + CW_OFF + CW_HALF);
        for (int i = tid; i < taps * 32; i += 256) {
            dh[i] = sh[i];
            dl[i] = sl[i];
        }
    }
    __syncthreads();

    float acc[2][2][4];
#pragma unroll
    for (int a = 0; a < 2; a++)
#pragma unroll
        for (int b = 0; b < 2; b++)
#pragma unroll
            for (int q = 0; q < 4; q++) acc[a][b][q] = 0.f;

    int g = lane >> 3;
    int h0 = wid * 2;
    uint32_t aoff[2];
#pragma unroll
    for (int mi = 0; mi < 2; mi++)
        aoff[mi] = (uint32_t)(((h0 + mi + 2) * 20 + 2 + (lane & 7) + (g & 1) * 8) * PSTR +
                              (g >> 1) * 16);
    uint32_t boff = (uint32_t)(((lane & 7) + (g >> 1) * 8) * 32 + (g & 1) * 16);
    uint32_t wb_h = sbase + CW_OFF;
    uint32_t wb_l = sbase + CW_OFF + CW_HALF;

#pragma unroll
    for (int kh = 0; kh < KS; kh++) {
#pragma unroll
        for (int kw = 0; kw < KS; kw++) {
            int t = kh * KS + kw;
            int shift = ((kh - P) * 20 + (kw - P)) * PSTR;
            uint32_t bh4[4], bl4[4];
            ldsm4(wb_h + t * 512 + boff, bh4);
            ldsm4(wb_l + t * 512 + boff, bl4);
#pragma unroll
            for (int mi = 0; mi < 2; mi++) {
                uint32_t ah[4], al[4];
                ldsm4(sbase + aoff[mi] + shift, ah);
                ldsm4(sbase + IMG_BYTES + aoff[mi] + shift, al);
#pragma unroll
                for (int nh = 0; nh < 2; nh++) {
                    mma16816(acc[mi][nh], ah, &bh4[nh * 2]);
                    mma16816(acc[mi][nh], ah, &bl4[nh * 2]);
                    mma16816(acc[mi][nh], al, &bh4[nh * 2]);
                }
            }
        }
    }
    __syncthreads();

#pragma unroll
    for (int mi = 0; mi < 2; mi++) {
        int h = h0 + mi;
#pragma unroll
        for (int nh = 0; nh < 2; nh++) {
            int co = nh * 8 + (lane & 3) * 2;
            float b0 = bias[co], b1 = bias[co + 1];
#pragma unroll
            for (int rr = 0; rr < 2; rr++) {
                int w = (lane >> 2) + rr * 8;
                float v0 = acc[mi][nh][rr * 2 + 0] + b0;
                float v1 = acc[mi][nh][rr * 2 + 1] + b1;
                v0 = v0 > 0.f ? v0 : 0.01f * v0;
                v1 = v1 > 0.f ? v1 : 0.01f * v1;
                if (LAST) {
                    gout[co * 256 + h * 16 + w] = v0;
                    gout[(co + 1) * 256 + h * 16 + w] = v1;
                } else {
                    uint32_t hp, lp;
                    split2(v0, v1, hp, lp);
                    int pb = ((h + 2) * 20 + (w + 2)) * PSTR + co * 2;
                    *(uint32_t*)(csm + pb) = hp;
                    *(uint32_t*)(csm + IMG_BYTES + pb) = lp;
                }
            }
        }
    }
    __syncthreads();
}

__global__ __launch_bounds__(256) void conv3_mma(
    const float* __restrict__ x,
    const float* __restrict__ b1, const float* __restrict__ b2,
    const float* __restrict__ b3) {
    extern __shared__ uint8_t csm[];
    uint32_t sbase = smem_to_u32(csm);
    int tid = threadIdx.x;
    int lane = tid & 31;
    int wid = tid >> 5;
    int img = blockIdx.x;
    const float* xi = x + (size_t)img * 4096;

    for (int i = tid; i < 2 * IMG_BYTES / 4; i += 256)
        ((uint32_t*)csm)[i] = 0;
    __syncthreads();
    for (int i = tid; i < 4096; i += 256) {
        int ci = i >> 8, p = i & 255;
        int h = p >> 4, w = p & 15;
        float v = xi[i];
        __nv_bfloat16 hv = __float2bfloat16(v);
        float lv = v - __bfloat162float(hv);
        int pb = ((h + 2) * 20 + (w + 2)) * PSTR + ci * 2;
        *(__nv_bfloat16*)(csm + pb) = hv;
        *(__nv_bfloat16*)(csm + IMG_BYTES + pb) = __float2bfloat16(lv);
    }
    __syncthreads();

    float* gout = g_conv + (size_t)img * 4096;
    conv_hmma_layer<5, 2, 0>(csm, sbase, g_cw1h, g_cw1l, b1, gout, tid, lane, wid);
    conv_hmma_layer<3, 1, 0>(csm, sbase, g_cw2h, g_cw2l, b2, gout, tid, lane, wid);
    conv_hmma_layer<3, 1, 1>(csm, sbase, g_cw3h, g_cw3l, b3, gout, tid, lane, wid);
}

// ----------------------------------------------------------------------------
// Persistent LSTM: all 128 steps in one kernel, grid barrier between steps.
// 64 blocks x 256 threads. Block b owns j-slice b*8..+8 of all 4 gates.
// Weights resident in smem (hi/lo, stride-1040 rows).
// ----------------------------------------------------------------------------
__device__ __forceinline__ float sigm(float x) { return 1.f / (1.f + expf(-x)); }

#define LW_STR   1040
#define LS_W_SZ  (2 * 32 * LW_STR)                 // 66560
#define LS_A_OFF LS_W_SZ
#define LS_A_SZ  (2 * 128 * SMSTR)                 // 20480
#define LS_M_OFF (LS_A_OFF + LS_A_SZ)              // 87040
#define LS_SMEM  (LS_M_OFF + 512)                  // 87552

__global__ __launch_bounds__(256) void lstm_persist(
    const float* __restrict__ xg, const int* __restrict__ done,
    __nv_bfloat16* __restrict__ hAh, __nv_bfloat16* __restrict__ hAl,
    __nv_bfloat16* __restrict__ hBh, __nv_bfloat16* __restrict__ hBl,
    float* __restrict__ c_st, float* __restrict__ feat) {
    extern __shared__ uint8_t psm[];
    float* s_m = (float*)(psm + LS_M_OFF);
    uint32_t sbW = smem_to_u32(psm);
    uint32_t sbA = sbW + LS_A_OFF;
    int tid = threadIdx.x, lane = tid & 31, wid = tid >> 5;
    int blk = blockIdx.x;
    int jb8 = blk * 8;

    // load resident weights: 32 rows x 512 bf16, hi and lo (64 uint4 per row)
    {
        const uint4* Wh = (const uint4*)(g_wlh + (size_t)blk * 32 * 512);
        const uint4* Wl = (const uint4*)(g_wll + (size_t)blk * 32 * 512);
#pragma unroll
        for (int i = 0; i < 8; i++) {
            int i4 = tid + 256 * i;
            int r = i4 >> 6, q = i4 & 63;
            *(uint4*)(psm + r * LW_STR + q * 16) = Wh[i4];
            *(uint4*)(psm + 32 * LW_STR + r * LW_STR + q * 16) = Wl[i4];
        }
    }

    int r1 = wid * 16 + (lane >> 2);
    int c0 = (lane & 3) * 2;
    int gq = lane >> 3;
    uint32_t arow = (uint32_t)((wid * 16 + (lane & 7) + (gq & 1) * 8) * SMSTR +
                               (gq >> 1) * 16);
    uint32_t brow = (uint32_t)(((lane & 7) + (gq >> 1) * 8) * LW_STR + (gq & 1) * 16);
    __syncthreads();

    for (int t = 0; t < T_STEPS; t++) {
        const __nv_bfloat16* hih = (t & 1) ? hBh : hAh;
        const __nv_bfloat16* hil = (t & 1) ? hBl : hAl;
        __nv_bfloat16* hoh = (t & 1) ? hAh : hBh;
        __nv_bfloat16* hol = (t & 1) ? hAl : hBl;

        if (tid < 128) s_m[tid] = done[t * 128 + tid] ? 0.f : 1.f;

        // acc init from xg (biases pre-folded by xg GEMM)
        float acc[4][4];
#pragma unroll
        for (int g = 0; g < 4; g++)
#pragma unroll
            for (int rr = 0; rr < 2; rr++) {
                float2 v = *(const float2*)(xg +
                    (size_t)(t * 128 + r1 + rr * 8) * 2048 + g * 512 + jb8 + c0);
                acc[g][rr * 2 + 0] = v.x;
                acc[g][rr * 2 + 1] = v.y;
            }
        __syncthreads();  // masks visible

        for (int s = 0; s < 16; s++) {
            // stage A: 128 rows x 32 k, hi+lo, masked
#pragma unroll
            for (int q = 0; q < 2; q++) {
                int idx = tid + 256 * q;
                int r = idx >> 2, quar = idx & 3;
                bool zz = (s_m[r] == 0.f);
                uint4 vh = zz ? make_uint4(0, 0, 0, 0)
                              : *(const uint4*)(hih + (size_t)r * 512 + s * 32 + quar * 8);
                uint4 vl = zz ? make_uint4(0, 0, 0, 0)
                              : *(const uint4*)(hil + (size_t)r * 512 + s * 32 + quar * 8);
                *(uint4*)(psm + LS_A_OFF + r * SMSTR + quar * 16) = vh;
                *(uint4*)(psm + LS_A_OFF + 128 * SMSTR + r * SMSTR + quar * 16) = vl;
            }
            __syncthreads();
#pragma unroll
            for (int kk2 = 0; kk2 < 2; kk2++) {
                int kb = kk2 * 32;
                uint32_t ah[4], al[4], bh[2][4], bl[2][4];
                ldsm4(sbA + arow + kb, ah);
                ldsm4(sbA + 128 * SMSTR + arow + kb, al);
#pragma unroll
                for (int pi = 0; pi < 2; pi++) {
                    uint32_t bo = brow + pi * 16 * LW_STR + s * 64 + kb;
                    ldsm4(sbW + bo, bh[pi]);
                    ldsm4(sbW + 32 * LW_STR + bo, bl[pi]);
                }
#pragma unroll
                for (int pi = 0; pi < 2; pi++)
#pragma unroll
                    for (int hf = 0; hf < 2; hf++) {
                        float* d = acc[pi * 2 + hf];
                        mma16816(d, ah, &bh[pi][hf * 2]);
                        mma16816(d, ah, &bl[pi][hf * 2]);
                        mma16816(d, al, &bh[pi][hf * 2]);
                    }
            }
            __syncthreads();
        }

        // epilogue
#pragma unroll
        for (int rr = 0; rr < 2; rr++) {
            int r = r1 + rr * 8;
            float m = s_m[r];
#pragma unroll
            for (int cc = 0; cc < 2; cc++) {
                int j = jb8 + c0 + cc;
                float gi = acc[0][rr * 2 + cc];
                float gf = acc[1][rr * 2 + cc];
                float gg = acc[2][rr * 2 + cc];
                float go = acc[3][rr * 2 + cc];
                float cold = c_st[(size_t)r * 512 + j];
                float cn = sigm(gf) * (cold * m) + sigm(gi) * tanhf(gg);
                float hn = sigm(go) * tanhf(cn);
                c_st[(size_t)r * 512 + j] = cn;
                feat[(size_t)(t * 128 + r) * 512 + j] = hn;
                __nv_bfloat16 hh = __float2bfloat16(hn);
                hoh[(size_t)r * 512 + j] = hh;
                hol[(size_t)r * 512 + j] = __float2bfloat16(hn - __bfloat162float(hh));
            }
        }
        grid_bar();
    }
}

// ----------------------------------------------------------------------------
// Scalar SGEMM kept for lofeat (with z one-hot epilogue)
// ----------------------------------------------------------------------------
template <int ACT, int ZMODE>
__global__ __launch_bounds__(256, 2) void sgemm128(
    const float* __restrict__ A, const float* __restrict__ B,
    const float* __restrict__ bias, const float* __restrict__ bias2,
    float* __restrict__ C, int M, int N, int K, int ldb,
    const int* __restrict__ z) {
    __shared__ float As[8 * 132];
    __shared__ float Bs[8 * 132];
    int tid = threadIdx.x;
    int tx = tid & 15, ty = tid >> 4;
    int row0 = blockIdx.y * 128;
    int col0 = blockIdx.x * 128;
    const float* Ag = A + (size_t)row0 * K;
    const float* Bg = B + (size_t)col0 * ldb;
    int lr = tid >> 1;
    int lc = (tid & 1) * 4;

    float acc[8][8];
#pragma unroll
    for (int i = 0; i < 8; i++)
#pragma unroll
        for (int j = 0; j < 8; j++) acc[i][j] = 0.f;

    for (int k0 = 0; k0 < K; k0 += 8) {
        float4 a4 = *(const float4*)(Ag + (size_t)lr * K + k0 + lc);
        float4 b4 = *(const float4*)(Bg + (size_t)lr * ldb + k0 + lc);
        As[(lc + 0) * 132 + lr] = a4.x;
        As[(lc + 1) * 132 + lr] = a4.y;
        As[(lc + 2) * 132 + lr] = a4.z;
        As[(lc + 3) * 132 + lr] = a4.w;
        Bs[(lc + 0) * 132 + lr] = b4.x;
        Bs[(lc + 1) * 132 + lr] = b4.y;
        Bs[(lc + 2) * 132 + lr] = b4.z;
        Bs[(lc + 3) * 132 + lr] = b4.w;
        __syncthreads();
#pragma unroll
        for (int k = 0; k < 8; k++) {
            float4 a0 = *(const float4*)(As + k * 132 + ty * 4);
            float4 a1 = *(const float4*)(As + k * 132 + 64 + ty * 4);
            float4 b0 = *(const float4*)(Bs + k * 132 + tx * 4);
            float4 b1 = *(const float4*)(Bs + k * 132 + 64 + tx * 4);
            float av[8] = {a0.x, a0.y, a0.z, a0.w, a1.x, a1.y, a1.z, a1.w};
            float bv[8] = {b0.x, b0.y, b0.z, b0.w, b1.x, b1.y, b1.z, b1.w};
#pragma unroll
            for (int i = 0; i < 8; i++)
#pragma unroll
                for (int j = 0; j < 8; j++)
                    acc[i][j] = fmaf(av[i], bv[j], acc[i][j]);
        }
        __syncthreads();
    }

#pragma unroll
    for (int i = 0; i < 8; i++) {
        int m = row0 + ((i < 4) ? (ty * 4 + i) : (64 + ty * 4 + i - 4));
        int zi = 0;
        if (ZMODE) zi = 512 + z[m];
#pragma unroll
        for (int j = 0; j < 8; j++) {
            int n = col0 + ((j < 4) ? (tx * 4 + j) : (64 + tx * 4 + j - 4));
            float v = acc[i][j] + bias[n];
            if (bias2) v += bias2[n];
            if (ZMODE) v += B[(size_t)n * ldb + zi];
            if (ACT) v = v > 0.f ? v : 0.01f * v;
            C[(size_t)m * N + n] = v;
        }
    }
}

// ----------------------------------------------------------------------------
// Head: warp per row; actor/critic GEMV + log_softmax/entropy/prob pack.
// ----------------------------------------------------------------------------
__global__ __launch_bounds__(256) void head_kernel(
    const float* __restrict__ lf, const float* __restrict__ aw,
    const float* __restrict__ ab, const float* __restrict__ cw,
    const float* __restrict__ cb, const int* __restrict__ action,
    float* __restrict__ out) {
    int warp = (blockIdx.x * blockDim.x + threadIdx.x) >> 5;
    int lane = threadIdx.x & 31;
    if (warp >= TBTOT) return;
    float4 f = *(const float4*)(lf + (size_t)warp * FE + lane * 4);
    float r[8];
#pragma unroll
    for (int a = 0; a < 7; a++) {
        float4 w = *(const float4*)(aw + a * FE + lane * 4);
        r[a] = f.x * w.x + f.y * w.y + f.z * w.z + f.w * w.w;
    }
    {
        float4 w = *(const float4*)(cw + lane * 4);
        r[7] = f.x * w.x + f.y * w.y + f.z * w.z + f.w * w.w;
    }
#pragma unroll
    for (int a = 0; a < 8; a++)
#pragma unroll
        for (int s = 16; s > 0; s >>= 1)
            r[a] += __shfl_xor_sync(0xffffffffu, r[a], s);

    if (lane == 0) {
        float lg[7];
        float mx = -1e30f;
#pragma unroll
        for (int a = 0; a < 7; a++) {
            lg[a] = r[a] + ab[a];
            mx = fmaxf(mx, lg[a]);
        }
        float se = 0.f;
        float e[7];
#pragma unroll
        for (int a = 0; a < 7; a++) {
            e[a] = expf(lg[a] - mx);
            se += e[a];
        }
        float lse = mx + logf(se);
        float inv = 1.f / se;
        float ent = 0.f;
        float* o = out + (size_t)warp * 10;
#pragma unroll
        for (int a = 0; a < 7; a++) {
            float p = e[a] * inv;
            float lp = lg[a] - lse;
            ent -= p * lp;
            o[3 + a] = p;
        }
        int act = action[warp];
        o[0] = lg[act] - lse;
        o[1] = ent;
        o[2] = r[7] + cb[0];
    }
}

// ----------------------------------------------------------------------------
// Launch
// ----------------------------------------------------------------------------
extern "C" void kernel_launch(void* const* d_in, const int* in_sizes, int n_in,
                              void* d_out, int out_size) {
    const float* x    = (const float*)d_in[0];
    const int* done   = (const int*)d_in[1];
    const int* z      = (const int*)d_in[2];
    const int* action = (const int*)d_in[3];
    const float* h0   = (const float*)d_in[4];
    const float* c0   = (const float*)d_in[5];
    const float* c1w = (const float*)d_in[6];  const float* c1b = (const float*)d_in[7];
    const float* c2w = (const float*)d_in[8];  const float* c2b = (const float*)d_in[9];
    const float* c3w = (const float*)d_in[10]; const float* c3b = (const float*)d_in[11];
    const float* fc1w = (const float*)d_in[12]; const float* fc1b = (const float*)d_in[13];
    const float* fc2w = (const float*)d_in[14]; const float* fc2b = (const float*)d_in[15];
    const float* wih = (const float*)d_in[16]; const float* whh = (const float*)d_in[17];
    const float* bih = (const float*)d_in[18]; const float* bhh = (const float*)d_in[19];
    const float* lfw = (const float*)d_in[20]; const float* lfb = (const float*)d_in[21];
    const float* aw = (const float*)d_in[22];  const float* ab = (const float*)d_in[23];
    const float* cw = (const float*)d_in[24];  const float* cb = (const float*)d_in[25];
    float* out = (float*)d_out;

    float *pconv, *ph1, *ph2, *pxg, *pfeat, *plf, *pcst;
    __nv_bfloat16 *pw1h, *pw1l, *pw2h, *pw2l, *pwih_h, *pwih_l;
    __nv_bfloat16 *pc1h, *pc1l, *pc2h, *pc2l, *pc3h, *pc3l;
    __nv_bfloat16 *phhA, *phlA, *phhB, *phlB;
    cudaGetSymbolAddress((void**)&pconv, g_conv);
    cudaGetSymbolAddress((void**)&ph1, g_h1);
    cudaGetSymbolAddress((void**)&ph2, g_h2);
    cudaGetSymbolAddress((void**)&pxg, g_xg);
    cudaGetSymbolAddress((void**)&pfeat, g_feat);
    cudaGetSymbolAddress((void**)&plf, g_lf);
    cudaGetSymbolAddress((void**)&pcst, g_cst);
    cudaGetSymbolAddress((void**)&phhA, g_hhA);
    cudaGetSymbolAddress((void**)&phlA, g_hlA);
    cudaGetSymbolAddress((void**)&phhB, g_hhB);
    cudaGetSymbolAddress((void**)&phlB, g_hlB);
    cudaGetSymbolAddress((void**)&pw1h, g_wfc1_hi);
    cudaGetSymbolAddress((void**)&pw1l, g_wfc1_lo);
    cudaGetSymbolAddress((void**)&pw2h, g_wfc2_hi);
    cudaGetSymbolAddress((void**)&pw2l, g_wfc2_lo);
    cudaGetSymbolAddress((void**)&pwih_h, g_wih_hi);
    cudaGetSymbolAddress((void**)&pwih_l, g_wih_lo);
    cudaGetSymbolAddress((void**)&pc1h, g_cw1h);
    cudaGetSymbolAddress((void**)&pc1l, g_cw1l);
    cudaGetSymbolAddress((void**)&pc2h, g_cw2h);
    cudaGetSymbolAddress((void**)&pc2l, g_cw2l);
    cudaGetSymbolAddress((void**)&pc3h, g_cw3h);
    cudaGetSymbolAddress((void**)&pc3l, g_cw3l);

    const int SMEM_TG = 128 * 132 * 4;
    cudaFuncSetAttribute(tgemm<1>, cudaFuncAttributeMaxDynamicSharedMemorySize, SMEM_TG);
    cudaFuncSetAttribute(tgemm<0>, cudaFuncAttributeMaxDynamicSharedMemorySize, SMEM_TG);
    const int SMEM_CONV = 2 * IMG_BYTES + 2 * CW_HALF;
    cudaFuncSetAttribute(conv3_mma, cudaFuncAttributeMaxDynamicSharedMemorySize, SMEM_CONV);
    cudaFuncSetAttribute(lstm_persist, cudaFuncAttributeMaxDynamicSharedMemorySize, LS_SMEM);

    wcprep<<<25, 256>>>(c1w, pc1h, pc1l, 25);
    wcprep<<<9, 256>>>(c2w, pc2h, pc2l, 9);
    wcprep<<<9, 256>>>(c3w, pc3h, pc3l, 9);
    conv3_mma<<<TBTOT, 256, SMEM_CONV>>>(x, c1b, c2b, c3b);
    wprep<<<(512 * 1024 + 255) / 256, 256>>>(fc1w, pw1h, pw1l, 512 * 1024);
    tgemm<1><<<dim3(512 / 128, TBTOT / 128), 256, SMEM_TG>>>(
        pconv, pw1h, pw1l, fc1b, nullptr, ph1, TBTOT, 512, 4096);

    wprep<<<(512 * 128 + 255) / 256, 256>>>(fc2w, pw2h, pw2l, 512 * 128);
    wprep<<<(2048 * 128 + 255) / 256, 256>>>(wih, pwih_h, pwih_l, 2048 * 128);
    wlstm_prep<<<(2048 * 128 + 255) / 256, 256>>>(whh);
    pack_h0<<<(B_ENV * HID + 255) / 256, 256>>>(h0);
    cudaMemcpyAsync(pcst, c0, (size_t)B_ENV * HID * sizeof(float),
                    cudaMemcpyDeviceToDevice, 0);

    tgemm<1><<<dim3(512 / 128, TBTOT / 128), 256, SMEM_TG>>>(
        ph1, pw2h, pw2l, fc2b, nullptr, ph2, TBTOT, 512, 512);
    tgemm<0><<<dim3(2048 / 128, TBTOT / 128), 256, SMEM_TG>>>(
        ph2, pwih_h, pwih_l, bih, bhh, pxg, TBTOT, 2048, 512);

    // entire recurrence in ONE persistent kernel
    lstm_persist<<<NB_LSTM, 256, LS_SMEM>>>(pxg, done, phhA, phlA, phhB, phlB,
                                            pcst, pfeat);

    // lofeat: feat(512) + one-hot(z) via epilogue, ldb=520, leaky
    sgemm128<1, 1><<<dim3(FE / 128, TBTOT / 128), 256>>>(
        pfeat, lfw, lfb, nullptr, plf, TBTOT, FE, 512, 520, z);

    // heads + softmax stats
    head_kernel<<<TBTOT / 8, 256>>>(plf, aw, ab, cw, cb, action, out);
}

// round 9
// speedup vs baseline: 1.5490x; 1.1565x over previous
#include <cuda_runtime.h>
#include <cuda_bf16.h>
#include <math.h>
#include <stdint.h>

#define T_STEPS 128
#define B_ENV   128
#define HID     512
#define TBTOT   (T_STEPS * B_ENV)
#define ZD      8
#define AD      7
#define FE      128
#define NB_LSTM 64

// ----------------------------------------------------------------------------
// Scratch (device globals; no allocation allowed)
// ----------------------------------------------------------------------------
__device__ float g_conv[TBTOT * 4096];
__device__ float g_h1[TBTOT * HID];
__device__ float g_h2[TBTOT * HID];
__device__ float g_xg[TBTOT * 2048];
__device__ float g_feat[TBTOT * HID];
__device__ float g_lf[TBTOT * FE];
__device__ float g_cst[B_ENV * HID];
__device__ __nv_bfloat16 g_hhA[B_ENV * HID];
__device__ __nv_bfloat16 g_hlA[B_ENV * HID];
__device__ __nv_bfloat16 g_hhB[B_ENV * HID];
__device__ __nv_bfloat16 g_hlB[B_ENV * HID];
__device__ __nv_bfloat16 g_wlh[64 * 32 * 512];
__device__ __nv_bfloat16 g_wll[64 * 32 * 512];
__device__ __nv_bfloat16 g_wfc1_hi[512 * 4096];
__device__ __nv_bfloat16 g_wfc1_lo[512 * 4096];
__device__ __nv_bfloat16 g_wfc2_hi[512 * 512];
__device__ __nv_bfloat16 g_wfc2_lo[512 * 512];
__device__ __nv_bfloat16 g_wih_hi[2048 * 512];
__device__ __nv_bfloat16 g_wih_lo[2048 * 512];
__device__ __nv_bfloat16 g_cw1h[25 * 256];
__device__ __nv_bfloat16 g_cw1l[25 * 256];
__device__ __nv_bfloat16 g_cw2h[9 * 256];
__device__ __nv_bfloat16 g_cw2l[9 * 256];
__device__ __nv_bfloat16 g_cw3h[9 * 256];
__device__ __nv_bfloat16 g_cw3l[9 * 256];
// grid barrier state
__device__ unsigned int g_bar_cnt;
__device__ volatile unsigned int g_bar_gen;

// ============================================================================
// Helpers
// ============================================================================
__device__ __forceinline__ uint32_t smem_to_u32(const void* smem_ptr) {
    uint32_t addr;
    asm("{ .reg .u64 tmp; cvta.to.shared.u64 tmp, %1; cvt.u32.u64 %0, tmp; }"
        : "=r"(addr) : "l"(smem_ptr));
    return addr;
}

__device__ __forceinline__ void ldsm4(uint32_t addr, uint32_t* r) {
    asm volatile("ldmatrix.sync.aligned.m8n8.x4.shared.b16 {%0,%1,%2,%3}, [%4];"
        : "=r"(r[0]), "=r"(r[1]), "=r"(r[2]), "=r"(r[3]) : "r"(addr));
}

__device__ __forceinline__ void mma16816(float* d, const uint32_t* a,
                                         const uint32_t* b) {
    asm volatile(
        "mma.sync.aligned.m16n8k16.row.col.f32.bf16.bf16.f32 "
        "{%0,%1,%2,%3}, {%4,%5,%6,%7}, {%8,%9}, {%0,%1,%2,%3};"
        : "+f"(d[0]), "+f"(d[1]), "+f"(d[2]), "+f"(d[3])
        : "r"(a[0]), "r"(a[1]), "r"(a[2]), "r"(a[3]), "r"(b[0]), "r"(b[1]));
}

__device__ __forceinline__ void split2(float x, float y, uint32_t& hi, uint32_t& lo) {
    __nv_bfloat16 hx = __float2bfloat16(x), hy = __float2bfloat16(y);
    __nv_bfloat162 h2; h2.x = hx; h2.y = hy;
    hi = reinterpret_cast<uint32_t&>(h2);
    float lx = x - __bfloat162float(hx);
    float ly = y - __bfloat162float(hy);
    __nv_bfloat162 l2 = __floats2bfloat162_rn(lx, ly);
    lo = reinterpret_cast<uint32_t&>(l2);
}

// software grid barrier (all NB_LSTM blocks co-resident by construction)
__device__ __forceinline__ void grid_bar() {
    __threadfence();
    __syncthreads();
    if (threadIdx.x == 0) {
        unsigned int gen = g_bar_gen;
        if (atomicAdd(&g_bar_cnt, 1u) == NB_LSTM - 1) {
            g_bar_cnt = 0;
            __threadfence();
            g_bar_gen = gen + 1;
        } else {
            while (g_bar_gen == gen) { }
            __threadfence();
        }
    }
    __syncthreads();
}

// ----------------------------------------------------------------------------
// Weight prep kernels
// ----------------------------------------------------------------------------
__global__ void wprep(const float* __restrict__ w, __nv_bfloat16* __restrict__ hi,
                      __nv_bfloat16* __restrict__ lo, int total4) {
    int idx = blockIdx.x * blockDim.x + threadIdx.x;
    if (idx >= total4) return;
    float4 a = *(const float4*)(w + (size_t)idx * 4);
    uint32_t h0, h1, l0, l1;
    split2(a.x, a.y, h0, l0);
    split2(a.z, a.w, h1, l1);
    *(uint2*)(hi + (size_t)idx * 4) = make_uint2(h0, h1);
    *(uint2*)(lo + (size_t)idx * 4) = make_uint2(l0, l1);
}

__global__ void wcprep(const float* __restrict__ w, __nv_bfloat16* __restrict__ hi,
                       __nv_bfloat16* __restrict__ lo, int taps) {
    int idx = blockIdx.x * blockDim.x + threadIdx.x;
    if (idx >= taps * 256) return;
    int r = idx & 255;
    int t = idx >> 8;
    float v = w[r * taps + t];
    __nv_bfloat16 hv = __float2bfloat16(v);
    float lv = v - __bfloat162float(hv);
    hi[t * 256 + r] = hv;
    lo[t * 256 + r] = __float2bfloat16(lv);
}

__global__ void wlstm_prep(const float* __restrict__ whh) {
    int idx = blockIdx.x * blockDim.x + threadIdx.x;
    if (idx >= 2048 * 128) return;
    int row = idx >> 7;
    int k4 = (idx & 127) * 4;
    int g = row >> 9, j = row & 511;
    int blk = j >> 3, jj = j & 7;
    size_t dst = ((size_t)(blk * 32 + g * 8 + jj)) * 512 + k4;
    float4 v = *(const float4*)(whh + (size_t)row * 512 + k4);
    uint32_t h0, h1, l0, l1;
    split2(v.x, v.y, h0, l0);
    split2(v.z, v.w, h1, l1);
    *(uint2*)(g_wlh + dst) = make_uint2(h0, h1);
    *(uint2*)(g_wll + dst) = make_uint2(l0, l1);
}

__global__ void pack_h0(const float* __restrict__ h0) {
    int i = blockIdx.x * blockDim.x + threadIdx.x;
    if (i >= B_ENV * HID) return;
    float v = h0[i];
    __nv_bfloat16 hv = __float2bfloat16(v);
    g_hhA[i] = hv;
    g_hlA[i] = __float2bfloat16(v - __bfloat162float(hv));
}

// ----------------------------------------------------------------------------
// HMMA GEMM (proven): 3-term bf16 split, fp32 accum
// ----------------------------------------------------------------------------
#define SMSTR 80

template <int ACT>
__global__ __launch_bounds__(256) void tgemm(
    const float* __restrict__ A, const __nv_bfloat16* __restrict__ Whi,
    const __nv_bfloat16* __restrict__ Wlo,
    const float* __restrict__ bias, const float* __restrict__ bias2,
    float* __restrict__ C, int M, int N, int K) {
    extern __shared__ uint8_t sm[];
    const uint32_t oAh = 0, oAl = 10240, oBh = 20480, oBl = 30720;
    uint32_t sb = smem_to_u32(sm);
    int tid = threadIdx.x;
    int lane = tid & 31;
    int wid = tid >> 5;
    int wm = wid & 3, wn = wid >> 2;
    int m0 = blockIdx.y * 128, n0 = blockIdx.x * 128;
    const float* Ag = A + (size_t)m0 * K;

    float acc[2][8][4];
#pragma unroll
    for (int i = 0; i < 2; i++)
#pragma unroll
        for (int j = 0; j < 8; j++)
#pragma unroll
            for (int q = 0; q < 4; q++) acc[i][j][q] = 0.f;

    int nslab = K / 32;
    float4 aR[4];
    uint4 bRh[2], bRl[2];

    auto load_slab = [&](int s) {
#pragma unroll
        for (int i = 0; i < 4; i++) {
            int row = (tid >> 3) + 32 * i;
            aR[i] = *(const float4*)(Ag + (size_t)row * K + s * 32 + (tid & 7) * 4);
        }
#pragma unroll
        for (int i = 0; i < 2; i++) {
            int row = (tid >> 2) + 64 * i;
            size_t boff = ((size_t)(n0 + row) * K + s * 32);
            bRh[i] = *(const uint4*)((const uint8_t*)(Whi + boff) + (tid & 3) * 16);
            bRl[i] = *(const uint4*)((const uint8_t*)(Wlo + boff) + (tid & 3) * 16);
        }
    };
    auto store_slab = [&]() {
#pragma unroll
        for (int i = 0; i < 4; i++) {
            int row = (tid >> 3) + 32 * i;
            int col8 = (tid & 7) * 8;
            uint32_t h0, h1, l0, l1;
            split2(aR[i].x, aR[i].y, h0, l0);
            split2(aR[i].z, aR[i].w, h1, l1);
            *(uint2*)(sm + oAh + row * SMSTR + col8) = make_uint2(h0, h1);
            *(uint2*)(sm + oAl + row * SMSTR + col8) = make_uint2(l0, l1);
        }
#pragma unroll
        for (int i = 0; i < 2; i++) {
            int row = (tid >> 2) + 64 * i;
            int c16 = (tid & 3) * 16;
            *(uint4*)(sm + oBh + row * SMSTR + c16) = bRh[i];
            *(uint4*)(sm + oBl + row * SMSTR + c16) = bRl[i];
        }
    };

    load_slab(0);
    store_slab();
    __syncthreads();

    int g = lane >> 3;
    int arow_off = (lane & 7) + (g & 1) * 8;
    int akb_off = (g >> 1) * 16;
    int brow_off = (lane & 7) + (g >> 1) * 8;
    int bkb_off = (g & 1) * 16;

    for (int s = 0; s < nslab; s++) {
        bool more = (s + 1 < nslab);
        if (more) load_slab(s + 1);

#pragma unroll
        for (int kk2 = 0; kk2 < 2; kk2++) {
            int kb = kk2 * 32;
            uint32_t ah[2][4], al[2][4], bh[4][4], bl[4][4];
#pragma unroll
            for (int mi = 0; mi < 2; mi++) {
                uint32_t r = (uint32_t)((wm * 32 + mi * 16 + arow_off) * SMSTR +
                                        kb + akb_off);
                ldsm4(sb + oAh + r, ah[mi]);
                ldsm4(sb + oAl + r, al[mi]);
            }
#pragma unroll
            for (int pi = 0; pi < 4; pi++) {
                uint32_t r = (uint32_t)((wn * 64 + pi * 16 + brow_off) * SMSTR +
                                        kb + bkb_off);
                ldsm4(sb + oBh + r, bh[pi]);
                ldsm4(sb + oBl + r, bl[pi]);
            }
#pragma unroll
            for (int mi = 0; mi < 2; mi++)
#pragma unroll
                for (int pi = 0; pi < 4; pi++)
#pragma unroll
                    for (int half = 0; half < 2; half++) {
                        float* d = acc[mi][pi * 2 + half];
                        mma16816(d, ah[mi], &bh[pi][half * 2]);
                        mma16816(d, ah[mi], &bl[pi][half * 2]);
                        mma16816(d, al[mi], &bh[pi][half * 2]);
                    }
        }
        __syncthreads();
        if (more) {
            store_slab();
            __syncthreads();
        }
    }

    float* ct = (float*)sm;
#pragma unroll
    for (int mi = 0; mi < 2; mi++) {
        int r0 = wm * 32 + mi * 16 + (lane >> 2);
#pragma unroll
        for (int ni = 0; ni < 8; ni++) {
            int c = wn * 64 + ni * 8 + (lane & 3) * 2;
            float b0 = bias[n0 + c], b1 = bias[n0 + c + 1];
            if (bias2) { b0 += bias2[n0 + c]; b1 += bias2[n0 + c + 1]; }
            float v0 = acc[mi][ni][0] + b0;
            float v1 = acc[mi][ni][1] + b1;
            float v2 = acc[mi][ni][2] + b0;
            float v3 = acc[mi][ni][3] + b1;
            if (ACT) {
                v0 = v0 > 0.f ? v0 : 0.01f * v0;
                v1 = v1 > 0.f ? v1 : 0.01f * v1;
                v2 = v2 > 0.f ? v2 : 0.01f * v2;
                v3 = v3 > 0.f ? v3 : 0.01f * v3;
            }
            ct[r0 * 132 + c] = v0;
            ct[r0 * 132 + c + 1] = v1;
            ct[(r0 + 8) * 132 + c] = v2;
            ct[(r0 + 8) * 132 + c + 1] = v3;
        }
    }
    __syncthreads();
    {
        int r8 = tid >> 5;
        int c4 = (tid & 31) * 4;
#pragma unroll
        for (int p = 0; p < 16; p++) {
            int r = p * 8 + r8;
            float4 v = *(const float4*)(ct + r * 132 + c4);
            *(float4*)(C + (size_t)(m0 + r) * N + n0 + c4) = v;
        }
    }
}

// ----------------------------------------------------------------------------
// HMMA conv (proven)
// ----------------------------------------------------------------------------
#define PSTR 48
#define IMG_BYTES (400 * PSTR)
#define CW_OFF   (2 * IMG_BYTES)
#define CW_HALF  12800

template <int KS, int P, int LAST>
__device__ __forceinline__ void conv_hmma_layer(
    uint8_t* csm, uint32_t sbase, const __nv_bfloat16* wsrc_h,
    const __nv_bfloat16* wsrc_l, const float* __restrict__ bias,
    float* gout, int tid, int lane, int wid) {
    const int taps = KS * KS;
    {
        const uint4* sh = (const uint4*)wsrc_h;
        const uint4* sl = (const uint4*)wsrc_l;
        uint4* dh = (uint4*)(csm + CW_OFF);
        uint4* dl = (uint4*)(csm + CW_OFF + CW_HALF);
        for (int i = tid; i < taps * 32; i += 256) {
            dh[i] = sh[i];
            dl[i] = sl[i];
        }
    }
    __syncthreads();

    float acc[2][2][4];
#pragma unroll
    for (int a = 0; a < 2; a++)
#pragma unroll
        for (int b = 0; b < 2; b++)
#pragma unroll
            for (int q = 0; q < 4; q++) acc[a][b][q] = 0.f;

    int g = lane >> 3;
    int h0 = wid * 2;
    uint32_t aoff[2];
#pragma unroll
    for (int mi = 0; mi < 2; mi++)
        aoff[mi] = (uint32_t)(((h0 + mi + 2) * 20 + 2 + (lane & 7) + (g & 1) * 8) * PSTR +
                              (g >> 1) * 16);
    uint32_t boff = (uint32_t)(((lane & 7) + (g >> 1) * 8) * 32 + (g & 1) * 16);
    uint32_t wb_h = sbase + CW_OFF;
    uint32_t wb_l = sbase + CW_OFF + CW_HALF;

#pragma unroll
    for (int kh = 0; kh < KS; kh++) {
#pragma unroll
        for (int kw = 0; kw < KS; kw++) {
            int t = kh * KS + kw;
            int shift = ((kh - P) * 20 + (kw - P)) * PSTR;
            uint32_t bh4[4], bl4[4];
            ldsm4(wb_h + t * 512 + boff, bh4);
            ldsm4(wb_l + t * 512 + boff, bl4);
#pragma unroll
            for (int mi = 0; mi < 2; mi++) {
                uint32_t ah[4], al[4];
                ldsm4(sbase + aoff[mi] + shift, ah);
                ldsm4(sbase + IMG_BYTES + aoff[mi] + shift, al);
#pragma unroll
                for (int nh = 0; nh < 2; nh++) {
                    mma16816(acc[mi][nh], ah, &bh4[nh * 2]);
                    mma16816(acc[mi][nh], ah, &bl4[nh * 2]);
                    mma16816(acc[mi][nh], al, &bh4[nh * 2]);
                }
            }
        }
    }
    __syncthreads();

#pragma unroll
    for (int mi = 0; mi < 2; mi++) {
        int h = h0 + mi;
#pragma unroll
        for (int nh = 0; nh < 2; nh++) {
            int co = nh * 8 + (lane & 3) * 2;
            float b0 = bias[co], b1 = bias[co + 1];
#pragma unroll
            for (int rr = 0; rr < 2; rr++) {
                int w = (lane >> 2) + rr * 8;
                float v0 = acc[mi][nh][rr * 2 + 0] + b0;
                float v1 = acc[mi][nh][rr * 2 + 1] + b1;
                v0 = v0 > 0.f ? v0 : 0.01f * v0;
                v1 = v1 > 0.f ? v1 : 0.01f * v1;
                if (LAST) {
                    gout[co * 256 + h * 16 + w] = v0;
                    gout[(co + 1) * 256 + h * 16 + w] = v1;
                } else {
                    uint32_t hp, lp;
                    split2(v0, v1, hp, lp);
                    int pb = ((h + 2) * 20 + (w + 2)) * PSTR + co * 2;
                    *(uint32_t*)(csm + pb) = hp;
                    *(uint32_t*)(csm + IMG_BYTES + pb) = lp;
                }
            }
        }
    }
    __syncthreads();
}

__global__ __launch_bounds__(256) void conv3_mma(
    const float* __restrict__ x,
    const float* __restrict__ b1, const float* __restrict__ b2,
    const float* __restrict__ b3) {
    extern __shared__ uint8_t csm[];
    uint32_t sbase = smem_to_u32(csm);
    int tid = threadIdx.x;
    int lane = tid & 31;
    int wid = tid >> 5;
    int img = blockIdx.x;
    const float* xi = x + (size_t)img * 4096;

    for (int i = tid; i < 2 * IMG_BYTES / 4; i += 256)
        ((uint32_t*)csm)[i] = 0;
    __syncthreads();
    for (int i = tid; i < 4096; i += 256) {
        int ci = i >> 8, p = i & 255;
        int h = p >> 4, w = p & 15;
        float v = xi[i];
        __nv_bfloat16 hv = __float2bfloat16(v);
        float lv = v - __bfloat162float(hv);
        int pb = ((h + 2) * 20 + (w + 2)) * PSTR + ci * 2;
        *(__nv_bfloat16*)(csm + pb) = hv;
        *(__nv_bfloat16*)(csm + IMG_BYTES + pb) = __float2bfloat16(lv);
    }
    __syncthreads();

    float* gout = g_conv + (size_t)img * 4096;
    conv_hmma_layer<5, 2, 0>(csm, sbase, g_cw1h, g_cw1l, b1, gout, tid, lane, wid);
    conv_hmma_layer<3, 1, 0>(csm, sbase, g_cw2h, g_cw2l, b2, gout, tid, lane, wid);
    conv_hmma_layer<3, 1, 1>(csm, sbase, g_cw3h, g_cw3l, b3, gout, tid, lane, wid);
}

// ----------------------------------------------------------------------------
// Persistent LSTM v2: pipelined staging (double-buffered A + reg prefetch),
// c state in registers, one syncthreads per slab.
// ----------------------------------------------------------------------------
__device__ __forceinline__ float sigm(float x) { return 1.f / (1.f + expf(-x)); }

#define LW_STR   1040
#define LS_W_SZ  (2 * 32 * LW_STR)                 // 66560
#define LS_A_OFF LS_W_SZ
#define LS_A_BUF (2 * 128 * SMSTR)                 // 20480 (hi+lo)
#define LS_M_OFF (LS_A_OFF + 2 * LS_A_BUF)         // 107520
#define LS_SMEM  (LS_M_OFF + 512)                  // 108032

__global__ __launch_bounds__(256) void lstm_persist(
    const float* __restrict__ xg, const int* __restrict__ done,
    __nv_bfloat16* __restrict__ hAh, __nv_bfloat16* __restrict__ hAl,
    __nv_bfloat16* __restrict__ hBh, __nv_bfloat16* __restrict__ hBl,
    float* __restrict__ c_st, float* __restrict__ feat) {
    extern __shared__ uint8_t psm[];
    float* s_m = (float*)(psm + LS_M_OFF);
    uint32_t sbW = smem_to_u32(psm);
    int tid = threadIdx.x, lane = tid & 31, wid = tid >> 5;
    int blk = blockIdx.x;
    int jb8 = blk * 8;

    // resident weights
    {
        const uint4* Wh = (const uint4*)(g_wlh + (size_t)blk * 32 * 512);
        const uint4* Wl = (const uint4*)(g_wll + (size_t)blk * 32 * 512);
#pragma unroll
        for (int i = 0; i < 8; i++) {
            int i4 = tid + 256 * i;
            int r = i4 >> 6, q = i4 & 63;
            *(uint4*)(psm + r * LW_STR + q * 16) = Wh[i4];
            *(uint4*)(psm + 32 * LW_STR + r * LW_STR + q * 16) = Wl[i4];
        }
    }

    int r1 = wid * 16 + (lane >> 2);
    int c0 = (lane & 3) * 2;
    int gq = lane >> 3;
    uint32_t arow = (uint32_t)((wid * 16 + (lane & 7) + (gq & 1) * 8) * SMSTR +
                               (gq >> 1) * 16);
    uint32_t brow = (uint32_t)(((lane & 7) + (gq >> 1) * 8) * LW_STR + (gq & 1) * 16);

    // staging thread map (fixed): r = (tid+256q)>>2, quar = tid&3
    int sr0 = tid >> 2, sq = tid & 3;

    // c state in registers (thread's (r,j) fixed across steps)
    float creg[2][2];
#pragma unroll
    for (int rr = 0; rr < 2; rr++)
#pragma unroll
        for (int cc = 0; cc < 2; cc++)
            creg[rr][cc] = c_st[(size_t)(r1 + rr * 8) * 512 + jb8 + c0 + cc];
    __syncthreads();

    uint4 pvh[2], pvl[2];

    for (int t = 0; t < T_STEPS; t++) {
        const __nv_bfloat16* hih = (t & 1) ? hBh : hAh;
        const __nv_bfloat16* hil = (t & 1) ? hBl : hAl;
        __nv_bfloat16* hoh = (t & 1) ? hAh : hBh;
        __nv_bfloat16* hol = (t & 1) ? hAl : hBl;

        if (tid < 128) s_m[tid] = done[t * 128 + tid] ? 0.f : 1.f;

        // acc init from xg (biases pre-folded)
        float acc[4][4];
#pragma unroll
        for (int g = 0; g < 4; g++)
#pragma unroll
            for (int rr = 0; rr < 2; rr++) {
                float2 v = *(const float2*)(xg +
                    (size_t)(t * 128 + r1 + rr * 8) * 2048 + g * 512 + jb8 + c0);
                acc[g][rr * 2 + 0] = v.x;
                acc[g][rr * 2 + 1] = v.y;
            }
        __syncthreads();  // masks visible before ld_slab uses them

        auto ld_slab = [&](int s) {
#pragma unroll
            for (int q = 0; q < 2; q++) {
                int r = sr0 + 64 * q;
                bool zz = (s_m[r] == 0.f);
                pvh[q] = zz ? make_uint4(0, 0, 0, 0)
                            : *(const uint4*)(hih + (size_t)r * 512 + s * 32 + sq * 8);
                pvl[q] = zz ? make_uint4(0, 0, 0, 0)
                            : *(const uint4*)(hil + (size_t)r * 512 + s * 32 + sq * 8);
            }
        };
        auto st_slab = [&](int buf) {
            uint8_t* base = psm + LS_A_OFF + buf * LS_A_BUF;
#pragma unroll
            for (int q = 0; q < 2; q++) {
                int r = sr0 + 64 * q;
                *(uint4*)(base + r * SMSTR + sq * 16) = pvh[q];
                *(uint4*)(base + 128 * SMSTR + r * SMSTR + sq * 16) = pvl[q];
            }
        };

        ld_slab(0);
        st_slab(0);
        __syncthreads();

        for (int s = 0; s < 16; s++) {
            if (s < 15) ld_slab(s + 1);          // gmem loads in flight
            uint32_t sbA = sbW + LS_A_OFF + (uint32_t)((s & 1) * LS_A_BUF);
#pragma unroll
            for (int kk2 = 0; kk2 < 2; kk2++) {
                int kb = kk2 * 32;
                uint32_t ah[4], al[4], bh[2][4], bl[2][4];
                ldsm4(sbA + arow + kb, ah);
                ldsm4(sbA + 128 * SMSTR + arow + kb, al);
#pragma unroll
                for (int pi = 0; pi < 2; pi++) {
                    uint32_t bo = brow + pi * 16 * LW_STR + s * 64 + kb;
                    ldsm4(sbW + bo, bh[pi]);
                    ldsm4(sbW + 32 * LW_STR + bo, bl[pi]);
                }
#pragma unroll
                for (int pi = 0; pi < 2; pi++)
#pragma unroll
                    for (int hf = 0; hf < 2; hf++) {
                        float* d = acc[pi * 2 + hf];
                        mma16816(d, ah, &bh[pi][hf * 2]);
                        mma16816(d, ah, &bl[pi][hf * 2]);
                        mma16816(d, al, &bh[pi][hf * 2]);
                    }
            }
            if (s < 15) {
                st_slab((s + 1) & 1);
                __syncthreads();
            }
        }

        // epilogue: register c, fused gates
#pragma unroll
        for (int rr = 0; rr < 2; rr++) {
            int r = r1 + rr * 8;
            float m = s_m[r];
#pragma unroll
            for (int cc = 0; cc < 2; cc++) {
                int j = jb8 + c0 + cc;
                float gi = acc[0][rr * 2 + cc];
                float gf = acc[1][rr * 2 + cc];
                float gg = acc[2][rr * 2 + cc];
                float go = acc[3][rr * 2 + cc];
                float cn = sigm(gf) * (creg[rr][cc] * m) + sigm(gi) * tanhf(gg);
                float hn = sigm(go) * tanhf(cn);
                creg[rr][cc] = cn;
                feat[(size_t)(t * 128 + r) * 512 + j] = hn;
                __nv_bfloat16 hh = __float2bfloat16(hn);
                hoh[(size_t)r * 512 + j] = hh;
                hol[(size_t)r * 512 + j] = __float2bfloat16(hn - __bfloat162float(hh));
            }
        }
        grid_bar();
    }
}

// ----------------------------------------------------------------------------
// Scalar SGEMM kept for lofeat (with z one-hot epilogue)
// ----------------------------------------------------------------------------
template <int ACT, int ZMODE>
__global__ __launch_bounds__(256, 2) void sgemm128(
    const float* __restrict__ A, const float* __restrict__ B,
    const float* __restrict__ bias, const float* __restrict__ bias2,
    float* __restrict__ C, int M, int N, int K, int ldb,
    const int* __restrict__ z) {
    __shared__ float As[8 * 132];
    __shared__ float Bs[8 * 132];
    int tid = threadIdx.x;
    int tx = tid & 15, ty = tid >> 4;
    int row0 = blockIdx.y * 128;
    int col0 = blockIdx.x * 128;
    const float* Ag = A + (size_t)row0 * K;
    const float* Bg = B + (size_t)col0 * ldb;
    int lr = tid >> 1;
    int lc = (tid & 1) * 4;

    float acc[8][8];
#pragma unroll
    for (int i = 0; i < 8; i++)
#pragma unroll
        for (int j = 0; j < 8; j++) acc[i][j] = 0.f;

    for (int k0 = 0; k0 < K; k0 += 8) {
        float4 a4 = *(const float4*)(Ag + (size_t)lr * K + k0 + lc);
        float4 b4 = *(const float4*)(Bg + (size_t)lr * ldb + k0 + lc);
        As[(lc + 0) * 132 + lr] = a4.x;
        As[(lc + 1) * 132 + lr] = a4.y;
        As[(lc + 2) * 132 + lr] = a4.z;
        As[(lc + 3) * 132 + lr] = a4.w;
        Bs[(lc + 0) * 132 + lr] = b4.x;
        Bs[(lc + 1) * 132 + lr] = b4.y;
        Bs[(lc + 2) * 132 + lr] = b4.z;
        Bs[(lc + 3) * 132 + lr] = b4.w;
        __syncthreads();
#pragma unroll
        for (int k = 0; k < 8; k++) {
            float4 a0 = *(const float4*)(As + k * 132 + ty * 4);
            float4 a1 = *(const float4*)(As + k * 132 + 64 + ty * 4);
            float4 b0 = *(const float4*)(Bs + k * 132 + tx * 4);
            float4 b1 = *(const float4*)(Bs + k * 132 + 64 + tx * 4);
            float av[8] = {a0.x, a0.y, a0.z, a0.w, a1.x, a1.y, a1.z, a1.w};
            float bv[8] = {b0.x, b0.y, b0.z, b0.w, b1.x, b1.y, b1.z, b1.w};
#pragma unroll
            for (int i = 0; i < 8; i++)
#pragma unroll
                for (int j = 0; j < 8; j++)
                    acc[i][j] = fmaf(av[i], bv[j], acc[i][j]);
        }
        __syncthreads();
    }

#pragma unroll
    for (int i = 0; i < 8; i++) {
        int m = row0 + ((i < 4) ? (ty * 4 + i) : (64 + ty * 4 + i - 4));
        int zi = 0;
        if (ZMODE) zi = 512 + z[m];
#pragma unroll
        for (int j = 0; j < 8; j++) {
            int n = col0 + ((j < 4) ? (tx * 4 + j) : (64 + tx * 4 + j - 4));
            float v = acc[i][j] + bias[n];
            if (bias2) v += bias2[n];
            if (ZMODE) v += B[(size_t)n * ldb + zi];
            if (ACT) v = v > 0.f ? v : 0.01f * v;
            C[(size_t)m * N + n] = v;
        }
    }
}

// ----------------------------------------------------------------------------
// Head: warp per row; actor/critic GEMV + log_softmax/entropy/prob pack.
// ----------------------------------------------------------------------------
__global__ __launch_bounds__(256) void head_kernel(
    const float* __restrict__ lf, const float* __restrict__ aw,
    const float* __restrict__ ab, const float* __restrict__ cw,
    const float* __restrict__ cb, const int* __restrict__ action,
    float* __restrict__ out) {
    int warp = (blockIdx.x * blockDim.x + threadIdx.x) >> 5;
    int lane = threadIdx.x & 31;
    if (warp >= TBTOT) return;
    float4 f = *(const float4*)(lf + (size_t)warp * FE + lane * 4);
    float r[8];
#pragma unroll
    for (int a = 0; a < 7; a++) {
        float4 w = *(const float4*)(aw + a * FE + lane * 4);
        r[a] = f.x * w.x + f.y * w.y + f.z * w.z + f.w * w.w;
    }
    {
        float4 w = *(const float4*)(cw + lane * 4);
        r[7] = f.x * w.x + f.y * w.y + f.z * w.z + f.w * w.w;
    }
#pragma unroll
    for (int a = 0; a < 8; a++)
#pragma unroll
        for (int s = 16; s > 0; s >>= 1)
            r[a] += __shfl_xor_sync(0xffffffffu, r[a], s);

    if (lane == 0) {
        float lg[7];
        float mx = -1e30f;
#pragma unroll
        for (int a = 0; a < 7; a++) {
            lg[a] = r[a] + ab[a];
            mx = fmaxf(mx, lg[a]);
        }
        float se = 0.f;
        float e[7];
#pragma unroll
        for (int a = 0; a < 7; a++) {
            e[a] = expf(lg[a] - mx);
            se += e[a];
        }
        float lse = mx + logf(se);
        float inv = 1.f / se;
        float ent = 0.f;
        float* o = out + (size_t)warp * 10;
#pragma unroll
        for (int a = 0; a < 7; a++) {
            float p = e[a] * inv;
            float lp = lg[a] - lse;
            ent -= p * lp;
            o[3 + a] = p;
        }
        int act = action[warp];
        o[0] = lg[act] - lse;
        o[1] = ent;
        o[2] = r[7] + cb[0];
    }
}

// ----------------------------------------------------------------------------
// Launch
// ----------------------------------------------------------------------------
extern "C" void kernel_launch(void* const* d_in, const int* in_sizes, int n_in,
                              void* d_out, int out_size) {
    const float* x    = (const float*)d_in[0];
    const int* done   = (const int*)d_in[1];
    const int* z      = (const int*)d_in[2];
    const int* action = (const int*)d_in[3];
    const float* h0   = (const float*)d_in[4];
    const float* c0   = (const float*)d_in[5];
    const float* c1w = (const float*)d_in[6];  const float* c1b = (const float*)d_in[7];
    const float* c2w = (const float*)d_in[8];  const float* c2b = (const float*)d_in[9];
    const float* c3w = (const float*)d_in[10]; const float* c3b = (const float*)d_in[11];
    const float* fc1w = (const float*)d_in[12]; const float* fc1b = (const float*)d_in[13];
    const float* fc2w = (const float*)d_in[14]; const float* fc2b = (const float*)d_in[15];
    const float* wih = (const float*)d_in[16]; const float* whh = (const float*)d_in[17];
    const float* bih = (const float*)d_in[18]; const float* bhh = (const float*)d_in[19];
    const float* lfw = (const float*)d_in[20]; const float* lfb = (const float*)d_in[21];
    const float* aw = (const float*)d_in[22];  const float* ab = (const float*)d_in[23];
    const float* cw = (const float*)d_in[24];  const float* cb = (const float*)d_in[25];
    float* out = (float*)d_out;

    float *pconv, *ph1, *ph2, *pxg, *pfeat, *plf, *pcst;
    __nv_bfloat16 *pw1h, *pw1l, *pw2h, *pw2l, *pwih_h, *pwih_l;
    __nv_bfloat16 *pc1h, *pc1l, *pc2h, *pc2l, *pc3h, *pc3l;
    __nv_bfloat16 *phhA, *phlA, *phhB, *phlB;
    cudaGetSymbolAddress((void**)&pconv, g_conv);
    cudaGetSymbolAddress((void**)&ph1, g_h1);
    cudaGetSymbolAddress((void**)&ph2, g_h2);
    cudaGetSymbolAddress((void**)&pxg, g_xg);
    cudaGetSymbolAddress((void**)&pfeat, g_feat);
    cudaGetSymbolAddress((void**)&plf, g_lf);
    cudaGetSymbolAddress((void**)&pcst, g_cst);
    cudaGetSymbolAddress((void**)&phhA, g_hhA);
    cudaGetSymbolAddress((void**)&phlA, g_hlA);
    cudaGetSymbolAddress((void**)&phhB, g_hhB);
    cudaGetSymbolAddress((void**)&phlB, g_hlB);
    cudaGetSymbolAddress((void**)&pw1h, g_wfc1_hi);
    cudaGetSymbolAddress((void**)&pw1l, g_wfc1_lo);
    cudaGetSymbolAddress((void**)&pw2h, g_wfc2_hi);
    cudaGetSymbolAddress((void**)&pw2l, g_wfc2_lo);
    cudaGetSymbolAddress((void**)&pwih_h, g_wih_hi);
    cudaGetSymbolAddress((void**)&pwih_l, g_wih_lo);
    cudaGetSymbolAddress((void**)&pc1h, g_cw1h);
    cudaGetSymbolAddress((void**)&pc1l, g_cw1l);
    cudaGetSymbolAddress((void**)&pc2h, g_cw2h);
    cudaGetSymbolAddress((void**)&pc2l, g_cw2l);
    cudaGetSymbolAddress((void**)&pc3h, g_cw3h);
    cudaGetSymbolAddress((void**)&pc3l, g_cw3l);

    const int SMEM_TG = 128 * 132 * 4;
    cudaFuncSetAttribute(tgemm<1>, cudaFuncAttributeMaxDynamicSharedMemorySize, SMEM_TG);
    cudaFuncSetAttribute(tgemm<0>, cudaFuncAttributeMaxDynamicSharedMemorySize, SMEM_TG);
    const int SMEM_CONV = 2 * IMG_BYTES + 2 * CW_HALF;
    cudaFuncSetAttribute(conv3_mma, cudaFuncAttributeMaxDynamicSharedMemorySize, SMEM_CONV);
    cudaFuncSetAttribute(lstm_persist, cudaFuncAttributeMaxDynamicSharedMemorySize, LS_SMEM);

    wcprep<<<25, 256>>>(c1w, pc1h, pc1l, 25);
    wcprep<<<9, 256>>>(c2w, pc2h, pc2l, 9);
    wcprep<<<9, 256>>>(c3w, pc3h, pc3l, 9);
    conv3_mma<<<TBTOT, 256, SMEM_CONV>>>(x, c1b, c2b, c3b);
    wprep<<<(512 * 1024 + 255) / 256, 256>>>(fc1w, pw1h, pw1l, 512 * 1024);
    tgemm<1><<<dim3(512 / 128, TBTOT / 128), 256, SMEM_TG>>>(
        pconv, pw1h, pw1l, fc1b, nullptr, ph1, TBTOT, 512, 4096);

    wprep<<<(512 * 128 + 255) / 256, 256>>>(fc2w, pw2h, pw2l, 512 * 128);
    wprep<<<(2048 * 128 + 255) / 256, 256>>>(wih, pwih_h, pwih_l, 2048 * 128);
    wlstm_prep<<<(2048 * 128 + 255) / 256, 256>>>(whh);
    pack_h0<<<(B_ENV * HID + 255) / 256, 256>>>(h0);
    cudaMemcpyAsync(pcst, c0, (size_t)B_ENV * HID * sizeof(float),
                    cudaMemcpyDeviceToDevice, 0);

    tgemm<1><<<dim3(512 / 128, TBTOT / 128), 256, SMEM_TG>>>(
        ph1, pw2h, pw2l, fc2b, nullptr, ph2, TBTOT, 512, 512);
    tgemm<0><<<dim3(2048 / 128, TBTOT / 128), 256, SMEM_TG>>>(
        ph2, pwih_h, pwih_l, bih, bhh, pxg, TBTOT, 2048, 512);

    // entire recurrence in ONE persistent kernel (pipelined staging)
    lstm_persist<<<NB_LSTM, 256, LS_SMEM>>>(pxg, done, phhA, phlA, phhB, phlB,
                                            pcst, pfeat);

    // lofeat: feat(512) + one-hot(z) via epilogue, ldb=520, leaky
    sgemm128<1, 1><<<dim3(FE / 128, TBTOT / 128), 256>>>(
        pfeat, lfw, lfb, nullptr, plf, TBTOT, FE, 512, 520, z);

    // heads + softmax stats
    head_kernel<<<TBTOT / 8, 256>>>(plf, aw, ab, cw, cb, action, out);
}

// round 10
// speedup vs baseline: 1.6280x; 1.0510x over previous
#include <cuda_runtime.h>
#include <cuda_bf16.h>
#include <math.h>
#include <stdint.h>

#define T_STEPS 128
#define B_ENV   128
#define HID     512
#define TBTOT   (T_STEPS * B_ENV)
#define ZD      8
#define AD      7
#define FE      128
#define NB_LSTM 128

// ----------------------------------------------------------------------------
// Scratch (device globals; no allocation allowed)
// ----------------------------------------------------------------------------
__device__ float g_conv[TBTOT * 4096];
__device__ float g_h1[TBTOT * HID];
__device__ float g_h2[TBTOT * HID];
__device__ float g_xg[TBTOT * 2048];
__device__ float g_feat[TBTOT * HID];
__device__ float g_lf[TBTOT * FE];
__device__ float g_cst[B_ENV * HID];
__device__ __nv_bfloat16 g_hhA[B_ENV * HID];
__device__ __nv_bfloat16 g_hlA[B_ENV * HID];
__device__ __nv_bfloat16 g_hhB[B_ENV * HID];
__device__ __nv_bfloat16 g_hlB[B_ENV * HID];
// W_hh reordered: [blk 128][n 16][k 512], n = 2*jj + (g&1) + 8*(g>>1)
__device__ __nv_bfloat16 g_wlh[128 * 16 * 512];
__device__ __nv_bfloat16 g_wll[128 * 16 * 512];
__device__ __nv_bfloat16 g_wfc1_hi[512 * 4096];
__device__ __nv_bfloat16 g_wfc1_lo[512 * 4096];
__device__ __nv_bfloat16 g_wfc2_hi[512 * 512];
__device__ __nv_bfloat16 g_wfc2_lo[512 * 512];
__device__ __nv_bfloat16 g_wih_hi[2048 * 512];
__device__ __nv_bfloat16 g_wih_lo[2048 * 512];
__device__ __nv_bfloat16 g_cw1h[25 * 256];
__device__ __nv_bfloat16 g_cw1l[25 * 256];
__device__ __nv_bfloat16 g_cw2h[9 * 256];
__device__ __nv_bfloat16 g_cw2l[9 * 256];
__device__ __nv_bfloat16 g_cw3h[9 * 256];
__device__ __nv_bfloat16 g_cw3l[9 * 256];
// grid barrier state
__device__ unsigned int g_bar_cnt;
__device__ volatile unsigned int g_bar_gen;

// ============================================================================
// Helpers
// ============================================================================
__device__ __forceinline__ uint32_t smem_to_u32(const void* smem_ptr) {
    uint32_t addr;
    asm("{ .reg .u64 tmp; cvta.to.shared.u64 tmp, %1; cvt.u32.u64 %0, tmp; }"
        : "=r"(addr) : "l"(smem_ptr));
    return addr;
}

__device__ __forceinline__ void ldsm4(uint32_t addr, uint32_t* r) {
    asm volatile("ldmatrix.sync.aligned.m8n8.x4.shared.b16 {%0,%1,%2,%3}, [%4];"
        : "=r"(r[0]), "=r"(r[1]), "=r"(r[2]), "=r"(r[3]) : "r"(addr));
}

__device__ __forceinline__ void mma16816(float* d, const uint32_t* a,
                                         const uint32_t* b) {
    asm volatile(
        "mma.sync.aligned.m16n8k16.row.col.f32.bf16.bf16.f32 "
        "{%0,%1,%2,%3}, {%4,%5,%6,%7}, {%8,%9}, {%0,%1,%2,%3};"
        : "+f"(d[0]), "+f"(d[1]), "+f"(d[2]), "+f"(d[3])
        : "r"(a[0]), "r"(a[1]), "r"(a[2]), "r"(a[3]), "r"(b[0]), "r"(b[1]));
}

__device__ __forceinline__ void split2(float x, float y, uint32_t& hi, uint32_t& lo) {
    __nv_bfloat16 hx = __float2bfloat16(x), hy = __float2bfloat16(y);
    __nv_bfloat162 h2; h2.x = hx; h2.y = hy;
    hi = reinterpret_cast<uint32_t&>(h2);
    float lx = x - __bfloat162float(hx);
    float ly = y - __bfloat162float(hy);
    __nv_bfloat162 l2 = __floats2bfloat162_rn(lx, ly);
    lo = reinterpret_cast<uint32_t&>(l2);
}

// software grid barrier (all NB_LSTM blocks co-resident by construction)
__device__ __forceinline__ void grid_bar() {
    __threadfence();
    __syncthreads();
    if (threadIdx.x == 0) {
        unsigned int gen = g_bar_gen;
        if (atomicAdd(&g_bar_cnt, 1u) == NB_LSTM - 1) {
            g_bar_cnt = 0;
            __threadfence();
            g_bar_gen = gen + 1;
        } else {
            while (g_bar_gen == gen) { }
            __threadfence();
        }
    }
    __syncthreads();
}

// ----------------------------------------------------------------------------
// Weight prep kernels
// ----------------------------------------------------------------------------
__global__ void wprep(const float* __restrict__ w, __nv_bfloat16* __restrict__ hi,
                      __nv_bfloat16* __restrict__ lo, int total4) {
    int idx = blockIdx.x * blockDim.x + threadIdx.x;
    if (idx >= total4) return;
    float4 a = *(const float4*)(w + (size_t)idx * 4);
    uint32_t h0, h1, l0, l1;
    split2(a.x, a.y, h0, l0);
    split2(a.z, a.w, h1, l1);
    *(uint2*)(hi + (size_t)idx * 4) = make_uint2(h0, h1);
    *(uint2*)(lo + (size_t)idx * 4) = make_uint2(l0, l1);
}

__global__ void wcprep(const float* __restrict__ w, __nv_bfloat16* __restrict__ hi,
                       __nv_bfloat16* __restrict__ lo, int taps) {
    int idx = blockIdx.x * blockDim.x + threadIdx.x;
    if (idx >= taps * 256) return;
    int r = idx & 255;
    int t = idx >> 8;
    float v = w[r * taps + t];
    __nv_bfloat16 hv = __float2bfloat16(v);
    float lv = v - __bfloat162float(hv);
    hi[t * 256 + r] = hv;
    lo[t * 256 + r] = __float2bfloat16(lv);
}

// whh [2048][512] -> per-block gate-interleaved rows:
// blk = j>>2, jj = j&3, n = 2*jj + (g&1) + 8*(g>>1); dst row = blk*16 + n
__global__ void wlstm_prep(const float* __restrict__ whh) {
    int idx = blockIdx.x * blockDim.x + threadIdx.x;
    if (idx >= 2048 * 128) return;
    int row = idx >> 7;
    int k4 = (idx & 127) * 4;
    int g = row >> 9, j = row & 511;
    int blk = j >> 2, jj = j & 3;
    int n = 2 * jj + (g & 1) + 8 * (g >> 1);
    size_t dst = ((size_t)(blk * 16 + n)) * 512 + k4;
    float4 v = *(const float4*)(whh + (size_t)row * 512 + k4);
    uint32_t h0, h1, l0, l1;
    split2(v.x, v.y, h0, l0);
    split2(v.z, v.w, h1, l1);
    *(uint2*)(g_wlh + dst) = make_uint2(h0, h1);
    *(uint2*)(g_wll + dst) = make_uint2(l0, l1);
}

__global__ void pack_h0(const float* __restrict__ h0) {
    int i = blockIdx.x * blockDim.x + threadIdx.x;
    if (i >= B_ENV * HID) return;
    float v = h0[i];
    __nv_bfloat16 hv = __float2bfloat16(v);
    g_hhA[i] = hv;
    g_hlA[i] = __float2bfloat16(v - __bfloat162float(hv));
}

// ----------------------------------------------------------------------------
// HMMA GEMM (proven): 3-term bf16 split, fp32 accum
// ----------------------------------------------------------------------------
#define SMSTR 80

template <int ACT>
__global__ __launch_bounds__(256) void tgemm(
    const float* __restrict__ A, const __nv_bfloat16* __restrict__ Whi,
    const __nv_bfloat16* __restrict__ Wlo,
    const float* __restrict__ bias, const float* __restrict__ bias2,
    float* __restrict__ C, int M, int N, int K) {
    extern __shared__ uint8_t sm[];
    const uint32_t oAh = 0, oAl = 10240, oBh = 20480, oBl = 30720;
    uint32_t sb = smem_to_u32(sm);
    int tid = threadIdx.x;
    int lane = tid & 31;
    int wid = tid >> 5;
    int wm = wid & 3, wn = wid >> 2;
    int m0 = blockIdx.y * 128, n0 = blockIdx.x * 128;
    const float* Ag = A + (size_t)m0 * K;

    float acc[2][8][4];
#pragma unroll
    for (int i = 0; i < 2; i++)
#pragma unroll
        for (int j = 0; j < 8; j++)
#pragma unroll
            for (int q = 0; q < 4; q++) acc[i][j][q] = 0.f;

    int nslab = K / 32;
    float4 aR[4];
    uint4 bRh[2], bRl[2];

    auto load_slab = [&](int s) {
#pragma unroll
        for (int i = 0; i < 4; i++) {
            int row = (tid >> 3) + 32 * i;
            aR[i] = *(const float4*)(Ag + (size_t)row * K + s * 32 + (tid & 7) * 4);
        }
#pragma unroll
        for (int i = 0; i < 2; i++) {
            int row = (tid >> 2) + 64 * i;
            size_t boff = ((size_t)(n0 + row) * K + s * 32);
            bRh[i] = *(const uint4*)((const uint8_t*)(Whi + boff) + (tid & 3) * 16);
            bRl[i] = *(const uint4*)((const uint8_t*)(Wlo + boff) + (tid & 3) * 16);
        }
    };
    auto store_slab = [&]() {
#pragma unroll
        for (int i = 0; i < 4; i++) {
            int row = (tid >> 3) + 32 * i;
            int col8 = (tid & 7) * 8;
            uint32_t h0, h1, l0, l1;
            split2(aR[i].x, aR[i].y, h0, l0);
            split2(aR[i].z, aR[i].w, h1, l1);
            *(uint2*)(sm + oAh + row * SMSTR + col8) = make_uint2(h0, h1);
            *(uint2*)(sm + oAl + row * SMSTR + col8) = make_uint2(l0, l1);
        }
#pragma unroll
        for (int i = 0; i < 2; i++) {
            int row = (tid >> 2) + 64 * i;
            int c16 = (tid & 3) * 16;
            *(uint4*)(sm + oBh + row * SMSTR + c16) = bRh[i];
            *(uint4*)(sm + oBl + row * SMSTR + c16) = bRl[i];
        }
    };

    load_slab(0);
    store_slab();
    __syncthreads();

    int g = lane >> 3;
    int arow_off = (lane & 7) + (g & 1) * 8;
    int akb_off = (g >> 1) * 16;
    int brow_off = (lane & 7) + (g >> 1) * 8;
    int bkb_off = (g & 1) * 16;

    for (int s = 0; s < nslab; s++) {
        bool more = (s + 1 < nslab);
        if (more) load_slab(s + 1);

#pragma unroll
        for (int kk2 = 0; kk2 < 2; kk2++) {
            int kb = kk2 * 32;
            uint32_t ah[2][4], al[2][4], bh[4][4], bl[4][4];
#pragma unroll
            for (int mi = 0; mi < 2; mi++) {
                uint32_t r = (uint32_t)((wm * 32 + mi * 16 + arow_off) * SMSTR +
                                        kb + akb_off);
                ldsm4(sb + oAh + r, ah[mi]);
                ldsm4(sb + oAl + r, al[mi]);
            }
#pragma unroll
            for (int pi = 0; pi < 4; pi++) {
                uint32_t r = (uint32_t)((wn * 64 + pi * 16 + brow_off) * SMSTR +
                                        kb + bkb_off);
                ldsm4(sb + oBh + r, bh[pi]);
                ldsm4(sb + oBl + r, bl[pi]);
            }
#pragma unroll
            for (int mi = 0; mi < 2; mi++)
#pragma unroll
                for (int pi = 0; pi < 4; pi++)
#pragma unroll
                    for (int half = 0; half < 2; half++) {
                        float* d = acc[mi][pi * 2 + half];
                        mma16816(d, ah[mi], &bh[pi][half * 2]);
                        mma16816(d, ah[mi], &bl[pi][half * 2]);
                        mma16816(d, al[mi], &bh[pi][half * 2]);
                    }
        }
        __syncthreads();
        if (more) {
            store_slab();
            __syncthreads();
        }
    }

    float* ct = (float*)sm;
#pragma unroll
    for (int mi = 0; mi < 2; mi++) {
        int r0 = wm * 32 + mi * 16 + (lane >> 2);
#pragma unroll
        for (int ni = 0; ni < 8; ni++) {
            int c = wn * 64 + ni * 8 + (lane & 3) * 2;
            float b0 = bias[n0 + c], b1 = bias[n0 + c + 1];
            if (bias2) { b0 += bias2[n0 + c]; b1 += bias2[n0 + c + 1]; }
            float v0 = acc[mi][ni][0] + b0;
            float v1 = acc[mi][ni][1] + b1;
            float v2 = acc[mi][ni][2] + b0;
            float v3 = acc[mi][ni][3] + b1;
            if (ACT) {
                v0 = v0 > 0.f ? v0 : 0.01f * v0;
                v1 = v1 > 0.f ? v1 : 0.01f * v1;
                v2 = v2 > 0.f ? v2 : 0.01f * v2;
                v3 = v3 > 0.f ? v3 : 0.01f * v3;
            }
            ct[r0 * 132 + c] = v0;
            ct[r0 * 132 + c + 1] = v1;
            ct[(r0 + 8) * 132 + c] = v2;
            ct[(r0 + 8) * 132 + c + 1] = v3;
        }
    }
    __syncthreads();
    {
        int r8 = tid >> 5;
        int c4 = (tid & 31) * 4;
#pragma unroll
        for (int p = 0; p < 16; p++) {
            int r = p * 8 + r8;
            float4 v = *(const float4*)(ct + r * 132 + c4);
            *(float4*)(C + (size_t)(m0 + r) * N + n0 + c4) = v;
        }
    }
}

// ----------------------------------------------------------------------------
// HMMA conv (proven)
// ----------------------------------------------------------------------------
#define PSTR 48
#define IMG_BYTES (400 * PSTR)
#define CW_OFF   (2 * IMG_BYTES)
#define CW_HALF  12800

template <int KS, int P, int LAST>
__device__ __forceinline__ void conv_hmma_layer(
    uint8_t* csm, uint32_t sbase, const __nv_bfloat16* wsrc_h,
    const __nv_bfloat16* wsrc_l, const float* __restrict__ bias,
    float* gout, int tid, int lane, int wid) {
    const int taps = KS * KS;
    {
        const uint4* sh = (const uint4*)wsrc_h;
        const uint4* sl = (const uint4*)wsrc_l;
        uint4* dh = (uint4*)(csm + CW_OFF);
        uint4* dl = (uint4*)(csm + CW_OFF + CW_HALF);
        for (int i = tid; i < taps * 32; i += 256) {
            dh[i] = sh[i];
            dl[i] = sl[i];
        }
    }
    __syncthreads();

    float acc[2][2][4];
#pragma unroll
    for (int a = 0; a < 2; a++)
#pragma unroll
        for (int b = 0; b < 2; b++)
#pragma unroll
            for (int q = 0; q < 4; q++) acc[a][b][q] = 0.f;

    int g = lane >> 3;
    int h0 = wid * 2;
    uint32_t aoff[2];
#pragma unroll
    for (int mi = 0; mi < 2; mi++)
        aoff[mi] = (uint32_t)(((h0 + mi + 2) * 20 + 2 + (lane & 7) + (g & 1) * 8) * PSTR +
                              (g >> 1) * 16);
    uint32_t boff = (uint32_t)(((lane & 7) + (g >> 1) * 8) * 32 + (g & 1) * 16);
    uint32_t wb_h = sbase + CW_OFF;
    uint32_t wb_l = sbase + CW_OFF + CW_HALF;

#pragma unroll
    for (int kh = 0; kh < KS; kh++) {
#pragma unroll
        for (int kw = 0; kw < KS; kw++) {
            int t = kh * KS + kw;
            int shift = ((kh - P) * 20 + (kw - P)) * PSTR;
            uint32_t bh4[4], bl4[4];
            ldsm4(wb_h + t * 512 + boff, bh4);
            ldsm4(wb_l + t * 512 + boff, bl4);
#pragma unroll
            for (int mi = 0; mi < 2; mi++) {
                uint32_t ah[4], al[4];
                ldsm4(sbase + aoff[mi] + shift, ah);
                ldsm4(sbase + IMG_BYTES + aoff[mi] + shift, al);
#pragma unroll
                for (int nh = 0; nh < 2; nh++) {
                    mma16816(acc[mi][nh], ah, &bh4[nh * 2]);
                    mma16816(acc[mi][nh], ah, &bl4[nh * 2]);
                    mma16816(acc[mi][nh], al, &bh4[nh * 2]);
                }
            }
        }
    }
    __syncthreads();

#pragma unroll
    for (int mi = 0; mi < 2; mi++) {
        int h = h0 + mi;
#pragma unroll
        for (int nh = 0; nh < 2; nh++) {
            int co = nh * 8 + (lane & 3) * 2;
            float b0 = bias[co], b1 = bias[co + 1];
#pragma unroll
            for (int rr = 0; rr < 2; rr++) {
                int w = (lane >> 2) + rr * 8;
                float v0 = acc[mi][nh][rr * 2 + 0] + b0;
                float v1 = acc[mi][nh][rr * 2 + 1] + b1;
                v0 = v0 > 0.f ? v0 : 0.01f * v0;
                v1 = v1 > 0.f ? v1 : 0.01f * v1;
                if (LAST) {
                    gout[co * 256 + h * 16 + w] = v0;
                    gout[(co + 1) * 256 + h * 16 + w] = v1;
                } else {
                    uint32_t hp, lp;
                    split2(v0, v1, hp, lp);
                    int pb = ((h + 2) * 20 + (w + 2)) * PSTR + co * 2;
                    *(uint32_t*)(csm + pb) = hp;
                    *(uint32_t*)(csm + IMG_BYTES + pb) = lp;
                }
            }
        }
    }
    __syncthreads();
}

__global__ __launch_bounds__(256) void conv3_mma(
    const float* __restrict__ x,
    const float* __restrict__ b1, const float* __restrict__ b2,
    const float* __restrict__ b3) {
    extern __shared__ uint8_t csm[];
    uint32_t sbase = smem_to_u32(csm);
    int tid = threadIdx.x;
    int lane = tid & 31;
    int wid = tid >> 5;
    int img = blockIdx.x;
    const float* xi = x + (size_t)img * 4096;

    for (int i = tid; i < 2 * IMG_BYTES / 4; i += 256)
        ((uint32_t*)csm)[i] = 0;
    __syncthreads();
    for (int i = tid; i < 4096; i += 256) {
        int ci = i >> 8, p = i & 255;
        int h = p >> 4, w = p & 15;
        float v = xi[i];
        __nv_bfloat16 hv = __float2bfloat16(v);
        float lv = v - __bfloat162float(hv);
        int pb = ((h + 2) * 20 + (w + 2)) * PSTR + ci * 2;
        *(__nv_bfloat16*)(csm + pb) = hv;
        *(__nv_bfloat16*)(csm + IMG_BYTES + pb) = __float2bfloat16(lv);
    }
    __syncthreads();

    float* gout = g_conv + (size_t)img * 4096;
    conv_hmma_layer<5, 2, 0>(csm, sbase, g_cw1h, g_cw1l, b1, gout, tid, lane, wid);
    conv_hmma_layer<3, 1, 0>(csm, sbase, g_cw2h, g_cw2l, b2, gout, tid, lane, wid);
    conv_hmma_layer<3, 1, 1>(csm, sbase, g_cw3h, g_cw3l, b3, gout, tid, lane, wid);
}

// ----------------------------------------------------------------------------
// Persistent LSTM v3: 128 blocks, N=16 gate-interleaved tiles; pipelined
// staging, register c. Block b owns j = b*4..b*4+3 of all 4 gates.
// ----------------------------------------------------------------------------
__device__ __forceinline__ float sigm(float x) { return 1.f / (1.f + expf(-x)); }

#define LW_STR   1040
#define LS_W_SZ  (2 * 16 * LW_STR)                 // 33280
#define LS_A_OFF LS_W_SZ
#define LS_A_BUF (2 * 128 * SMSTR)                 // 20480 (hi+lo)
#define LS_M_OFF (LS_A_OFF + 2 * LS_A_BUF)         // 74240
#define LS_SMEM  (LS_M_OFF + 512)                  // 74752

__global__ __launch_bounds__(256) void lstm_persist(
    const float* __restrict__ xg, const int* __restrict__ done,
    __nv_bfloat16* __restrict__ hAh, __nv_bfloat16* __restrict__ hAl,
    __nv_bfloat16* __restrict__ hBh, __nv_bfloat16* __restrict__ hBl,
    float* __restrict__ c_st, float* __restrict__ feat) {
    extern __shared__ uint8_t psm[];
    float* s_m = (float*)(psm + LS_M_OFF);
    uint32_t sbW = smem_to_u32(psm);
    int tid = threadIdx.x, lane = tid & 31, wid = tid >> 5;
    int blk = blockIdx.x;
    int jb4 = blk * 4;

    // resident weights: 16 rows hi + 16 rows lo, 64 uint4/row
    {
        const uint4* Wh = (const uint4*)(g_wlh + (size_t)blk * 16 * 512);
        const uint4* Wl = (const uint4*)(g_wll + (size_t)blk * 16 * 512);
#pragma unroll
        for (int i = 0; i < 4; i++) {
            int i4 = tid + 256 * i;   // 1024 uint4 per part
            int r = i4 >> 6, q = i4 & 63;
            *(uint4*)(psm + r * LW_STR + q * 16) = Wh[i4];
            *(uint4*)(psm + 16 * LW_STR + r * LW_STR + q * 16) = Wl[i4];
        }
    }

    int r1 = wid * 16 + (lane >> 2);
    int L = lane & 3;            // j offset within block's 4 columns
    int gq = lane >> 3;
    uint32_t arow = (uint32_t)((wid * 16 + (lane & 7) + (gq & 1) * 8) * SMSTR +
                               (gq >> 1) * 16);
    uint32_t brow = (uint32_t)(((lane & 7) + (gq >> 1) * 8) * LW_STR + (gq & 1) * 16);
    int sr0 = tid >> 2, sq = tid & 3;

    // c state in registers: this thread owns (r1 + rr*8, jb4 + L)
    float creg[2];
#pragma unroll
    for (int rr = 0; rr < 2; rr++)
        creg[rr] = c_st[(size_t)(r1 + rr * 8) * 512 + jb4 + L];
    __syncthreads();

    uint4 pvh[2], pvl[2];

    for (int t = 0; t < T_STEPS; t++) {
        const __nv_bfloat16* hih = (t & 1) ? hBh : hAh;
        const __nv_bfloat16* hil = (t & 1) ? hBl : hAl;
        __nv_bfloat16* hoh = (t & 1) ? hAh : hBh;
        __nv_bfloat16* hol = (t & 1) ? hAl : hBl;

        if (tid < 128) s_m[tid] = done[t * 128 + tid] ? 0.f : 1.f;

        // acc init from xg; gate = cc + 2*pi (n = pi*8 + L*2 + cc after reorder)
        float acc[2][4];
#pragma unroll
        for (int pi = 0; pi < 2; pi++)
#pragma unroll
            for (int rr = 0; rr < 2; rr++)
#pragma unroll
                for (int cc = 0; cc < 2; cc++)
                    acc[pi][rr * 2 + cc] = xg[(size_t)(t * 128 + r1 + rr * 8) * 2048 +
                                              (cc + 2 * pi) * 512 + jb4 + L];
        __syncthreads();  // masks visible

        auto ld_slab = [&](int s) {
#pragma unroll
            for (int q = 0; q < 2; q++) {
                int r = sr0 + 64 * q;
                bool zz = (s_m[r] == 0.f);
                pvh[q] = zz ? make_uint4(0, 0, 0, 0)
                            : *(const uint4*)(hih + (size_t)r * 512 + s * 32 + sq * 8);
                pvl[q] = zz ? make_uint4(0, 0, 0, 0)
                            : *(const uint4*)(hil + (size_t)r * 512 + s * 32 + sq * 8);
            }
        };
        auto st_slab = [&](int buf) {
            uint8_t* base = psm + LS_A_OFF + buf * LS_A_BUF;
#pragma unroll
            for (int q = 0; q < 2; q++) {
                int r = sr0 + 64 * q;
                *(uint4*)(base + r * SMSTR + sq * 16) = pvh[q];
                *(uint4*)(base + 128 * SMSTR + r * SMSTR + sq * 16) = pvl[q];
            }
        };

        ld_slab(0);
        st_slab(0);
        __syncthreads();

        for (int s = 0; s < 16; s++) {
            if (s < 15) ld_slab(s + 1);
            uint32_t sbA = sbW + LS_A_OFF + (uint32_t)((s & 1) * LS_A_BUF);
#pragma unroll
            for (int kk2 = 0; kk2 < 2; kk2++) {
                int kb = kk2 * 32;
                uint32_t ah[4], al[4], bh4[4], bl4[4];
                ldsm4(sbA + arow + kb, ah);
                ldsm4(sbA + 128 * SMSTR + arow + kb, al);
                uint32_t bo = brow + s * 64 + kb;
                ldsm4(sbW + bo, bh4);
                ldsm4(sbW + 16 * LW_STR + bo, bl4);
#pragma unroll
                for (int pi = 0; pi < 2; pi++) {
                    float* d = acc[pi];
                    mma16816(d, ah, &bh4[pi * 2]);
                    mma16816(d, ah, &bl4[pi * 2]);
                    mma16816(d, al, &bh4[pi * 2]);
                }
            }
            if (s < 15) {
                st_slab((s + 1) & 1);
                __syncthreads();
            }
        }

        // epilogue: 4 gates fully thread-local per (r, j)
#pragma unroll
        for (int rr = 0; rr < 2; rr++) {
            int r = r1 + rr * 8;
            float m = s_m[r];
            int j = jb4 + L;
            float gi = acc[0][rr * 2 + 0];
            float gf = acc[0][rr * 2 + 1];
            float gg = acc[1][rr * 2 + 0];
            float go = acc[1][rr * 2 + 1];
            float cn = sigm(gf) * (creg[rr] * m) + sigm(gi) * tanhf(gg);
            float hn = sigm(go) * tanhf(cn);
            creg[rr] = cn;
            feat[(size_t)(t * 128 + r) * 512 + j] = hn;
            __nv_bfloat16 hh = __float2bfloat16(hn);
            hoh[(size_t)r * 512 + j] = hh;
            hol[(size_t)r * 512 + j] = __float2bfloat16(hn - __bfloat162float(hh));
        }
        grid_bar();
    }
}

// ----------------------------------------------------------------------------
// Scalar SGEMM kept for lofeat (with z one-hot epilogue)
// ----------------------------------------------------------------------------
template <int ACT, int ZMODE>
__global__ __launch_bounds__(256, 2) void sgemm128(
    const float* __restrict__ A, const float* __restrict__ B,
    const float* __restrict__ bias, const float* __restrict__ bias2,
    float* __restrict__ C, int M, int N, int K, int ldb,
    const int* __restrict__ z) {
    __shared__ float As[8 * 132];
    __shared__ float Bs[8 * 132];
    int tid = threadIdx.x;
    int tx = tid & 15, ty = tid >> 4;
    int row0 = blockIdx.y * 128;
    int col0 = blockIdx.x * 128;
    const float* Ag = A + (size_t)row0 * K;
    const float* Bg = B + (size_t)col0 * ldb;
    int lr = tid >> 1;
    int lc = (tid & 1) * 4;

    float acc[8][8];
#pragma unroll
    for (int i = 0; i < 8; i++)
#pragma unroll
        for (int j = 0; j < 8; j++) acc[i][j] = 0.f;

    for (int k0 = 0; k0 < K; k0 += 8) {
        float4 a4 = *(const float4*)(Ag + (size_t)lr * K + k0 + lc);
        float4 b4 = *(const float4*)(Bg + (size_t)lr * ldb + k0 + lc);
        As[(lc + 0) * 132 + lr] = a4.x;
        As[(lc + 1) * 132 + lr] = a4.y;
        As[(lc + 2) * 132 + lr] = a4.z;
        As[(lc + 3) * 132 + lr] = a4.w;
        Bs[(lc + 0) * 132 + lr] = b4.x;
        Bs[(lc + 1) * 132 + lr] = b4.y;
        Bs[(lc + 2) * 132 + lr] = b4.z;
        Bs[(lc + 3) * 132 + lr] = b4.w;
        __syncthreads();
#pragma unroll
        for (int k = 0; k < 8; k++) {
            float4 a0 = *(const float4*)(As + k * 132 + ty * 4);
            float4 a1 = *(const float4*)(As + k * 132 + 64 + ty * 4);
            float4 b0 = *(const float4*)(Bs + k * 132 + tx * 4);
            float4 b1 = *(const float4*)(Bs + k * 132 + 64 + tx * 4);
            float av[8] = {a0.x, a0.y, a0.z, a0.w, a1.x, a1.y, a1.z, a1.w};
            float bv[8] = {b0.x, b0.y, b0.z, b0.w, b1.x, b1.y, b1.z, b1.w};
#pragma unroll
            for (int i = 0; i < 8; i++)
#pragma unroll
                for (int j = 0; j < 8; j++)
                    acc[i][j] = fmaf(av[i], bv[j], acc[i][j]);
        }
        __syncthreads();
    }

#pragma unroll
    for (int i = 0; i < 8; i++) {
        int m = row0 + ((i < 4) ? (ty * 4 + i) : (64 + ty * 4 + i - 4));
        int zi = 0;
        if (ZMODE) zi = 512 + z[m];
#pragma unroll
        for (int j = 0; j < 8; j++) {
            int n = col0 + ((j < 4) ? (tx * 4 + j) : (64 + tx * 4 + j - 4));
            float v = acc[i][j] + bias[n];
            if (bias2) v += bias2[n];
            if (ZMODE) v += B[(size_t)n * ldb + zi];
            if (ACT) v = v > 0.f ? v : 0.01f * v;
            C[(size_t)m * N + n] = v;
        }
    }
}

// ----------------------------------------------------------------------------
// Head: warp per row; actor/critic GEMV + log_softmax/entropy/prob pack.
// ----------------------------------------------------------------------------
__global__ __launch_bounds__(256) void head_kernel(
    const float* __restrict__ lf, const float* __restrict__ aw,
    const float* __restrict__ ab, const float* __restrict__ cw,
    const float* __restrict__ cb, const int* __restrict__ action,
    float* __restrict__ out) {
    int warp = (blockIdx.x * blockDim.x + threadIdx.x) >> 5;
    int lane = threadIdx.x & 31;
    if (warp >= TBTOT) return;
    float4 f = *(const float4*)(lf + (size_t)warp * FE + lane * 4);
    float r[8];
#pragma unroll
    for (int a = 0; a < 7; a++) {
        float4 w = *(const float4*)(aw + a * FE + lane * 4);
        r[a] = f.x * w.x + f.y * w.y + f.z * w.z + f.w * w.w;
    }
    {
        float4 w = *(const float4*)(cw + lane * 4);
        r[7] = f.x * w.x + f.y * w.y + f.z * w.z + f.w * w.w;
    }
#pragma unroll
    for (int a = 0; a < 8; a++)
#pragma unroll
        for (int s = 16; s > 0; s >>= 1)
            r[a] += __shfl_xor_sync(0xffffffffu, r[a], s);

    if (lane == 0) {
        float lg[7];
        float mx = -1e30f;
#pragma unroll
        for (int a = 0; a < 7; a++) {
            lg[a] = r[a] + ab[a];
            mx = fmaxf(mx, lg[a]);
        }
        float se = 0.f;
        float e[7];
#pragma unroll
        for (int a = 0; a < 7; a++) {
            e[a] = expf(lg[a] - mx);
            se += e[a];
        }
        float lse = mx + logf(se);
        float inv = 1.f / se;
        float ent = 0.f;
        float* o = out + (size_t)warp * 10;
#pragma unroll
        for (int a = 0; a < 7; a++) {
            float p = e[a] * inv;
            float lp = lg[a] - lse;
            ent -= p * lp;
            o[3 + a] = p;
        }
        int act = action[warp];
        o[0] = lg[act] - lse;
        o[1] = ent;
        o[2] = r[7] + cb[0];
    }
}

// ----------------------------------------------------------------------------
// Launch
// ----------------------------------------------------------------------------
extern "C" void kernel_launch(void* const* d_in, const int* in_sizes, int n_in,
                              void* d_out, int out_size) {
    const float* x    = (const float*)d_in[0];
    const int* done   = (const int*)d_in[1];
    const int* z      = (const int*)d_in[2];
    const int* action = (const int*)d_in[3];
    const float* h0   = (const float*)d_in[4];
    const float* c0   = (const float*)d_in[5];
    const float* c1w = (const float*)d_in[6];  const float* c1b = (const float*)d_in[7];
    const float* c2w = (const float*)d_in[8];  const float* c2b = (const float*)d_in[9];
    const float* c3w = (const float*)d_in[10]; const float* c3b = (const float*)d_in[11];
    const float* fc1w = (const float*)d_in[12]; const float* fc1b = (const float*)d_in[13];
    const float* fc2w = (const float*)d_in[14]; const float* fc2b = (const float*)d_in[15];
    const float* wih = (const float*)d_in[16]; const float* whh = (const float*)d_in[17];
    const float* bih = (const float*)d_in[18]; const float* bhh = (const float*)d_in[19];
    const float* lfw = (const float*)d_in[20]; const float* lfb = (const float*)d_in[21];
    const float* aw = (const float*)d_in[22];  const float* ab = (const float*)d_in[23];
    const float* cw = (const float*)d_in[24];  const float* cb = (const float*)d_in[25];
    float* out = (float*)d_out;

    float *pconv, *ph1, *ph2, *pxg, *pfeat, *plf, *pcst;
    __nv_bfloat16 *pw1h, *pw1l, *pw2h, *pw2l, *pwih_h, *pwih_l;
    __nv_bfloat16 *pc1h, *pc1l, *pc2h, *pc2l, *pc3h, *pc3l;
    __nv_bfloat16 *phhA, *phlA, *phhB, *phlB;
    cudaGetSymbolAddress((void**)&pconv, g_conv);
    cudaGetSymbolAddress((void**)&ph1, g_h1);
    cudaGetSymbolAddress((void**)&ph2, g_h2);
    cudaGetSymbolAddress((void**)&pxg, g_xg);
    cudaGetSymbolAddress((void**)&pfeat, g_feat);
    cudaGetSymbolAddress((void**)&plf, g_lf);
    cudaGetSymbolAddress((void**)&pcst, g_cst);
    cudaGetSymbolAddress((void**)&phhA, g_hhA);
    cudaGetSymbolAddress((void**)&phlA, g_hlA);
    cudaGetSymbolAddress((void**)&phhB, g_hhB);
    cudaGetSymbolAddress((void**)&phlB, g_hlB);
    cudaGetSymbolAddress((void**)&pw1h, g_wfc1_hi);
    cudaGetSymbolAddress((void**)&pw1l, g_wfc1_lo);
    cudaGetSymbolAddress((void**)&pw2h, g_wfc2_hi);
    cudaGetSymbolAddress((void**)&pw2l, g_wfc2_lo);
    cudaGetSymbolAddress((void**)&pwih_h, g_wih_hi);
    cudaGetSymbolAddress((void**)&pwih_l, g_wih_lo);
    cudaGetSymbolAddress((void**)&pc1h, g_cw1h);
    cudaGetSymbolAddress((void**)&pc1l, g_cw1l);
    cudaGetSymbolAddress((void**)&pc2h, g_cw2h);
    cudaGetSymbolAddress((void**)&pc2l, g_cw2l);
    cudaGetSymbolAddress((void**)&pc3h, g_cw3h);
    cudaGetSymbolAddress((void**)&pc3l, g_cw3l);

    const int SMEM_TG = 128 * 132 * 4;
    cudaFuncSetAttribute(tgemm<1>, cudaFuncAttributeMaxDynamicSharedMemorySize, SMEM_TG);
    cudaFuncSetAttribute(tgemm<0>, cudaFuncAttributeMaxDynamicSharedMemorySize, SMEM_TG);
    const int SMEM_CONV = 2 * IMG_BYTES + 2 * CW_HALF;
    cudaFuncSetAttribute(conv3_mma, cudaFuncAttributeMaxDynamicSharedMemorySize, SMEM_CONV);
    cudaFuncSetAttribute(lstm_persist, cudaFuncAttributeMaxDynamicSharedMemorySize, LS_SMEM);

    wcprep<<<25, 256>>>(c1w, pc1h, pc1l, 25);
    wcprep<<<9, 256>>>(c2w, pc2h, pc2l, 9);
    wcprep<<<9, 256>>>(c3w, pc3h, pc3l, 9);
    conv3_mma<<<TBTOT, 256, SMEM_CONV>>>(x, c1b, c2b, c3b);
    wprep<<<(512 * 1024 + 255) / 256, 256>>>(fc1w, pw1h, pw1l, 512 * 1024);
    tgemm<1><<<dim3(512 / 128, TBTOT / 128), 256, SMEM_TG>>>(
        pconv, pw1h, pw1l, fc1b, nullptr, ph1, TBTOT, 512, 4096);

    wprep<<<(512 * 128 + 255) / 256, 256>>>(fc2w, pw2h, pw2l, 512 * 128);
    wprep<<<(2048 * 128 + 255) / 256, 256>>>(wih, pwih_h, pwih_l, 2048 * 128);
    wlstm_prep<<<(2048 * 128 + 255) / 256, 256>>>(whh);
    pack_h0<<<(B_ENV * HID + 255) / 256, 256>>>(h0);
    cudaMemcpyAsync(pcst, c0, (size_t)B_ENV * HID * sizeof(float),
                    cudaMemcpyDeviceToDevice, 0);

    tgemm<1><<<dim3(512 / 128, TBTOT / 128), 256, SMEM_TG>>>(
        ph1, pw2h, pw2l, fc2b, nullptr, ph2, TBTOT, 512, 512);
    tgemm<0><<<dim3(2048 / 128, TBTOT / 128), 256, SMEM_TG>>>(
        ph2, pwih_h, pwih_l, bih, bhh, pxg, TBTOT, 2048, 512);

    // entire recurrence in ONE persistent kernel (128 blocks, N=16 tiles)
    lstm_persist<<<NB_LSTM, 256, LS_SMEM>>>(pxg, done, phhA, phlA, phhB, phlB,
                                            pcst, pfeat);

    // lofeat: feat(512) + one-hot(z) via epilogue, ldb=520, leaky
    sgemm128<1, 1><<<dim3(FE / 128, TBTOT / 128), 256>>>(
        pfeat, lfw, lfb, nullptr, plf, TBTOT, FE, 512, 520, z);

    // heads + softmax stats
    head_kernel<<<TBTOT / 8, 256>>>(plf, aw, ab, cw, cb, action, out);
}

// round 11
// speedup vs baseline: 1.8897x; 1.1608x over previous
#include <cuda_runtime.h>
#include <cuda_bf16.h>
#include <math.h>
#include <stdint.h>

#define T_STEPS 128
#define B_ENV   128
#define HID     512
#define TBTOT   (T_STEPS * B_ENV)
#define ZD      8
#define AD      7
#define FE      128
#define NB_LSTM 128

// ----------------------------------------------------------------------------
// Scratch (device globals; no allocation allowed)
// ----------------------------------------------------------------------------
__device__ float g_conv[TBTOT * 4096];
__device__ float g_h1[TBTOT * HID];
__device__ float g_h2[TBTOT * HID];
__device__ float g_xg[TBTOT * 2048];
__device__ float g_feat[TBTOT * HID];
__device__ float g_lf[TBTOT * FE];
__device__ float g_cst[B_ENV * HID];
__device__ __nv_bfloat16 g_hhA[B_ENV * HID];
__device__ __nv_bfloat16 g_hlA[B_ENV * HID];
__device__ __nv_bfloat16 g_hhB[B_ENV * HID];
__device__ __nv_bfloat16 g_hlB[B_ENV * HID];
// W_hh reordered: [blk 128][n 16][k 512], n = 2*jj + (g&1) + 8*(g>>1)
__device__ __nv_bfloat16 g_wlh[128 * 16 * 512];
__device__ __nv_bfloat16 g_wll[128 * 16 * 512];
__device__ __nv_bfloat16 g_wfc1_hi[512 * 4096];
__device__ __nv_bfloat16 g_wfc1_lo[512 * 4096];
__device__ __nv_bfloat16 g_wfc2_hi[512 * 512];
__device__ __nv_bfloat16 g_wfc2_lo[512 * 512];
__device__ __nv_bfloat16 g_wih_hi[2048 * 512];
__device__ __nv_bfloat16 g_wih_lo[2048 * 512];
__device__ __nv_bfloat16 g_cw1h[25 * 256];
__device__ __nv_bfloat16 g_cw1l[25 * 256];
__device__ __nv_bfloat16 g_cw2h[9 * 256];
__device__ __nv_bfloat16 g_cw2l[9 * 256];
__device__ __nv_bfloat16 g_cw3h[9 * 256];
__device__ __nv_bfloat16 g_cw3l[9 * 256];
// grid barrier state
__device__ unsigned int g_bar_cnt;
__device__ volatile unsigned int g_bar_gen;

// ============================================================================
// Helpers
// ============================================================================
__device__ __forceinline__ uint32_t smem_to_u32(const void* smem_ptr) {
    uint32_t addr;
    asm("{ .reg .u64 tmp; cvta.to.shared.u64 tmp, %1; cvt.u32.u64 %0, tmp; }"
        : "=r"(addr) : "l"(smem_ptr));
    return addr;
}

__device__ __forceinline__ void ldsm4(uint32_t addr, uint32_t* r) {
    asm volatile("ldmatrix.sync.aligned.m8n8.x4.shared.b16 {%0,%1,%2,%3}, [%4];"
        : "=r"(r[0]), "=r"(r[1]), "=r"(r[2]), "=r"(r[3]) : "r"(addr));
}

__device__ __forceinline__ void mma16816(float* d, const uint32_t* a,
                                         const uint32_t* b) {
    asm volatile(
        "mma.sync.aligned.m16n8k16.row.col.f32.bf16.bf16.f32 "
        "{%0,%1,%2,%3}, {%4,%5,%6,%7}, {%8,%9}, {%0,%1,%2,%3};"
        : "+f"(d[0]), "+f"(d[1]), "+f"(d[2]), "+f"(d[3])
        : "r"(a[0]), "r"(a[1]), "r"(a[2]), "r"(a[3]), "r"(b[0]), "r"(b[1]));
}

__device__ __forceinline__ void split2(float x, float y, uint32_t& hi, uint32_t& lo) {
    __nv_bfloat16 hx = __float2bfloat16(x), hy = __float2bfloat16(y);
    __nv_bfloat162 h2; h2.x = hx; h2.y = hy;
    hi = reinterpret_cast<uint32_t&>(h2);
    float lx = x - __bfloat162float(hx);
    float ly = y - __bfloat162float(hy);
    __nv_bfloat162 l2 = __floats2bfloat162_rn(lx, ly);
    lo = reinterpret_cast<uint32_t&>(l2);
}

#define CP_ASYNC16(dst, src) \
    asm volatile("cp.async.ca.shared.global [%0], [%1], 16;" \
        :: "r"(dst), "l"(src) : "memory")
#define CP_COMMIT() asm volatile("cp.async.commit_group;" ::: "memory")
#define CP_WAIT2() asm volatile("cp.async.wait_group 2;" ::: "memory")

// software grid barrier (all NB_LSTM blocks co-resident by construction)
__device__ __forceinline__ void grid_bar() {
    __threadfence();
    __syncthreads();
    if (threadIdx.x == 0) {
        unsigned int gen = g_bar_gen;
        if (atomicAdd(&g_bar_cnt, 1u) == NB_LSTM - 1) {
            g_bar_cnt = 0;
            __threadfence();
            g_bar_gen = gen + 1;
        } else {
            while (g_bar_gen == gen) { }
            __threadfence();
        }
    }
    __syncthreads();
}

// ----------------------------------------------------------------------------
// Weight prep kernels
// ----------------------------------------------------------------------------
__global__ void wprep(const float* __restrict__ w, __nv_bfloat16* __restrict__ hi,
                      __nv_bfloat16* __restrict__ lo, int total4) {
    int idx = blockIdx.x * blockDim.x + threadIdx.x;
    if (idx >= total4) return;
    float4 a = *(const float4*)(w + (size_t)idx * 4);
    uint32_t h0, h1, l0, l1;
    split2(a.x, a.y, h0, l0);
    split2(a.z, a.w, h1, l1);
    *(uint2*)(hi + (size_t)idx * 4) = make_uint2(h0, h1);
    *(uint2*)(lo + (size_t)idx * 4) = make_uint2(l0, l1);
}

__global__ void wcprep(const float* __restrict__ w, __nv_bfloat16* __restrict__ hi,
                       __nv_bfloat16* __restrict__ lo, int taps) {
    int idx = blockIdx.x * blockDim.x + threadIdx.x;
    if (idx >= taps * 256) return;
    int r = idx & 255;
    int t = idx >> 8;
    float v = w[r * taps + t];
    __nv_bfloat16 hv = __float2bfloat16(v);
    float lv = v - __bfloat162float(hv);
    hi[t * 256 + r] = hv;
    lo[t * 256 + r] = __float2bfloat16(lv);
}

// whh [2048][512] -> per-block gate-interleaved rows:
// blk = j>>2, jj = j&3, n = 2*jj + (g&1) + 8*(g>>1); dst row = blk*16 + n
__global__ void wlstm_prep(const float* __restrict__ whh) {
    int idx = blockIdx.x * blockDim.x + threadIdx.x;
    if (idx >= 2048 * 128) return;
    int row = idx >> 7;
    int k4 = (idx & 127) * 4;
    int g = row >> 9, j = row & 511;
    int blk = j >> 2, jj = j & 3;
    int n = 2 * jj + (g & 1) + 8 * (g >> 1);
    size_t dst = ((size_t)(blk * 16 + n)) * 512 + k4;
    float4 v = *(const float4*)(whh + (size_t)row * 512 + k4);
    uint32_t h0, h1, l0, l1;
    split2(v.x, v.y, h0, l0);
    split2(v.z, v.w, h1, l1);
    *(uint2*)(g_wlh + dst) = make_uint2(h0, h1);
    *(uint2*)(g_wll + dst) = make_uint2(l0, l1);
}

// pack h0 pre-masked with m[0] = 1 - done[0]
__global__ void pack_h0(const float* __restrict__ h0, const int* __restrict__ done) {
    int i = blockIdx.x * blockDim.x + threadIdx.x;
    if (i >= B_ENV * HID) return;
    int b = i >> 9;
    float m = done[b] ? 0.f : 1.f;
    float v = h0[i] * m;
    __nv_bfloat16 hv = __float2bfloat16(v);
    g_hhA[i] = hv;
    g_hlA[i] = __float2bfloat16(v - __bfloat162float(hv));
}

// ----------------------------------------------------------------------------
// HMMA GEMM (proven): 3-term bf16 split, fp32 accum
// ----------------------------------------------------------------------------
#define SMSTR 80

template <int ACT>
__global__ __launch_bounds__(256) void tgemm(
    const float* __restrict__ A, const __nv_bfloat16* __restrict__ Whi,
    const __nv_bfloat16* __restrict__ Wlo,
    const float* __restrict__ bias, const float* __restrict__ bias2,
    float* __restrict__ C, int M, int N, int K) {
    extern __shared__ uint8_t sm[];
    const uint32_t oAh = 0, oAl = 10240, oBh = 20480, oBl = 30720;
    uint32_t sb = smem_to_u32(sm);
    int tid = threadIdx.x;
    int lane = tid & 31;
    int wid = tid >> 5;
    int wm = wid & 3, wn = wid >> 2;
    int m0 = blockIdx.y * 128, n0 = blockIdx.x * 128;
    const float* Ag = A + (size_t)m0 * K;

    float acc[2][8][4];
#pragma unroll
    for (int i = 0; i < 2; i++)
#pragma unroll
        for (int j = 0; j < 8; j++)
#pragma unroll
            for (int q = 0; q < 4; q++) acc[i][j][q] = 0.f;

    int nslab = K / 32;
    float4 aR[4];
    uint4 bRh[2], bRl[2];

    auto load_slab = [&](int s) {
#pragma unroll
        for (int i = 0; i < 4; i++) {
            int row = (tid >> 3) + 32 * i;
            aR[i] = *(const float4*)(Ag + (size_t)row * K + s * 32 + (tid & 7) * 4);
        }
#pragma unroll
        for (int i = 0; i < 2; i++) {
            int row = (tid >> 2) + 64 * i;
            size_t boff = ((size_t)(n0 + row) * K + s * 32);
            bRh[i] = *(const uint4*)((const uint8_t*)(Whi + boff) + (tid & 3) * 16);
            bRl[i] = *(const uint4*)((const uint8_t*)(Wlo + boff) + (tid & 3) * 16);
        }
    };
    auto store_slab = [&]() {
#pragma unroll
        for (int i = 0; i < 4; i++) {
            int row = (tid >> 3) + 32 * i;
            int col8 = (tid & 7) * 8;
            uint32_t h0, h1, l0, l1;
            split2(aR[i].x, aR[i].y, h0, l0);
            split2(aR[i].z, aR[i].w, h1, l1);
            *(uint2*)(sm + oAh + row * SMSTR + col8) = make_uint2(h0, h1);
            *(uint2*)(sm + oAl + row * SMSTR + col8) = make_uint2(l0, l1);
        }
#pragma unroll
        for (int i = 0; i < 2; i++) {
            int row = (tid >> 2) + 64 * i;
            int c16 = (tid & 3) * 16;
            *(uint4*)(sm + oBh + row * SMSTR + c16) = bRh[i];
            *(uint4*)(sm + oBl + row * SMSTR + c16) = bRl[i];
        }
    };

    load_slab(0);
    store_slab();
    __syncthreads();

    int g = lane >> 3;
    int arow_off = (lane & 7) + (g & 1) * 8;
    int akb_off = (g >> 1) * 16;
    int brow_off = (lane & 7) + (g >> 1) * 8;
    int bkb_off = (g & 1) * 16;

    for (int s = 0; s < nslab; s++) {
        bool more = (s + 1 < nslab);
        if (more) load_slab(s + 1);

#pragma unroll
        for (int kk2 = 0; kk2 < 2; kk2++) {
            int kb = kk2 * 32;
            uint32_t ah[2][4], al[2][4], bh[4][4], bl[4][4];
#pragma unroll
            for (int mi = 0; mi < 2; mi++) {
                uint32_t r = (uint32_t)((wm * 32 + mi * 16 + arow_off) * SMSTR +
                                        kb + akb_off);
                ldsm4(sb + oAh + r, ah[mi]);
                ldsm4(sb + oAl + r, al[mi]);
            }
#pragma unroll
            for (int pi = 0; pi < 4; pi++) {
                uint32_t r = (uint32_t)((wn * 64 + pi * 16 + brow_off) * SMSTR +
                                        kb + bkb_off);
                ldsm4(sb + oBh + r, bh[pi]);
                ldsm4(sb + oBl + r, bl[pi]);
            }
#pragma unroll
            for (int mi = 0; mi < 2; mi++)
#pragma unroll
                for (int pi = 0; pi < 4; pi++)
#pragma unroll
                    for (int half = 0; half < 2; half++) {
                        float* d = acc[mi][pi * 2 + half];
                        mma16816(d, ah[mi], &bh[pi][half * 2]);
                        mma16816(d, ah[mi], &bl[pi][half * 2]);
                        mma16816(d, al[mi], &bh[pi][half * 2]);
                    }
        }
        __syncthreads();
        if (more) {
            store_slab();
            __syncthreads();
        }
    }

    float* ct = (float*)sm;
#pragma unroll
    for (int mi = 0; mi < 2; mi++) {
        int r0 = wm * 32 + mi * 16 + (lane >> 2);
#pragma unroll
        for (int ni = 0; ni < 8; ni++) {
            int c = wn * 64 + ni * 8 + (lane & 3) * 2;
            float b0 = bias[n0 + c], b1 = bias[n0 + c + 1];
            if (bias2) { b0 += bias2[n0 + c]; b1 += bias2[n0 + c + 1]; }
            float v0 = acc[mi][ni][0] + b0;
            float v1 = acc[mi][ni][1] + b1;
            float v2 = acc[mi][ni][2] + b0;
            float v3 = acc[mi][ni][3] + b1;
            if (ACT) {
                v0 = v0 > 0.f ? v0 : 0.01f * v0;
                v1 = v1 > 0.f ? v1 : 0.01f * v1;
                v2 = v2 > 0.f ? v2 : 0.01f * v2;
                v3 = v3 > 0.f ? v3 : 0.01f * v3;
            }
            ct[r0 * 132 + c] = v0;
            ct[r0 * 132 + c + 1] = v1;
            ct[(r0 + 8) * 132 + c] = v2;
            ct[(r0 + 8) * 132 + c + 1] = v3;
        }
    }
    __syncthreads();
    {
        int r8 = tid >> 5;
        int c4 = (tid & 31) * 4;
#pragma unroll
        for (int p = 0; p < 16; p++) {
            int r = p * 8 + r8;
            float4 v = *(const float4*)(ct + r * 132 + c4);
            *(float4*)(C + (size_t)(m0 + r) * N + n0 + c4) = v;
        }
    }
}

// ----------------------------------------------------------------------------
// HMMA conv (proven)
// ----------------------------------------------------------------------------
#define PSTR 48
#define IMG_BYTES (400 * PSTR)
#define CW_OFF   (2 * IMG_BYTES)
#define CW_HALF  12800

template <int KS, int P, int LAST>
__device__ __forceinline__ void conv_hmma_layer(
    uint8_t* csm, uint32_t sbase, const __nv_bfloat16* wsrc_h,
    const __nv_bfloat16* wsrc_l, const float* __restrict__ bias,
    float* gout, int tid, int lane, int wid) {
    const int taps = KS * KS;
    {
        const uint4* sh = (const uint4*)wsrc_h;
        const uint4* sl = (const uint4*)wsrc_l;
        uint4* dh = (uint4*)(csm + CW_OFF);
        uint4* dl = (uint4*)(csm + CW_OFF + CW_HALF);
        for (int i = tid; i < taps * 32; i += 256) {
            dh[i] = sh[i];
            dl[i] = sl[i];
        }
    }
    __syncthreads();

    float acc[2][2][4];
#pragma unroll
    for (int a = 0; a < 2; a++)
#pragma unroll
        for (int b = 0; b < 2; b++)
#pragma unroll
            for (int q = 0; q < 4; q++) acc[a][b][q] = 0.f;

    int g = lane >> 3;
    int h0 = wid * 2;
    uint32_t aoff[2];
#pragma unroll
    for (int mi = 0; mi < 2; mi++)
        aoff[mi] = (uint32_t)(((h0 + mi + 2) * 20 + 2 + (lane & 7) + (g & 1) * 8) * PSTR +
                              (g >> 1) * 16);
    uint32_t boff = (uint32_t)(((lane & 7) + (g >> 1) * 8) * 32 + (g & 1) * 16);
    uint32_t wb_h = sbase + CW_OFF;
    uint32_t wb_l = sbase + CW_OFF + CW_HALF;

#pragma unroll
    for (int kh = 0; kh < KS; kh++) {
#pragma unroll
        for (int kw = 0; kw < KS; kw++) {
            int t = kh * KS + kw;
            int shift = ((kh - P) * 20 + (kw - P)) * PSTR;
            uint32_t bh4[4], bl4[4];
            ldsm4(wb_h + t * 512 + boff, bh4);
            ldsm4(wb_l + t * 512 + boff, bl4);
#pragma unroll
            for (int mi = 0; mi < 2; mi++) {
                uint32_t ah[4], al[4];
                ldsm4(sbase + aoff[mi] + shift, ah);
                ldsm4(sbase + IMG_BYTES + aoff[mi] + shift, al);
#pragma unroll
                for (int nh = 0; nh < 2; nh++) {
                    mma16816(acc[mi][nh], ah, &bh4[nh * 2]);
                    mma16816(acc[mi][nh], ah, &bl4[nh * 2]);
                    mma16816(acc[mi][nh], al, &bh4[nh * 2]);
                }
            }
        }
    }
    __syncthreads();

#pragma unroll
    for (int mi = 0; mi < 2; mi++) {
        int h = h0 + mi;
#pragma unroll
        for (int nh = 0; nh < 2; nh++) {
            int co = nh * 8 + (lane & 3) * 2;
            float b0 = bias[co], b1 = bias[co + 1];
#pragma unroll
            for (int rr = 0; rr < 2; rr++) {
                int w = (lane >> 2) + rr * 8;
                float v0 = acc[mi][nh][rr * 2 + 0] + b0;
                float v1 = acc[mi][nh][rr * 2 + 1] + b1;
                v0 = v0 > 0.f ? v0 : 0.01f * v0;
                v1 = v1 > 0.f ? v1 : 0.01f * v1;
                if (LAST) {
                    gout[co * 256 + h * 16 + w] = v0;
                    gout[(co + 1) * 256 + h * 16 + w] = v1;
                } else {
                    uint32_t hp, lp;
                    split2(v0, v1, hp, lp);
                    int pb = ((h + 2) * 20 + (w + 2)) * PSTR + co * 2;
                    *(uint32_t*)(csm + pb) = hp;
                    *(uint32_t*)(csm + IMG_BYTES + pb) = lp;
                }
            }
        }
    }
    __syncthreads();
}

__global__ __launch_bounds__(256) void conv3_mma(
    const float* __restrict__ x,
    const float* __restrict__ b1, const float* __restrict__ b2,
    const float* __restrict__ b3) {
    extern __shared__ uint8_t csm[];
    uint32_t sbase = smem_to_u32(csm);
    int tid = threadIdx.x;
    int lane = tid & 31;
    int wid = tid >> 5;
    int img = blockIdx.x;
    const float* xi = x + (size_t)img * 4096;

    for (int i = tid; i < 2 * IMG_BYTES / 4; i += 256)
        ((uint32_t*)csm)[i] = 0;
    __syncthreads();
    for (int i = tid; i < 4096; i += 256) {
        int ci = i >> 8, p = i & 255;
        int h = p >> 4, w = p & 15;
        float v = xi[i];
        __nv_bfloat16 hv = __float2bfloat16(v);
        float lv = v - __bfloat162float(hv);
        int pb = ((h + 2) * 20 + (w + 2)) * PSTR + ci * 2;
        *(__nv_bfloat16*)(csm + pb) = hv;
        *(__nv_bfloat16*)(csm + IMG_BYTES + pb) = __float2bfloat16(lv);
    }
    __syncthreads();

    float* gout = g_conv + (size_t)img * 4096;
    conv_hmma_layer<5, 2, 0>(csm, sbase, g_cw1h, g_cw1l, b1, gout, tid, lane, wid);
    conv_hmma_layer<3, 1, 0>(csm, sbase, g_cw2h, g_cw2l, b2, gout, tid, lane, wid);
    conv_hmma_layer<3, 1, 1>(csm, sbase, g_cw3h, g_cw3l, b3, gout, tid, lane, wid);
}

// ----------------------------------------------------------------------------
// Persistent LSTM v4: cp.async staging, depth-3 pipeline, 4 smem A-buffers.
// h stored in gmem PRE-MASKED with next step's done mask. 128 blocks, N=16
// gate-interleaved tiles, register c.
// ----------------------------------------------------------------------------
__device__ __forceinline__ float sigm(float x) { return 1.f / (1.f + expf(-x)); }

#define LW_STR   1040
#define LS_W_SZ  (2 * 16 * LW_STR)                 // 33280
#define LS_A_OFF LS_W_SZ
#define LS_A_BUF (2 * 128 * SMSTR)                 // 20480 (hi+lo)
#define LS_M_OFF (LS_A_OFF + 4 * LS_A_BUF)         // 115200
#define LS_SMEM  (LS_M_OFF + 1024)                 // 116224

__global__ __launch_bounds__(256) void lstm_persist(
    const float* __restrict__ xg, const int* __restrict__ done,
    __nv_bfloat16* __restrict__ hAh, __nv_bfloat16* __restrict__ hAl,
    __nv_bfloat16* __restrict__ hBh, __nv_bfloat16* __restrict__ hBl,
    float* __restrict__ c_st, float* __restrict__ feat) {
    extern __shared__ uint8_t psm[];
    float* s_m  = (float*)(psm + LS_M_OFF);        // mask m[t]   (for c)
    float* s_mn = (float*)(psm + LS_M_OFF + 512);  // mask m[t+1] (for h write)
    uint32_t sbW = smem_to_u32(psm);
    int tid = threadIdx.x, lane = tid & 31, wid = tid >> 5;
    int blk = blockIdx.x;
    int jb4 = blk * 4;

    // resident weights: 16 rows hi + 16 rows lo, 64 uint4/row
    {
        const uint4* Wh = (const uint4*)(g_wlh + (size_t)blk * 16 * 512);
        const uint4* Wl = (const uint4*)(g_wll + (size_t)blk * 16 * 512);
#pragma unroll
        for (int i = 0; i < 4; i++) {
            int i4 = tid + 256 * i;
            int r = i4 >> 6, q = i4 & 63;
            *(uint4*)(psm + r * LW_STR + q * 16) = Wh[i4];
            *(uint4*)(psm + 16 * LW_STR + r * LW_STR + q * 16) = Wl[i4];
        }
    }

    int r1 = wid * 16 + (lane >> 2);
    int L = lane & 3;
    int gq = lane >> 3;
    uint32_t arow = (uint32_t)((wid * 16 + (lane & 7) + (gq & 1) * 8) * SMSTR +
                               (gq >> 1) * 16);
    uint32_t brow = (uint32_t)(((lane & 7) + (gq >> 1) * 8) * LW_STR + (gq & 1) * 16);
    int sr0 = tid >> 2, sq = tid & 3;

    float creg[2];
#pragma unroll
    for (int rr = 0; rr < 2; rr++)
        creg[rr] = c_st[(size_t)(r1 + rr * 8) * 512 + jb4 + L];
    __syncthreads();

    for (int t = 0; t < T_STEPS; t++) {
        const __nv_bfloat16* hih = (t & 1) ? hBh : hAh;
        const __nv_bfloat16* hil = (t & 1) ? hBl : hAl;
        __nv_bfloat16* hoh = (t & 1) ? hAh : hBh;
        __nv_bfloat16* hol = (t & 1) ? hAl : hBl;

        // cp.async stage: pure copy (h already pre-masked in gmem)
        auto cpa_slab = [&](int s) {
            uint32_t base = sbW + LS_A_OFF + (uint32_t)((s & 3) * LS_A_BUF);
#pragma unroll
            for (int q = 0; q < 2; q++) {
                int r = sr0 + 64 * q;
                CP_ASYNC16(base + r * SMSTR + sq * 16,
                           hih + (size_t)r * 512 + s * 32 + sq * 8);
                CP_ASYNC16(base + 128 * SMSTR + r * SMSTR + sq * 16,
                           hil + (size_t)r * 512 + s * 32 + sq * 8);
            }
            CP_COMMIT();
        };

        // prologue: get 3 slabs in flight immediately
        cpa_slab(0);
        cpa_slab(1);
        cpa_slab(2);

        if (tid < 128) {
            s_m[tid] = done[t * 128 + tid] ? 0.f : 1.f;
            s_mn[tid] = (t + 1 < T_STEPS)
                            ? (done[(t + 1) * 128 + tid] ? 0.f : 1.f) : 1.f;
        }

        // acc init from xg (biases pre-folded); overlaps with cp.async
        float acc[2][4];
#pragma unroll
        for (int pi = 0; pi < 2; pi++)
#pragma unroll
            for (int rr = 0; rr < 2; rr++)
#pragma unroll
                for (int cc = 0; cc < 2; cc++)
                    acc[pi][rr * 2 + cc] = xg[(size_t)(t * 128 + r1 + rr * 8) * 2048 +
                                              (cc + 2 * pi) * 512 + jb4 + L];

        for (int s = 0; s < 16; s++) {
            CP_WAIT2();          // group s complete (this thread)
            __syncthreads();     // all threads' slab-s data visible; prev compute done
            if (s < 13) cpa_slab(s + 3);
            else CP_COMMIT();    // empty group keeps wait-count uniform
            uint32_t sbA = sbW + LS_A_OFF + (uint32_t)((s & 3) * LS_A_BUF);
#pragma unroll
            for (int kk2 = 0; kk2 < 2; kk2++) {
                int kb = kk2 * 32;
                uint32_t ah[4], al[4], bh4[4], bl4[4];
                ldsm4(sbA + arow + kb, ah);
                ldsm4(sbA + 128 * SMSTR + arow + kb, al);
                uint32_t bo = brow + s * 64 + kb;
                ldsm4(sbW + bo, bh4);
                ldsm4(sbW + 16 * LW_STR + bo, bl4);
#pragma unroll
                for (int pi = 0; pi < 2; pi++) {
                    float* d = acc[pi];
                    mma16816(d, ah, &bh4[pi * 2]);
                    mma16816(d, ah, &bl4[pi * 2]);
                    mma16816(d, al, &bh4[pi * 2]);
                }
            }
        }

        // epilogue: gates thread-local; h written pre-masked with m[t+1]
#pragma unroll
        for (int rr = 0; rr < 2; rr++) {
            int r = r1 + rr * 8;
            float m = s_m[r];
            float mn = s_mn[r];
            int j = jb4 + L;
            float gi = acc[0][rr * 2 + 0];
            float gf = acc[0][rr * 2 + 1];
            float gg = acc[1][rr * 2 + 0];
            float go = acc[1][rr * 2 + 1];
            float cn = sigm(gf) * (creg[rr] * m) + sigm(gi) * tanhf(gg);
            float hn = sigm(go) * tanhf(cn);
            creg[rr] = cn;
            feat[(size_t)(t * 128 + r) * 512 + j] = hn;
            float hw = hn * mn;
            __nv_bfloat16 hh = __float2bfloat16(hw);
            hoh[(size_t)r * 512 + j] = hh;
            hol[(size_t)r * 512 + j] = __float2bfloat16(hw - __bfloat162float(hh));
        }
        grid_bar();
    }
}

// ----------------------------------------------------------------------------
// Scalar SGEMM kept for lofeat (with z one-hot epilogue)
// ----------------------------------------------------------------------------
template <int ACT, int ZMODE>
__global__ __launch_bounds__(256, 2) void sgemm128(
    const float* __restrict__ A, const float* __restrict__ B,
    const float* __restrict__ bias, const float* __restrict__ bias2,
    float* __restrict__ C, int M, int N, int K, int ldb,
    const int* __restrict__ z) {
    __shared__ float As[8 * 132];
    __shared__ float Bs[8 * 132];
    int tid = threadIdx.x;
    int tx = tid & 15, ty = tid >> 4;
    int row0 = blockIdx.y * 128;
    int col0 = blockIdx.x * 128;
    const float* Ag = A + (size_t)row0 * K;
    const float* Bg = B + (size_t)col0 * ldb;
    int lr = tid >> 1;
    int lc = (tid & 1) * 4;

    float acc[8][8];
#pragma unroll
    for (int i = 0; i < 8; i++)
#pragma unroll
        for (int j = 0; j < 8; j++) acc[i][j] = 0.f;

    for (int k0 = 0; k0 < K; k0 += 8) {
        float4 a4 = *(const float4*)(Ag + (size_t)lr * K + k0 + lc);
        float4 b4 = *(const float4*)(Bg + (size_t)lr * ldb + k0 + lc);
        As[(lc + 0) * 132 + lr] = a4.x;
        As[(lc + 1) * 132 + lr] = a4.y;
        As[(lc + 2) * 132 + lr] = a4.z;
        As[(lc + 3) * 132 + lr] = a4.w;
        Bs[(lc + 0) * 132 + lr] = b4.x;
        Bs[(lc + 1) * 132 + lr] = b4.y;
        Bs[(lc + 2) * 132 + lr] = b4.z;
        Bs[(lc + 3) * 132 + lr] = b4.w;
        __syncthreads();
#pragma unroll
        for (int k = 0; k < 8; k++) {
            float4 a0 = *(const float4*)(As + k * 132 + ty * 4);
            float4 a1 = *(const float4*)(As + k * 132 + 64 + ty * 4);
            float4 b0 = *(const float4*)(Bs + k * 132 + tx * 4);
            float4 b1 = *(const float4*)(Bs + k * 132 + 64 + tx * 4);
            float av[8] = {a0.x, a0.y, a0.z, a0.w, a1.x, a1.y, a1.z, a1.w};
            float bv[8] = {b0.x, b0.y, b0.z, b0.w, b1.x, b1.y, b1.z, b1.w};
#pragma unroll
            for (int i = 0; i < 8; i++)
#pragma unroll
                for (int j = 0; j < 8; j++)
                    acc[i][j] = fmaf(av[i], bv[j], acc[i][j]);
        }
        __syncthreads();
    }

#pragma unroll
    for (int i = 0; i < 8; i++) {
        int m = row0 + ((i < 4) ? (ty * 4 + i) : (64 + ty * 4 + i - 4));
        int zi = 0;
        if (ZMODE) zi = 512 + z[m];
#pragma unroll
        for (int j = 0; j < 8; j++) {
            int n = col0 + ((j < 4) ? (tx * 4 + j) : (64 + tx * 4 + j - 4));
            float v = acc[i][j] + bias[n];
            if (bias2) v += bias2[n];
            if (ZMODE) v += B[(size_t)n * ldb + zi];
            if (ACT) v = v > 0.f ? v : 0.01f * v;
            C[(size_t)m * N + n] = v;
        }
    }
}

// ----------------------------------------------------------------------------
// Head: warp per row; actor/critic GEMV + log_softmax/entropy/prob pack.
// ----------------------------------------------------------------------------
__global__ __launch_bounds__(256) void head_kernel(
    const float* __restrict__ lf, const float* __restrict__ aw,
    const float* __restrict__ ab, const float* __restrict__ cw,
    const float* __restrict__ cb, const int* __restrict__ action,
    float* __restrict__ out) {
    int warp = (blockIdx.x * blockDim.x + threadIdx.x) >> 5;
    int lane = threadIdx.x & 31;
    if (warp >= TBTOT) return;
    float4 f = *(const float4*)(lf + (size_t)warp * FE + lane * 4);
    float r[8];
#pragma unroll
    for (int a = 0; a < 7; a++) {
        float4 w = *(const float4*)(aw + a * FE + lane * 4);
        r[a] = f.x * w.x + f.y * w.y + f.z * w.z + f.w * w.w;
    }
    {
        float4 w = *(const float4*)(cw + lane * 4);
        r[7] = f.x * w.x + f.y * w.y + f.z * w.z + f.w * w.w;
    }
#pragma unroll
    for (int a = 0; a < 8; a++)
#pragma unroll
        for (int s = 16; s > 0; s >>= 1)
            r[a] += __shfl_xor_sync(0xffffffffu, r[a], s);

    if (lane == 0) {
        float lg[7];
        float mx = -1e30f;
#pragma unroll
        for (int a = 0; a < 7; a++) {
            lg[a] = r[a] + ab[a];
            mx = fmaxf(mx, lg[a]);
        }
        float se = 0.f;
        float e[7];
#pragma unroll
        for (int a = 0; a < 7; a++) {
            e[a] = expf(lg[a] - mx);
            se += e[a];
        }
        float lse = mx + logf(se);
        float inv = 1.f / se;
        float ent = 0.f;
        float* o = out + (size_t)warp * 10;
#pragma unroll
        for (int a = 0; a < 7; a++) {
            float p = e[a] * inv;
            float lp = lg[a] - lse;
            ent -= p * lp;
            o[3 + a] = p;
        }
        int act = action[warp];
        o[0] = lg[act] - lse;
        o[1] = ent;
        o[2] = r[7] + cb[0];
    }
}

// ----------------------------------------------------------------------------
// Launch
// ----------------------------------------------------------------------------
extern "C" void kernel_launch(void* const* d_in, const int* in_sizes, int n_in,
                              void* d_out, int out_size) {
    const float* x    = (const float*)d_in[0];
    const int* done   = (const int*)d_in[1];
    const int* z      = (const int*)d_in[2];
    const int* action = (const int*)d_in[3];
    const float* h0   = (const float*)d_in[4];
    const float* c0   = (const float*)d_in[5];
    const float* c1w = (const float*)d_in[6];  const float* c1b = (const float*)d_in[7];
    const float* c2w = (const float*)d_in[8];  const float* c2b = (const float*)d_in[9];
    const float* c3w = (const float*)d_in[10]; const float* c3b = (const float*)d_in[11];
    const float* fc1w = (const float*)d_in[12]; const float* fc1b = (const float*)d_in[13];
    const float* fc2w = (const float*)d_in[14]; const float* fc2b = (const float*)d_in[15];
    const float* wih = (const float*)d_in[16]; const float* whh = (const float*)d_in[17];
    const float* bih = (const float*)d_in[18]; const float* bhh = (const float*)d_in[19];
    const float* lfw = (const float*)d_in[20]; const float* lfb = (const float*)d_in[21];
    const float* aw = (const float*)d_in[22];  const float* ab = (const float*)d_in[23];
    const float* cw = (const float*)d_in[24];  const float* cb = (const float*)d_in[25];
    float* out = (float*)d_out;

    float *pconv, *ph1, *ph2, *pxg, *pfeat, *plf, *pcst;
    __nv_bfloat16 *pw1h, *pw1l, *pw2h, *pw2l, *pwih_h, *pwih_l;
    __nv_bfloat16 *pc1h, *pc1l, *pc2h, *pc2l, *pc3h, *pc3l;
    __nv_bfloat16 *phhA, *phlA, *phhB, *phlB;
    cudaGetSymbolAddress((void**)&pconv, g_conv);
    cudaGetSymbolAddress((void**)&ph1, g_h1);
    cudaGetSymbolAddress((void**)&ph2, g_h2);
    cudaGetSymbolAddress((void**)&pxg, g_xg);
    cudaGetSymbolAddress((void**)&pfeat, g_feat);
    cudaGetSymbolAddress((void**)&plf, g_lf);
    cudaGetSymbolAddress((void**)&pcst, g_cst);
    cudaGetSymbolAddress((void**)&phhA, g_hhA);
    cudaGetSymbolAddress((void**)&phlA, g_hlA);
    cudaGetSymbolAddress((void**)&phhB, g_hhB);
    cudaGetSymbolAddress((void**)&phlB, g_hlB);
    cudaGetSymbolAddress((void**)&pw1h, g_wfc1_hi);
    cudaGetSymbolAddress((void**)&pw1l, g_wfc1_lo);
    cudaGetSymbolAddress((void**)&pw2h, g_wfc2_hi);
    cudaGetSymbolAddress((void**)&pw2l, g_wfc2_lo);
    cudaGetSymbolAddress((void**)&pwih_h, g_wih_hi);
    cudaGetSymbolAddress((void**)&pwih_l, g_wih_lo);
    cudaGetSymbolAddress((void**)&pc1h, g_cw1h);
    cudaGetSymbolAddress((void**)&pc1l, g_cw1l);
    cudaGetSymbolAddress((void**)&pc2h, g_cw2h);
    cudaGetSymbolAddress((void**)&pc2l, g_cw2l);
    cudaGetSymbolAddress((void**)&pc3h, g_cw3h);
    cudaGetSymbolAddress((void**)&pc3l, g_cw3l);

    const int SMEM_TG = 128 * 132 * 4;
    cudaFuncSetAttribute(tgemm<1>, cudaFuncAttributeMaxDynamicSharedMemorySize, SMEM_TG);
    cudaFuncSetAttribute(tgemm<0>, cudaFuncAttributeMaxDynamicSharedMemorySize, SMEM_TG);
    const int SMEM_CONV = 2 * IMG_BYTES + 2 * CW_HALF;
    cudaFuncSetAttribute(conv3_mma, cudaFuncAttributeMaxDynamicSharedMemorySize, SMEM_CONV);
    cudaFuncSetAttribute(lstm_persist, cudaFuncAttributeMaxDynamicSharedMemorySize, LS_SMEM);

    wcprep<<<25, 256>>>(c1w, pc1h, pc1l, 25);
    wcprep<<<9, 256>>>(c2w, pc2h, pc2l, 9);
    wcprep<<<9, 256>>>(c3w, pc3h, pc3l, 9);
    conv3_mma<<<TBTOT, 256, SMEM_CONV>>>(x, c1b, c2b, c3b);
    wprep<<<(512 * 1024 + 255) / 256, 256>>>(fc1w, pw1h, pw1l, 512 * 1024);
    tgemm<1><<<dim3(512 / 128, TBTOT / 128), 256, SMEM_TG>>>(
        pconv, pw1h, pw1l, fc1b, nullptr, ph1, TBTOT, 512, 4096);

    wprep<<<(512 * 128 + 255) / 256, 256>>>(fc2w, pw2h, pw2l, 512 * 128);
    wprep<<<(2048 * 128 + 255) / 256, 256>>>(wih, pwih_h, pwih_l, 2048 * 128);
    wlstm_prep<<<(2048 * 128 + 255) / 256, 256>>>(whh);
    pack_h0<<<(B_ENV * HID + 255) / 256, 256>>>(h0, done);
    cudaMemcpyAsync(pcst, c0, (size_t)B_ENV * HID * sizeof(float),
                    cudaMemcpyDeviceToDevice, 0);

    tgemm<1><<<dim3(512 / 128, TBTOT / 128), 256, SMEM_TG>>>(
        ph1, pw2h, pw2l, fc2b, nullptr, ph2, TBTOT, 512, 512);
    tgemm<0><<<dim3(2048 / 128, TBTOT / 128), 256, SMEM_TG>>>(
        ph2, pwih_h, pwih_l, bih, bhh, pxg, TBTOT, 2048, 512);

    // entire recurrence in ONE persistent kernel (cp.async pipeline)
    lstm_persist<<<NB_LSTM, 256, LS_SMEM>>>(pxg, done, phhA, phlA, phhB, phlB,
                                            pcst, pfeat);

    // lofeat: feat(512) + one-hot(z) via epilogue, ldb=520, leaky
    sgemm128<1, 1><<<dim3(FE / 128, TBTOT / 128), 256>>>(
        pfeat, lfw, lfb, nullptr, plf, TBTOT, FE, 512, 520, z);

    // heads + softmax stats
    head_kernel<<<TBTOT / 8, 256>>>(plf, aw, ab, cw, cb, action, out);
}

// round 12
// speedup vs baseline: 1.9421x; 1.0277x over previous
#include <cuda_runtime.h>
#include <cuda_bf16.h>
#include <math.h>
#include <stdint.h>

#define T_STEPS 128
#define B_ENV   128
#define HID     512
#define TBTOT   (T_STEPS * B_ENV)
#define ZD      8
#define AD      7
#define FE      128
#define NB_LSTM 128

// ----------------------------------------------------------------------------
// Scratch (device globals; no allocation allowed)
// ----------------------------------------------------------------------------
__device__ __nv_bfloat16 g_a1h[TBTOT * 4096];
__device__ __nv_bfloat16 g_a1l[TBTOT * 4096];
__device__ __nv_bfloat16 g_h1h[TBTOT * HID];
__device__ __nv_bfloat16 g_h1l[TBTOT * HID];
__device__ __nv_bfloat16 g_h2h[TBTOT * HID];
__device__ __nv_bfloat16 g_h2l[TBTOT * HID];
__device__ float g_xg[TBTOT * 2048];
__device__ __nv_bfloat16 g_feath[TBTOT * HID];
__device__ __nv_bfloat16 g_featl[TBTOT * HID];
__device__ float g_lf[TBTOT * FE];
__device__ float g_cst[B_ENV * HID];
__device__ __nv_bfloat16 g_hhA[B_ENV * HID];
__device__ __nv_bfloat16 g_hlA[B_ENV * HID];
__device__ __nv_bfloat16 g_hhB[B_ENV * HID];
__device__ __nv_bfloat16 g_hlB[B_ENV * HID];
__device__ __nv_bfloat16 g_wlh[128 * 16 * 512];
__device__ __nv_bfloat16 g_wll[128 * 16 * 512];
__device__ __nv_bfloat16 g_wfc1_hi[512 * 4096];
__device__ __nv_bfloat16 g_wfc1_lo[512 * 4096];
__device__ __nv_bfloat16 g_wfc2_hi[512 * 512];
__device__ __nv_bfloat16 g_wfc2_lo[512 * 512];
__device__ __nv_bfloat16 g_wih_hi[2048 * 512];
__device__ __nv_bfloat16 g_wih_lo[2048 * 512];
__device__ __nv_bfloat16 g_wlf_hi[128 * 512];
__device__ __nv_bfloat16 g_wlf_lo[128 * 512];
__device__ __nv_bfloat16 g_cw1h[25 * 256];
__device__ __nv_bfloat16 g_cw1l[25 * 256];
__device__ __nv_bfloat16 g_cw2h[9 * 256];
__device__ __nv_bfloat16 g_cw2l[9 * 256];
__device__ __nv_bfloat16 g_cw3h[9 * 256];
__device__ __nv_bfloat16 g_cw3l[9 * 256];
__device__ unsigned int g_bar_cnt;
__device__ volatile unsigned int g_bar_gen;

// ============================================================================
// Helpers
// ============================================================================
__device__ __forceinline__ uint32_t smem_to_u32(const void* smem_ptr) {
    uint32_t addr;
    asm("{ .reg .u64 tmp; cvta.to.shared.u64 tmp, %1; cvt.u32.u64 %0, tmp; }"
        : "=r"(addr) : "l"(smem_ptr));
    return addr;
}

__device__ __forceinline__ void ldsm4(uint32_t addr, uint32_t* r) {
    asm volatile("ldmatrix.sync.aligned.m8n8.x4.shared.b16 {%0,%1,%2,%3}, [%4];"
        : "=r"(r[0]), "=r"(r[1]), "=r"(r[2]), "=r"(r[3]) : "r"(addr));
}

__device__ __forceinline__ void mma16816(float* d, const uint32_t* a,
                                         const uint32_t* b) {
    asm volatile(
        "mma.sync.aligned.m16n8k16.row.col.f32.bf16.bf16.f32 "
        "{%0,%1,%2,%3}, {%4,%5,%6,%7}, {%8,%9}, {%0,%1,%2,%3};"
        : "+f"(d[0]), "+f"(d[1]), "+f"(d[2]), "+f"(d[3])
        : "r"(a[0]), "r"(a[1]), "r"(a[2]), "r"(a[3]), "r"(b[0]), "r"(b[1]));
}

__device__ __forceinline__ void split2(float x, float y, uint32_t& hi, uint32_t& lo) {
    __nv_bfloat16 hx = __float2bfloat16(x), hy = __float2bfloat16(y);
    __nv_bfloat162 h2; h2.x = hx; h2.y = hy;
    hi = reinterpret_cast<uint32_t&>(h2);
    float lx = x - __bfloat162float(hx);
    float ly = y - __bfloat162float(hy);
    __nv_bfloat162 l2 = __floats2bfloat162_rn(lx, ly);
    lo = reinterpret_cast<uint32_t&>(l2);
}

#define CP_ASYNC16(dst, src) \
    asm volatile("cp.async.ca.shared.global [%0], [%1], 16;" \
        :: "r"(dst), "l"(src) : "memory")
#define CP_COMMIT() asm volatile("cp.async.commit_group;" ::: "memory")
#define CP_WAIT2() asm volatile("cp.async.wait_group 2;" ::: "memory")

__device__ __forceinline__ void grid_bar() {
    __threadfence();
    __syncthreads();
    if (threadIdx.x == 0) {
        unsigned int gen = g_bar_gen;
        if (atomicAdd(&g_bar_cnt, 1u) == NB_LSTM - 1) {
            g_bar_cnt = 0;
            __threadfence();
            g_bar_gen = gen + 1;
        } else {
            while (g_bar_gen == gen) { }
            __threadfence();
        }
    }
    __syncthreads();
}

// ----------------------------------------------------------------------------
// Weight prep kernels
// ----------------------------------------------------------------------------
__global__ void wprep(const float* __restrict__ w, __nv_bfloat16* __restrict__ hi,
                      __nv_bfloat16* __restrict__ lo, int total4) {
    int idx = blockIdx.x * blockDim.x + threadIdx.x;
    if (idx >= total4) return;
    float4 a = *(const float4*)(w + (size_t)idx * 4);
    uint32_t h0, h1, l0, l1;
    split2(a.x, a.y, h0, l0);
    split2(a.z, a.w, h1, l1);
    *(uint2*)(hi + (size_t)idx * 4) = make_uint2(h0, h1);
    *(uint2*)(lo + (size_t)idx * 4) = make_uint2(l0, l1);
}

// strided variant: rows x 512 from src with row stride ldw
__global__ void wprep_ld(const float* __restrict__ w, __nv_bfloat16* __restrict__ hi,
                         __nv_bfloat16* __restrict__ lo, int rows, int ldw) {
    int idx = blockIdx.x * blockDim.x + threadIdx.x;
    if (idx >= rows * 128) return;
    int row = idx >> 7;
    int k4 = (idx & 127) * 4;
    float4 a = *(const float4*)(w + (size_t)row * ldw + k4);
    uint32_t h0, h1, l0, l1;
    split2(a.x, a.y, h0, l0);
    split2(a.z, a.w, h1, l1);
    *(uint2*)(hi + (size_t)row * 512 + k4) = make_uint2(h0, h1);
    *(uint2*)(lo + (size_t)row * 512 + k4) = make_uint2(l0, l1);
}

__global__ void wcprep(const float* __restrict__ w, __nv_bfloat16* __restrict__ hi,
                       __nv_bfloat16* __restrict__ lo, int taps) {
    int idx = blockIdx.x * blockDim.x + threadIdx.x;
    if (idx >= taps * 256) return;
    int r = idx & 255;
    int t = idx >> 8;
    float v = w[r * taps + t];
    __nv_bfloat16 hv = __float2bfloat16(v);
    float lv = v - __bfloat162float(hv);
    hi[t * 256 + r] = hv;
    lo[t * 256 + r] = __float2bfloat16(lv);
}

__global__ void wlstm_prep(const float* __restrict__ whh) {
    int idx = blockIdx.x * blockDim.x + threadIdx.x;
    if (idx >= 2048 * 128) return;
    int row = idx >> 7;
    int k4 = (idx & 127) * 4;
    int g = row >> 9, j = row & 511;
    int blk = j >> 2, jj = j & 3;
    int n = 2 * jj + (g & 1) + 8 * (g >> 1);
    size_t dst = ((size_t)(blk * 16 + n)) * 512 + k4;
    float4 v = *(const float4*)(whh + (size_t)row * 512 + k4);
    uint32_t h0, h1, l0, l1;
    split2(v.x, v.y, h0, l0);
    split2(v.z, v.w, h1, l1);
    *(uint2*)(g_wlh + dst) = make_uint2(h0, h1);
    *(uint2*)(g_wll + dst) = make_uint2(l0, l1);
}

__global__ void pack_h0(const float* __restrict__ h0, const int* __restrict__ done) {
    int i = blockIdx.x * blockDim.x + threadIdx.x;
    if (i >= B_ENV * HID) return;
    int b = i >> 9;
    float m = done[b] ? 0.f : 1.f;
    float v = h0[i] * m;
    __nv_bfloat16 hv = __float2bfloat16(v);
    g_hhA[i] = hv;
    g_hlA[i] = __float2bfloat16(v - __bfloat162float(hv));
}

// ----------------------------------------------------------------------------
// tgemm2: all operands pre-split bf16 hi/lo, cp.async 4-buffer depth-3
// pipeline. C = act(A W^T + bias (+bias2) (+z one-hot)). 128x128 tiles.
// OUTSPLIT: write bf16 hi/lo; else fp32.
// ----------------------------------------------------------------------------
#define SMSTR 80
#define TG_BUF 40960     // per-stage: Ah|Al|Bh|Bl each 10240
#define TG_SMEM (4 * TG_BUF)

template <int ACT, int OUTSPLIT, int ZMODE>
__global__ __launch_bounds__(256) void tgemm2(
    const __nv_bfloat16* __restrict__ Ahi, const __nv_bfloat16* __restrict__ Alo,
    const __nv_bfloat16* __restrict__ Whi, const __nv_bfloat16* __restrict__ Wlo,
    const float* __restrict__ bias, const float* __restrict__ bias2,
    float* __restrict__ C, __nv_bfloat16* __restrict__ Chi,
    __nv_bfloat16* __restrict__ Clo,
    const float* __restrict__ Wzf, int ldw, const int* __restrict__ z,
    int M, int N, int K) {
    extern __shared__ uint8_t sm[];
    uint32_t sb = smem_to_u32(sm);
    int tid = threadIdx.x;
    int lane = tid & 31;
    int wid = tid >> 5;
    int wm = wid & 3, wn = wid >> 2;
    int m0 = blockIdx.y * 128, n0 = blockIdx.x * 128;
    int sr0 = tid >> 2, sq = tid & 3;
    int nslab = K / 32;

    float acc[2][8][4];
#pragma unroll
    for (int i = 0; i < 2; i++)
#pragma unroll
        for (int j = 0; j < 8; j++)
#pragma unroll
            for (int q = 0; q < 4; q++) acc[i][j][q] = 0.f;

    auto cpa = [&](int s) {
        uint32_t buf = sb + (uint32_t)((s & 3) * TG_BUF);
        size_t ko = (size_t)s * 32 + sq * 8;
#pragma unroll
        for (int q = 0; q < 2; q++) {
            int r = sr0 + 64 * q;
            uint32_t d = (uint32_t)(r * SMSTR + sq * 16);
            CP_ASYNC16(buf + d,         Ahi + (size_t)(m0 + r) * K + ko);
            CP_ASYNC16(buf + 10240 + d, Alo + (size_t)(m0 + r) * K + ko);
            CP_ASYNC16(buf + 20480 + d, Whi + (size_t)(n0 + r) * K + ko);
            CP_ASYNC16(buf + 30720 + d, Wlo + (size_t)(n0 + r) * K + ko);
        }
        CP_COMMIT();
    };

    cpa(0); cpa(1); cpa(2);

    int g = lane >> 3;
    int arow_off = (lane & 7) + (g & 1) * 8;
    int akb_off = (g >> 1) * 16;
    int brow_off = (lane & 7) + (g >> 1) * 8;
    int bkb_off = (g & 1) * 16;

    for (int s = 0; s < nslab; s++) {
        CP_WAIT2();
        __syncthreads();
        if (s + 3 < nslab) cpa(s + 3);
        else CP_COMMIT();
        uint32_t buf = sb + (uint32_t)((s & 3) * TG_BUF);
#pragma unroll
        for (int kk2 = 0; kk2 < 2; kk2++) {
            int kb = kk2 * 32;
            uint32_t ah[2][4], al[2][4], bh[4][4], bl[4][4];
#pragma unroll
            for (int mi = 0; mi < 2; mi++) {
                uint32_t r = (uint32_t)((wm * 32 + mi * 16 + arow_off) * SMSTR +
                                        kb + akb_off);
                ldsm4(buf + r, ah[mi]);
                ldsm4(buf + 10240 + r, al[mi]);
            }
#pragma unroll
            for (int pi = 0; pi < 4; pi++) {
                uint32_t r = (uint32_t)((wn * 64 + pi * 16 + brow_off) * SMSTR +
                                        kb + bkb_off);
                ldsm4(buf + 20480 + r, bh[pi]);
                ldsm4(buf + 30720 + r, bl[pi]);
            }
#pragma unroll
            for (int mi = 0; mi < 2; mi++)
#pragma unroll
                for (int pi = 0; pi < 4; pi++)
#pragma unroll
                    for (int half = 0; half < 2; half++) {
                        float* d = acc[mi][pi * 2 + half];
                        mma16816(d, ah[mi], &bh[pi][half * 2]);
                        mma16816(d, ah[mi], &bl[pi][half * 2]);
                        mma16816(d, al[mi], &bh[pi][half * 2]);
                    }
        }
    }
    __syncthreads();

    // epilogue via smem (ct = 128x132 fp32)
    float* ct = (float*)sm;
#pragma unroll
    for (int mi = 0; mi < 2; mi++) {
        int r0 = wm * 32 + mi * 16 + (lane >> 2);
        int z0 = 0, z1 = 0;
        if (ZMODE) {
            z0 = z[m0 + r0];
            z1 = z[m0 + r0 + 8];
        }
#pragma unroll
        for (int ni = 0; ni < 8; ni++) {
            int c = wn * 64 + ni * 8 + (lane & 3) * 2;
            float b0 = bias[n0 + c], b1 = bias[n0 + c + 1];
            if (bias2) { b0 += bias2[n0 + c]; b1 += bias2[n0 + c + 1]; }
            float v0 = acc[mi][ni][0] + b0;
            float v1 = acc[mi][ni][1] + b1;
            float v2 = acc[mi][ni][2] + b0;
            float v3 = acc[mi][ni][3] + b1;
            if (ZMODE) {
                v0 += Wzf[(size_t)(n0 + c) * ldw + 512 + z0];
                v1 += Wzf[(size_t)(n0 + c + 1) * ldw + 512 + z0];
                v2 += Wzf[(size_t)(n0 + c) * ldw + 512 + z1];
                v3 += Wzf[(size_t)(n0 + c + 1) * ldw + 512 + z1];
            }
            if (ACT) {
                v0 = v0 > 0.f ? v0 : 0.01f * v0;
                v1 = v1 > 0.f ? v1 : 0.01f * v1;
                v2 = v2 > 0.f ? v2 : 0.01f * v2;
                v3 = v3 > 0.f ? v3 : 0.01f * v3;
            }
            ct[r0 * 132 + c] = v0;
            ct[r0 * 132 + c + 1] = v1;
            ct[(r0 + 8) * 132 + c] = v2;
            ct[(r0 + 8) * 132 + c + 1] = v3;
        }
    }
    __syncthreads();
    {
        int r8 = tid >> 5;
        int c4 = (tid & 31) * 4;
#pragma unroll
        for (int p = 0; p < 16; p++) {
            int r = p * 8 + r8;
            float4 v = *(const float4*)(ct + r * 132 + c4);
            size_t o = (size_t)(m0 + r) * N + n0 + c4;
            if (OUTSPLIT) {
                uint32_t h0, h1, l0, l1;
                split2(v.x, v.y, h0, l0);
                split2(v.z, v.w, h1, l1);
                *(uint2*)(Chi + o) = make_uint2(h0, h1);
                *(uint2*)(Clo + o) = make_uint2(l0, l1);
            } else {
                *(float4*)(C + o) = v;
            }
        }
    }
}

// ----------------------------------------------------------------------------
// HMMA conv (proven); final layer writes SPLIT bf16 activations
// ----------------------------------------------------------------------------
#define PSTR 48
#define IMG_BYTES (400 * PSTR)
#define CW_OFF   (2 * IMG_BYTES)
#define CW_HALF  12800

template <int KS, int P, int LAST>
__device__ __forceinline__ void conv_hmma_layer(
    uint8_t* csm, uint32_t sbase, const __nv_bfloat16* wsrc_h,
    const __nv_bfloat16* wsrc_l, const float* __restrict__ bias,
    __nv_bfloat16* goh, __nv_bfloat16* gol, int tid, int lane, int wid) {
    const int taps = KS * KS;
    {
        const uint4* sh = (const uint4*)wsrc_h;
        const uint4* sl = (const uint4*)wsrc_l;
        uint4* dh = (uint4*)(csm + CW_OFF);
        uint4* dl = (uint4*)(csm + CW_OFF + CW_HALF);
        for (int i = tid; i < taps * 32; i += 256) {
            dh[i] = sh[i];
            dl[i] = sl[i];
        }
    }
    __syncthreads();

    float acc[2][2][4];
#pragma unroll
    for (int a = 0; a < 2; a++)
#pragma unroll
        for (int b = 0; b < 2; b++)
#pragma unroll
            for (int q = 0; q < 4; q++) acc[a][b][q] = 0.f;

    int g = lane >> 3;
    int h0 = wid * 2;
    uint32_t aoff[2];
#pragma unroll
    for (int mi = 0; mi < 2; mi++)
        aoff[mi] = (uint32_t)(((h0 + mi + 2) * 20 + 2 + (lane & 7) + (g & 1) * 8) * PSTR +
                              (g >> 1) * 16);
    uint32_t boff = (uint32_t)(((lane & 7) + (g >> 1) * 8) * 32 + (g & 1) * 16);
    uint32_t wb_h = sbase + CW_OFF;
    uint32_t wb_l = sbase + CW_OFF + CW_HALF;

#pragma unroll
    for (int kh = 0; kh < KS; kh++) {
#pragma unroll
        for (int kw = 0; kw < KS; kw++) {
            int t = kh * KS + kw;
            int shift = ((kh - P) * 20 + (kw - P)) * PSTR;
            uint32_t bh4[4], bl4[4];
            ldsm4(wb_h + t * 512 + boff, bh4);
            ldsm4(wb_l + t * 512 + boff, bl4);
#pragma unroll
            for (int mi = 0; mi < 2; mi++) {
                uint32_t ah[4], al[4];
                ldsm4(sbase + aoff[mi] + shift, ah);
                ldsm4(sbase + IMG_BYTES + aoff[mi] + shift, al);
#pragma unroll
                for (int nh = 0; nh < 2; nh++) {
                    mma16816(acc[mi][nh], ah, &bh4[nh * 2]);
                    mma16816(acc[mi][nh], ah, &bl4[nh * 2]);
                    mma16816(acc[mi][nh], al, &bh4[nh * 2]);
                }
            }
        }
    }
    __syncthreads();

#pragma unroll
    for (int mi = 0; mi < 2; mi++) {
        int h = h0 + mi;
#pragma unroll
        for (int nh = 0; nh < 2; nh++) {
            int co = nh * 8 + (lane & 3) * 2;
            float b0 = bias[co], b1 = bias[co + 1];
#pragma unroll
            for (int rr = 0; rr < 2; rr++) {
                int w = (lane >> 2) + rr * 8;
                float v0 = acc[mi][nh][rr * 2 + 0] + b0;
                float v1 = acc[mi][nh][rr * 2 + 1] + b1;
                v0 = v0 > 0.f ? v0 : 0.01f * v0;
                v1 = v1 > 0.f ? v1 : 0.01f * v1;
                if (LAST) {
                    int k0 = co * 256 + h * 16 + w;
                    __nv_bfloat16 hv0 = __float2bfloat16(v0);
                    goh[k0] = hv0;
                    gol[k0] = __float2bfloat16(v0 - __bfloat162float(hv0));
                    __nv_bfloat16 hv1 = __float2bfloat16(v1);
                    goh[k0 + 256] = hv1;
                    gol[k0 + 256] = __float2bfloat16(v1 - __bfloat162float(hv1));
                } else {
                    uint32_t hp, lp;
                    split2(v0, v1, hp, lp);
                    int pb = ((h + 2) * 20 + (w + 2)) * PSTR + co * 2;
                    *(uint32_t*)(csm + pb) = hp;
                    *(uint32_t*)(csm + IMG_BYTES + pb) = lp;
                }
            }
        }
    }
    __syncthreads();
}

__global__ __launch_bounds__(256) void conv3_mma(
    const float* __restrict__ x,
    const float* __restrict__ b1, const float* __restrict__ b2,
    const float* __restrict__ b3) {
    extern __shared__ uint8_t csm[];
    uint32_t sbase = smem_to_u32(csm);
    int tid = threadIdx.x;
    int lane = tid & 31;
    int wid = tid >> 5;
    int img = blockIdx.x;
    const float* xi = x + (size_t)img * 4096;

    for (int i = tid; i < 2 * IMG_BYTES / 4; i += 256)
        ((uint32_t*)csm)[i] = 0;
    __syncthreads();
    for (int i = tid; i < 4096; i += 256) {
        int ci = i >> 8, p = i & 255;
        int h = p >> 4, w = p & 15;
        float v = xi[i];
        __nv_bfloat16 hv = __float2bfloat16(v);
        float lv = v - __bfloat162float(hv);
        int pb = ((h + 2) * 20 + (w + 2)) * PSTR + ci * 2;
        *(__nv_bfloat16*)(csm + pb) = hv;
        *(__nv_bfloat16*)(csm + IMG_BYTES + pb) = __float2bfloat16(lv);
    }
    __syncthreads();

    __nv_bfloat16* goh = g_a1h + (size_t)img * 4096;
    __nv_bfloat16* gol = g_a1l + (size_t)img * 4096;
    conv_hmma_layer<5, 2, 0>(csm, sbase, g_cw1h, g_cw1l, b1, goh, gol, tid, lane, wid);
    conv_hmma_layer<3, 1, 0>(csm, sbase, g_cw2h, g_cw2l, b2, goh, gol, tid, lane, wid);
    conv_hmma_layer<3, 1, 1>(csm, sbase, g_cw3h, g_cw3l, b3, goh, gol, tid, lane, wid);
}

// ----------------------------------------------------------------------------
// Persistent LSTM (R11, proven): cp.async depth-3 pipeline; feat written SPLIT
// ----------------------------------------------------------------------------
__device__ __forceinline__ float sigm(float x) { return 1.f / (1.f + expf(-x)); }

#define LW_STR   1040
#define LS_W_SZ  (2 * 16 * LW_STR)
#define LS_A_OFF LS_W_SZ
#define LS_A_BUF (2 * 128 * SMSTR)
#define LS_M_OFF (LS_A_OFF + 4 * LS_A_BUF)
#define LS_SMEM  (LS_M_OFF + 1024)

__global__ __launch_bounds__(256) void lstm_persist(
    const float* __restrict__ xg, const int* __restrict__ done,
    __nv_bfloat16* __restrict__ hAh, __nv_bfloat16* __restrict__ hAl,
    __nv_bfloat16* __restrict__ hBh, __nv_bfloat16* __restrict__ hBl,
    float* __restrict__ c_st) {
    extern __shared__ uint8_t psm[];
    float* s_m  = (float*)(psm + LS_M_OFF);
    float* s_mn = (float*)(psm + LS_M_OFF + 512);
    uint32_t sbW = smem_to_u32(psm);
    int tid = threadIdx.x, lane = tid & 31, wid = tid >> 5;
    int blk = blockIdx.x;
    int jb4 = blk * 4;

    {
        const uint4* Wh = (const uint4*)(g_wlh + (size_t)blk * 16 * 512);
        const uint4* Wl = (const uint4*)(g_wll + (size_t)blk * 16 * 512);
#pragma unroll
        for (int i = 0; i < 4; i++) {
            int i4 = tid + 256 * i;
            int r = i4 >> 6, q = i4 & 63;
            *(uint4*)(psm + r * LW_STR + q * 16) = Wh[i4];
            *(uint4*)(psm + 16 * LW_STR + r * LW_STR + q * 16) = Wl[i4];
        }
    }

    int r1 = wid * 16 + (lane >> 2);
    int L = lane & 3;
    int gq = lane >> 3;
    uint32_t arow = (uint32_t)((wid * 16 + (lane & 7) + (gq & 1) * 8) * SMSTR +
                               (gq >> 1) * 16);
    uint32_t brow = (uint32_t)(((lane & 7) + (gq >> 1) * 8) * LW_STR + (gq & 1) * 16);
    int sr0 = tid >> 2, sq = tid & 3;

    float creg[2];
#pragma unroll
    for (int rr = 0; rr < 2; rr++)
        creg[rr] = c_st[(size_t)(r1 + rr * 8) * 512 + jb4 + L];
    __syncthreads();

    for (int t = 0; t < T_STEPS; t++) {
        const __nv_bfloat16* hih = (t & 1) ? hBh : hAh;
        const __nv_bfloat16* hil = (t & 1) ? hBl : hAl;
        __nv_bfloat16* hoh = (t & 1) ? hAh : hBh;
        __nv_bfloat16* hol = (t & 1) ? hAl : hBl;

        auto cpa_slab = [&](int s) {
            uint32_t base = sbW + LS_A_OFF + (uint32_t)((s & 3) * LS_A_BUF);
#pragma unroll
            for (int q = 0; q < 2; q++) {
                int r = sr0 + 64 * q;
                CP_ASYNC16(base + r * SMSTR + sq * 16,
                           hih + (size_t)r * 512 + s * 32 + sq * 8);
                CP_ASYNC16(base + 128 * SMSTR + r * SMSTR + sq * 16,
                           hil + (size_t)r * 512 + s * 32 + sq * 8);
            }
            CP_COMMIT();
        };

        cpa_slab(0);
        cpa_slab(1);
        cpa_slab(2);

        if (tid < 128) {
            s_m[tid] = done[t * 128 + tid] ? 0.f : 1.f;
            s_mn[tid] = (t + 1 < T_STEPS)
                            ? (done[(t + 1) * 128 + tid] ? 0.f : 1.f) : 1.f;
        }

        float acc[2][4];
#pragma unroll
        for (int pi = 0; pi < 2; pi++)
#pragma unroll
            for (int rr = 0; rr < 2; rr++)
#pragma unroll
                for (int cc = 0; cc < 2; cc++)
                    acc[pi][rr * 2 + cc] = xg[(size_t)(t * 128 + r1 + rr * 8) * 2048 +
                                              (cc + 2 * pi) * 512 + jb4 + L];

        for (int s = 0; s < 16; s++) {
            CP_WAIT2();
            __syncthreads();
            if (s < 13) cpa_slab(s + 3);
            else CP_COMMIT();
            uint32_t sbA = sbW + LS_A_OFF + (uint32_t)((s & 3) * LS_A_BUF);
#pragma unroll
            for (int kk2 = 0; kk2 < 2; kk2++) {
                int kb = kk2 * 32;
                uint32_t ah[4], al[4], bh4[4], bl4[4];
                ldsm4(sbA + arow + kb, ah);
                ldsm4(sbA + 128 * SMSTR + arow + kb, al);
                uint32_t bo = brow + s * 64 + kb;
                ldsm4(sbW + bo, bh4);
                ldsm4(sbW + 16 * LW_STR + bo, bl4);
#pragma unroll
                for (int pi = 0; pi < 2; pi++) {
                    float* d = acc[pi];
                    mma16816(d, ah, &bh4[pi * 2]);
                    mma16816(d, ah, &bl4[pi * 2]);
                    mma16816(d, al, &bh4[pi * 2]);
                }
            }
        }

#pragma unroll
        for (int rr = 0; rr < 2; rr++) {
            int r = r1 + rr * 8;
            float m = s_m[r];
            float mn = s_mn[r];
            int j = jb4 + L;
            float gi = acc[0][rr * 2 + 0];
            float gf = acc[0][rr * 2 + 1];
            float gg = acc[1][rr * 2 + 0];
            float go = acc[1][rr * 2 + 1];
            float cn = sigm(gf) * (creg[rr] * m) + sigm(gi) * tanhf(gg);
            float hn = sigm(go) * tanhf(cn);
            creg[rr] = cn;
            size_t fo = (size_t)(t * 128 + r) * 512 + j;
            __nv_bfloat16 fh = __float2bfloat16(hn);
            g_feath[fo] = fh;
            g_featl[fo] = __float2bfloat16(hn - __bfloat162float(fh));
            float hw = hn * mn;
            __nv_bfloat16 hh = __float2bfloat16(hw);
            hoh[(size_t)r * 512 + j] = hh;
            hol[(size_t)r * 512 + j] = __float2bfloat16(hw - __bfloat162float(hh));
        }
        grid_bar();
    }
}

// ----------------------------------------------------------------------------
// Head: warp per row; actor/critic GEMV + log_softmax/entropy/prob pack.
// ----------------------------------------------------------------------------
__global__ __launch_bounds__(256) void head_kernel(
    const float* __restrict__ lf, const float* __restrict__ aw,
    const float* __restrict__ ab, const float* __restrict__ cw,
    const float* __restrict__ cb, const int* __restrict__ action,
    float* __restrict__ out) {
    int warp = (blockIdx.x * blockDim.x + threadIdx.x) >> 5;
    int lane = threadIdx.x & 31;
    if (warp >= TBTOT) return;
    float4 f = *(const float4*)(lf + (size_t)warp * FE + lane * 4);
    float r[8];
#pragma unroll
    for (int a = 0; a < 7; a++) {
        float4 w = *(const float4*)(aw + a * FE + lane * 4);
        r[a] = f.x * w.x + f.y * w.y + f.z * w.z + f.w * w.w;
    }
    {
        float4 w = *(const float4*)(cw + lane * 4);
        r[7] = f.x * w.x + f.y * w.y + f.z * w.z + f.w * w.w;
    }
#pragma unroll
    for (int a = 0; a < 8; a++)
#pragma unroll
        for (int s = 16; s > 0; s >>= 1)
            r[a] += __shfl_xor_sync(0xffffffffu, r[a], s);

    if (lane == 0) {
        float lg[7];
        float mx = -1e30f;
#pragma unroll
        for (int a = 0; a < 7; a++) {
            lg[a] = r[a] + ab[a];
            mx = fmaxf(mx, lg[a]);
        }
        float se = 0.f;
        float e[7];
#pragma unroll
        for (int a = 0; a < 7; a++) {
            e[a] = expf(lg[a] - mx);
            se += e[a];
        }
        float lse = mx + logf(se);
        float inv = 1.f / se;
        float ent = 0.f;
        float* o = out + (size_t)warp * 10;
#pragma unroll
        for (int a = 0; a < 7; a++) {
            float p = e[a] * inv;
            float lp = lg[a] - lse;
            ent -= p * lp;
            o[3 + a] = p;
        }
        int act = action[warp];
        o[0] = lg[act] - lse;
        o[1] = ent;
        o[2] = r[7] + cb[0];
    }
}

// ----------------------------------------------------------------------------
// Launch
// ----------------------------------------------------------------------------
extern "C" void kernel_launch(void* const* d_in, const int* in_sizes, int n_in,
                              void* d_out, int out_size) {
    const float* x    = (const float*)d_in[0];
    const int* done   = (const int*)d_in[1];
    const int* z      = (const int*)d_in[2];
    const int* action = (const int*)d_in[3];
    const float* h0   = (const float*)d_in[4];
    const float* c0   = (const float*)d_in[5];
    const float* c1w = (const float*)d_in[6];  const float* c1b = (const float*)d_in[7];
    const float* c2w = (const float*)d_in[8];  const float* c2b = (const float*)d_in[9];
    const float* c3w = (const float*)d_in[10]; const float* c3b = (const float*)d_in[11];
    const float* fc1w = (const float*)d_in[12]; const float* fc1b = (const float*)d_in[13];
    const float* fc2w = (const float*)d_in[14]; const float* fc2b = (const float*)d_in[15];
    const float* wih = (const float*)d_in[16]; const float* whh = (const float*)d_in[17];
    const float* bih = (const float*)d_in[18]; const float* bhh = (const float*)d_in[19];
    const float* lfw = (const float*)d_in[20]; const float* lfb = (const float*)d_in[21];
    const float* aw = (const float*)d_in[22];  const float* ab = (const float*)d_in[23];
    const float* cw = (const float*)d_in[24];  const float* cb = (const float*)d_in[25];
    float* out = (float*)d_out;

    float *pxg, *plf, *pcst;
    __nv_bfloat16 *pa1h, *pa1l, *ph1h, *ph1l, *ph2h, *ph2l, *pfh, *pfl;
    __nv_bfloat16 *pw1h, *pw1l, *pw2h, *pw2l, *pwih_h, *pwih_l, *pwlfh, *pwlfl;
    __nv_bfloat16 *pc1h, *pc1l, *pc2h, *pc2l, *pc3h, *pc3l;
    __nv_bfloat16 *phhA, *phlA, *phhB, *phlB;
    cudaGetSymbolAddress((void**)&pa1h, g_a1h);
    cudaGetSymbolAddress((void**)&pa1l, g_a1l);
    cudaGetSymbolAddress((void**)&ph1h, g_h1h);
    cudaGetSymbolAddress((void**)&ph1l, g_h1l);
    cudaGetSymbolAddress((void**)&ph2h, g_h2h);
    cudaGetSymbolAddress((void**)&ph2l, g_h2l);
    cudaGetSymbolAddress((void**)&pxg, g_xg);
    cudaGetSymbolAddress((void**)&pfh, g_feath);
    cudaGetSymbolAddress((void**)&pfl, g_featl);
    cudaGetSymbolAddress((void**)&plf, g_lf);
    cudaGetSymbolAddress((void**)&pcst, g_cst);
    cudaGetSymbolAddress((void**)&phhA, g_hhA);
    cudaGetSymbolAddress((void**)&phlA, g_hlA);
    cudaGetSymbolAddress((void**)&phhB, g_hhB);
    cudaGetSymbolAddress((void**)&phlB, g_hlB);
    cudaGetSymbolAddress((void**)&pw1h, g_wfc1_hi);
    cudaGetSymbolAddress((void**)&pw1l, g_wfc1_lo);
    cudaGetSymbolAddress((void**)&pw2h, g_wfc2_hi);
    cudaGetSymbolAddress((void**)&pw2l, g_wfc2_lo);
    cudaGetSymbolAddress((void**)&pwih_h, g_wih_hi);
    cudaGetSymbolAddress((void**)&pwih_l, g_wih_lo);
    cudaGetSymbolAddress((void**)&pwlfh, g_wlf_hi);
    cudaGetSymbolAddress((void**)&pwlfl, g_wlf_lo);
    cudaGetSymbolAddress((void**)&pc1h, g_cw1h);
    cudaGetSymbolAddress((void**)&pc1l, g_cw1l);
    cudaGetSymbolAddress((void**)&pc2h, g_cw2h);
    cudaGetSymbolAddress((void**)&pc2l, g_cw2l);
    cudaGetSymbolAddress((void**)&pc3h, g_cw3h);
    cudaGetSymbolAddress((void**)&pc3l, g_cw3l);

    cudaFuncSetAttribute(tgemm2<1, 1, 0>, cudaFuncAttributeMaxDynamicSharedMemorySize, TG_SMEM);
    cudaFuncSetAttribute(tgemm2<0, 0, 0>, cudaFuncAttributeMaxDynamicSharedMemorySize, TG_SMEM);
    cudaFuncSetAttribute(tgemm2<1, 0, 1>, cudaFuncAttributeMaxDynamicSharedMemorySize, TG_SMEM);
    const int SMEM_CONV = 2 * IMG_BYTES + 2 * CW_HALF;
    cudaFuncSetAttribute(conv3_mma, cudaFuncAttributeMaxDynamicSharedMemorySize, SMEM_CONV);
    cudaFuncSetAttribute(lstm_persist, cudaFuncAttributeMaxDynamicSharedMemorySize, LS_SMEM);

    wcprep<<<25, 256>>>(c1w, pc1h, pc1l, 25);
    wcprep<<<9, 256>>>(c2w, pc2h, pc2l, 9);
    wcprep<<<9, 256>>>(c3w, pc3h, pc3l, 9);
    conv3_mma<<<TBTOT, 256, SMEM_CONV>>>(x, c1b, c2b, c3b);
    wprep<<<(512 * 1024 + 255) / 256, 256>>>(fc1w, pw1h, pw1l, 512 * 1024);
    tgemm2<1, 1, 0><<<dim3(4, 128), 256, TG_SMEM>>>(             // #6 profiled: fc1
        pa1h, pa1l, pw1h, pw1l, fc1b, nullptr,
        nullptr, ph1h, ph1l, nullptr, 0, nullptr, TBTOT, 512, 4096);

    wprep<<<(512 * 128 + 255) / 256, 256>>>(fc2w, pw2h, pw2l, 512 * 128);
    wprep<<<(2048 * 128 + 255) / 256, 256>>>(wih, pwih_h, pwih_l, 2048 * 128);
    wprep_ld<<<(128 * 128 + 255) / 256, 256>>>(lfw, pwlfh, pwlfl, 128, 520);
    wlstm_prep<<<(2048 * 128 + 255) / 256, 256>>>(whh);
    pack_h0<<<(B_ENV * HID + 255) / 256, 256>>>(h0, done);
    cudaMemcpyAsync(pcst, c0, (size_t)B_ENV * HID * sizeof(float),
                    cudaMemcpyDeviceToDevice, 0);

    tgemm2<1, 1, 0><<<dim3(4, 128), 256, TG_SMEM>>>(
        ph1h, ph1l, pw2h, pw2l, fc2b, nullptr,
        nullptr, ph2h, ph2l, nullptr, 0, nullptr, TBTOT, 512, 512);
    tgemm2<0, 0, 0><<<dim3(16, 128), 256, TG_SMEM>>>(
        ph2h, ph2l, pwih_h, pwih_l, bih, bhh,
        pxg, nullptr, nullptr, nullptr, 0, nullptr, TBTOT, 2048, 512);

    // recurrence (persistent, cp.async)
    lstm_persist<<<NB_LSTM, 256, LS_SMEM>>>(pxg, done, phhA, phlA, phhB, phlB,
                                            pcst);

    // lofeat on tensor cores, z one-hot via fp32 gather epilogue
    tgemm2<1, 0, 1><<<dim3(1, 128), 256, TG_SMEM>>>(
        pfh, pfl, pwlfh, pwlfl, lfb, nullptr,
        plf, nullptr, nullptr, lfw, 520, z, TBTOT, FE, 512);

    // heads + softmax stats
    head_kernel<<<TBTOT / 8, 256>>>(plf, aw, ab, cw, cb, action, out);
}

// round 13
// speedup vs baseline: 2.0110x; 1.0355x over previous
#include <cuda_runtime.h>
#include <cuda_bf16.h>
#include <math.h>
#include <stdint.h>

#define T_STEPS 128
#define B_ENV   128
#define HID     512
#define TBTOT   (T_STEPS * B_ENV)
#define ZD      8
#define AD      7
#define FE      128
#define NB_LSTM 128

// ----------------------------------------------------------------------------
// Scratch (device globals; no allocation allowed)
// ----------------------------------------------------------------------------
__device__ __nv_bfloat16 g_a1h[TBTOT * 4096];
__device__ __nv_bfloat16 g_a1l[TBTOT * 4096];
__device__ __nv_bfloat16 g_h1h[TBTOT * HID];
__device__ __nv_bfloat16 g_h1l[TBTOT * HID];
__device__ __nv_bfloat16 g_h2h[TBTOT * HID];
__device__ __nv_bfloat16 g_h2l[TBTOT * HID];
__device__ float g_xg[TBTOT * 2048];
__device__ __nv_bfloat16 g_feath[TBTOT * HID];
__device__ __nv_bfloat16 g_featl[TBTOT * HID];
__device__ float g_lf[TBTOT * FE];
__device__ float g_cst[B_ENV * HID];
__device__ __nv_bfloat16 g_hhA[B_ENV * HID];
__device__ __nv_bfloat16 g_hlA[B_ENV * HID];
__device__ __nv_bfloat16 g_hhB[B_ENV * HID];
__device__ __nv_bfloat16 g_hlB[B_ENV * HID];
__device__ __nv_bfloat16 g_wlh[128 * 16 * 512];
__device__ __nv_bfloat16 g_wll[128 * 16 * 512];
__device__ __nv_bfloat16 g_wfc1_hi[512 * 4096];
__device__ __nv_bfloat16 g_wfc1_lo[512 * 4096];
__device__ __nv_bfloat16 g_wfc2_hi[512 * 512];
__device__ __nv_bfloat16 g_wfc2_lo[512 * 512];
__device__ __nv_bfloat16 g_wih_hi[2048 * 512];
__device__ __nv_bfloat16 g_wih_lo[2048 * 512];
__device__ __nv_bfloat16 g_wlf_hi[128 * 512];
__device__ __nv_bfloat16 g_wlf_lo[128 * 512];
__device__ __nv_bfloat16 g_cw1h[25 * 256];
__device__ __nv_bfloat16 g_cw1l[25 * 256];
__device__ __nv_bfloat16 g_cw2h[9 * 256];
__device__ __nv_bfloat16 g_cw2l[9 * 256];
__device__ __nv_bfloat16 g_cw3h[9 * 256];
__device__ __nv_bfloat16 g_cw3l[9 * 256];
__device__ unsigned int g_bar_cnt;
__device__ volatile unsigned int g_bar_gen;

// ============================================================================
// Helpers
// ============================================================================
__device__ __forceinline__ uint32_t smem_to_u32(const void* smem_ptr) {
    uint32_t addr;
    asm("{ .reg .u64 tmp; cvta.to.shared.u64 tmp, %1; cvt.u32.u64 %0, tmp; }"
        : "=r"(addr) : "l"(smem_ptr));
    return addr;
}

__device__ __forceinline__ void ldsm4(uint32_t addr, uint32_t* r) {
    asm volatile("ldmatrix.sync.aligned.m8n8.x4.shared.b16 {%0,%1,%2,%3}, [%4];"
        : "=r"(r[0]), "=r"(r[1]), "=r"(r[2]), "=r"(r[3]) : "r"(addr));
}

__device__ __forceinline__ void mma16816(float* d, const uint32_t* a,
                                         const uint32_t* b) {
    asm volatile(
        "mma.sync.aligned.m16n8k16.row.col.f32.bf16.bf16.f32 "
        "{%0,%1,%2,%3}, {%4,%5,%6,%7}, {%8,%9}, {%0,%1,%2,%3};"
        : "+f"(d[0]), "+f"(d[1]), "+f"(d[2]), "+f"(d[3])
        : "r"(a[0]), "r"(a[1]), "r"(a[2]), "r"(a[3]), "r"(b[0]), "r"(b[1]));
}

__device__ __forceinline__ void split2(float x, float y, uint32_t& hi, uint32_t& lo) {
    __nv_bfloat16 hx = __float2bfloat16(x), hy = __float2bfloat16(y);
    __nv_bfloat162 h2; h2.x = hx; h2.y = hy;
    hi = reinterpret_cast<uint32_t&>(h2);
    float lx = x - __bfloat162float(hx);
    float ly = y - __bfloat162float(hy);
    __nv_bfloat162 l2 = __floats2bfloat162_rn(lx, ly);
    lo = reinterpret_cast<uint32_t&>(l2);
}

#define CP_ASYNC16(dst, src) \
    asm volatile("cp.async.ca.shared.global [%0], [%1], 16;" \
        :: "r"(dst), "l"(src) : "memory")
#define CP_COMMIT() asm volatile("cp.async.commit_group;" ::: "memory")
#define CP_WAIT2() asm volatile("cp.async.wait_group 2;" ::: "memory")

__device__ __forceinline__ void grid_bar() {
    __threadfence();
    __syncthreads();
    if (threadIdx.x == 0) {
        unsigned int gen = g_bar_gen;
        if (atomicAdd(&g_bar_cnt, 1u) == NB_LSTM - 1) {
            g_bar_cnt = 0;
            __threadfence();
            g_bar_gen = gen + 1;
        } else {
            while (g_bar_gen == gen) { }
            __threadfence();
        }
    }
    __syncthreads();
}

// ----------------------------------------------------------------------------
// Weight prep kernels
// ----------------------------------------------------------------------------
__global__ void wprep(const float* __restrict__ w, __nv_bfloat16* __restrict__ hi,
                      __nv_bfloat16* __restrict__ lo, int total4) {
    int idx = blockIdx.x * blockDim.x + threadIdx.x;
    if (idx >= total4) return;
    float4 a = *(const float4*)(w + (size_t)idx * 4);
    uint32_t h0, h1, l0, l1;
    split2(a.x, a.y, h0, l0);
    split2(a.z, a.w, h1, l1);
    *(uint2*)(hi + (size_t)idx * 4) = make_uint2(h0, h1);
    *(uint2*)(lo + (size_t)idx * 4) = make_uint2(l0, l1);
}

__global__ void wprep_ld(const float* __restrict__ w, __nv_bfloat16* __restrict__ hi,
                         __nv_bfloat16* __restrict__ lo, int rows, int ldw) {
    int idx = blockIdx.x * blockDim.x + threadIdx.x;
    if (idx >= rows * 128) return;
    int row = idx >> 7;
    int k4 = (idx & 127) * 4;
    float4 a = *(const float4*)(w + (size_t)row * ldw + k4);
    uint32_t h0, h1, l0, l1;
    split2(a.x, a.y, h0, l0);
    split2(a.z, a.w, h1, l1);
    *(uint2*)(hi + (size_t)row * 512 + k4) = make_uint2(h0, h1);
    *(uint2*)(lo + (size_t)row * 512 + k4) = make_uint2(l0, l1);
}

// all three conv weight sets in one launch
__global__ void wcprep_all(const float* __restrict__ w1, const float* __restrict__ w2,
                           const float* __restrict__ w3) {
    int idx = blockIdx.x * blockDim.x + threadIdx.x;
    const float* w;
    __nv_bfloat16 *hi, *lo;
    int taps, local;
    if (idx < 6400) { w = w1; hi = g_cw1h; lo = g_cw1l; taps = 25; local = idx; }
    else if (idx < 8704) { w = w2; hi = g_cw2h; lo = g_cw2l; taps = 9; local = idx - 6400; }
    else if (idx < 11008) { w = w3; hi = g_cw3h; lo = g_cw3l; taps = 9; local = idx - 8704; }
    else return;
    int r = local & 255;
    int t = local >> 8;
    float v = w[r * taps + t];
    __nv_bfloat16 hv = __float2bfloat16(v);
    hi[t * 256 + r] = hv;
    lo[t * 256 + r] = __float2bfloat16(v - __bfloat162float(hv));
}

__global__ void wlstm_prep(const float* __restrict__ whh) {
    int idx = blockIdx.x * blockDim.x + threadIdx.x;
    if (idx >= 2048 * 128) return;
    int row = idx >> 7;
    int k4 = (idx & 127) * 4;
    int g = row >> 9, j = row & 511;
    int blk = j >> 2, jj = j & 3;
    int n = 2 * jj + (g & 1) + 8 * (g >> 1);
    size_t dst = ((size_t)(blk * 16 + n)) * 512 + k4;
    float4 v = *(const float4*)(whh + (size_t)row * 512 + k4);
    uint32_t h0, h1, l0, l1;
    split2(v.x, v.y, h0, l0);
    split2(v.z, v.w, h1, l1);
    *(uint2*)(g_wlh + dst) = make_uint2(h0, h1);
    *(uint2*)(g_wll + dst) = make_uint2(l0, l1);
}

__global__ void pack_h0(const float* __restrict__ h0, const int* __restrict__ done) {
    int i = blockIdx.x * blockDim.x + threadIdx.x;
    if (i >= B_ENV * HID) return;
    int b = i >> 9;
    float m = done[b] ? 0.f : 1.f;
    float v = h0[i] * m;
    __nv_bfloat16 hv = __float2bfloat16(v);
    g_hhA[i] = hv;
    g_hlA[i] = __float2bfloat16(v - __bfloat162float(hv));
}

// ----------------------------------------------------------------------------
// tgemm2 (R12, proven): pre-split operands, cp.async depth-3 pipeline
// ----------------------------------------------------------------------------
#define SMSTR 80
#define TG_BUF 40960
#define TG_SMEM (4 * TG_BUF)

template <int ACT, int OUTSPLIT, int ZMODE>
__global__ __launch_bounds__(256) void tgemm2(
    const __nv_bfloat16* __restrict__ Ahi, const __nv_bfloat16* __restrict__ Alo,
    const __nv_bfloat16* __restrict__ Whi, const __nv_bfloat16* __restrict__ Wlo,
    const float* __restrict__ bias, const float* __restrict__ bias2,
    float* __restrict__ C, __nv_bfloat16* __restrict__ Chi,
    __nv_bfloat16* __restrict__ Clo,
    const float* __restrict__ Wzf, int ldw, const int* __restrict__ z,
    int M, int N, int K) {
    extern __shared__ uint8_t sm[];
    uint32_t sb = smem_to_u32(sm);
    int tid = threadIdx.x;
    int lane = tid & 31;
    int wid = tid >> 5;
    int wm = wid & 3, wn = wid >> 2;
    int m0 = blockIdx.y * 128, n0 = blockIdx.x * 128;
    int sr0 = tid >> 2, sq = tid & 3;
    int nslab = K / 32;

    float acc[2][8][4];
#pragma unroll
    for (int i = 0; i < 2; i++)
#pragma unroll
        for (int j = 0; j < 8; j++)
#pragma unroll
            for (int q = 0; q < 4; q++) acc[i][j][q] = 0.f;

    auto cpa = [&](int s) {
        uint32_t buf = sb + (uint32_t)((s & 3) * TG_BUF);
        size_t ko = (size_t)s * 32 + sq * 8;
#pragma unroll
        for (int q = 0; q < 2; q++) {
            int r = sr0 + 64 * q;
            uint32_t d = (uint32_t)(r * SMSTR + sq * 16);
            CP_ASYNC16(buf + d,         Ahi + (size_t)(m0 + r) * K + ko);
            CP_ASYNC16(buf + 10240 + d, Alo + (size_t)(m0 + r) * K + ko);
            CP_ASYNC16(buf + 20480 + d, Whi + (size_t)(n0 + r) * K + ko);
            CP_ASYNC16(buf + 30720 + d, Wlo + (size_t)(n0 + r) * K + ko);
        }
        CP_COMMIT();
    };

    cpa(0); cpa(1); cpa(2);

    int g = lane >> 3;
    int arow_off = (lane & 7) + (g & 1) * 8;
    int akb_off = (g >> 1) * 16;
    int brow_off = (lane & 7) + (g >> 1) * 8;
    int bkb_off = (g & 1) * 16;

    for (int s = 0; s < nslab; s++) {
        CP_WAIT2();
        __syncthreads();
        if (s + 3 < nslab) cpa(s + 3);
        else CP_COMMIT();
        uint32_t buf = sb + (uint32_t)((s & 3) * TG_BUF);
#pragma unroll
        for (int kk2 = 0; kk2 < 2; kk2++) {
            int kb = kk2 * 32;
            uint32_t ah[2][4], al[2][4], bh[4][4], bl[4][4];
#pragma unroll
            for (int mi = 0; mi < 2; mi++) {
                uint32_t r = (uint32_t)((wm * 32 + mi * 16 + arow_off) * SMSTR +
                                        kb + akb_off);
                ldsm4(buf + r, ah[mi]);
                ldsm4(buf + 10240 + r, al[mi]);
            }
#pragma unroll
            for (int pi = 0; pi < 4; pi++) {
                uint32_t r = (uint32_t)((wn * 64 + pi * 16 + brow_off) * SMSTR +
                                        kb + bkb_off);
                ldsm4(buf + 20480 + r, bh[pi]);
                ldsm4(buf + 30720 + r, bl[pi]);
            }
#pragma unroll
            for (int mi = 0; mi < 2; mi++)
#pragma unroll
                for (int pi = 0; pi < 4; pi++)
#pragma unroll
                    for (int half = 0; half < 2; half++) {
                        float* d = acc[mi][pi * 2 + half];
                        mma16816(d, ah[mi], &bh[pi][half * 2]);
                        mma16816(d, ah[mi], &bl[pi][half * 2]);
                        mma16816(d, al[mi], &bh[pi][half * 2]);
                    }
        }
    }
    __syncthreads();

    float* ct = (float*)sm;
#pragma unroll
    for (int mi = 0; mi < 2; mi++) {
        int r0 = wm * 32 + mi * 16 + (lane >> 2);
        int z0 = 0, z1 = 0;
        if (ZMODE) {
            z0 = z[m0 + r0];
            z1 = z[m0 + r0 + 8];
        }
#pragma unroll
        for (int ni = 0; ni < 8; ni++) {
            int c = wn * 64 + ni * 8 + (lane & 3) * 2;
            float b0 = bias[n0 + c], b1 = bias[n0 + c + 1];
            if (bias2) { b0 += bias2[n0 + c]; b1 += bias2[n0 + c + 1]; }
            float v0 = acc[mi][ni][0] + b0;
            float v1 = acc[mi][ni][1] + b1;
            float v2 = acc[mi][ni][2] + b0;
            float v3 = acc[mi][ni][3] + b1;
            if (ZMODE) {
                v0 += Wzf[(size_t)(n0 + c) * ldw + 512 + z0];
                v1 += Wzf[(size_t)(n0 + c + 1) * ldw + 512 + z0];
                v2 += Wzf[(size_t)(n0 + c) * ldw + 512 + z1];
                v3 += Wzf[(size_t)(n0 + c + 1) * ldw + 512 + z1];
            }
            if (ACT) {
                v0 = v0 > 0.f ? v0 : 0.01f * v0;
                v1 = v1 > 0.f ? v1 : 0.01f * v1;
                v2 = v2 > 0.f ? v2 : 0.01f * v2;
                v3 = v3 > 0.f ? v3 : 0.01f * v3;
            }
            ct[r0 * 132 + c] = v0;
            ct[r0 * 132 + c + 1] = v1;
            ct[(r0 + 8) * 132 + c] = v2;
            ct[(r0 + 8) * 132 + c + 1] = v3;
        }
    }
    __syncthreads();
    {
        int r8 = tid >> 5;
        int c4 = (tid & 31) * 4;
#pragma unroll
        for (int p = 0; p < 16; p++) {
            int r = p * 8 + r8;
            float4 v = *(const float4*)(ct + r * 132 + c4);
            size_t o = (size_t)(m0 + r) * N + n0 + c4;
            if (OUTSPLIT) {
                uint32_t h0, h1, l0, l1;
                split2(v.x, v.y, h0, l0);
                split2(v.z, v.w, h1, l1);
                *(uint2*)(Chi + o) = make_uint2(h0, h1);
                *(uint2*)(Clo + o) = make_uint2(l0, l1);
            } else {
                *(float4*)(C + o) = v;
            }
        }
    }
}

// ----------------------------------------------------------------------------
// HMMA conv (proven); final layer writes SPLIT bf16 activations
// ----------------------------------------------------------------------------
#define PSTR 48
#define IMG_BYTES (400 * PSTR)
#define CW_OFF   (2 * IMG_BYTES)
#define CW_HALF  12800

template <int KS, int P, int LAST>
__device__ __forceinline__ void conv_hmma_layer(
    uint8_t* csm, uint32_t sbase, const __nv_bfloat16* wsrc_h,
    const __nv_bfloat16* wsrc_l, const float* __restrict__ bias,
    __nv_bfloat16* goh, __nv_bfloat16* gol, int tid, int lane, int wid) {
    const int taps = KS * KS;
    {
        const uint4* sh = (const uint4*)wsrc_h;
        const uint4* sl = (const uint4*)wsrc_l;
        uint4* dh = (uint4*)(csm + CW_OFF);
        uint4* dl = (uint4*)(csm + CW_OFF + CW_HALF);
        for (int i = tid; i < taps * 32; i += 256) {
            dh[i] = sh[i];
            dl[i] = sl[i];
        }
    }
    __syncthreads();

    float acc[2][2][4];
#pragma unroll
    for (int a = 0; a < 2; a++)
#pragma unroll
        for (int b = 0; b < 2; b++)
#pragma unroll
            for (int q = 0; q < 4; q++) acc[a][b][q] = 0.f;

    int g = lane >> 3;
    int h0 = wid * 2;
    uint32_t aoff[2];
#pragma unroll
    for (int mi = 0; mi < 2; mi++)
        aoff[mi] = (uint32_t)(((h0 + mi + 2) * 20 + 2 + (lane & 7) + (g & 1) * 8) * PSTR +
                              (g >> 1) * 16);
    uint32_t boff = (uint32_t)(((lane & 7) + (g >> 1) * 8) * 32 + (g & 1) * 16);
    uint32_t wb_h = sbase + CW_OFF;
    uint32_t wb_l = sbase + CW_OFF + CW_HALF;

#pragma unroll
    for (int kh = 0; kh < KS; kh++) {
#pragma unroll
        for (int kw = 0; kw < KS; kw++) {
            int t = kh * KS + kw;
            int shift = ((kh - P) * 20 + (kw - P)) * PSTR;
            uint32_t bh4[4], bl4[4];
            ldsm4(wb_h + t * 512 + boff, bh4);
            ldsm4(wb_l + t * 512 + boff, bl4);
#pragma unroll
            for (int mi = 0; mi < 2; mi++) {
                uint32_t ah[4], al[4];
                ldsm4(sbase + aoff[mi] + shift, ah);
                ldsm4(sbase + IMG_BYTES + aoff[mi] + shift, al);
#pragma unroll
                for (int nh = 0; nh < 2; nh++) {
                    mma16816(acc[mi][nh], ah, &bh4[nh * 2]);
                    mma16816(acc[mi][nh], ah, &bl4[nh * 2]);
                    mma16816(acc[mi][nh], al, &bh4[nh * 2]);
                }
            }
        }
    }
    __syncthreads();

#pragma unroll
    for (int mi = 0; mi < 2; mi++) {
        int h = h0 + mi;
#pragma unroll
        for (int nh = 0; nh < 2; nh++) {
            int co = nh * 8 + (lane & 3) * 2;
            float b0 = bias[co], b1 = bias[co + 1];
#pragma unroll
            for (int rr = 0; rr < 2; rr++) {
                int w = (lane >> 2) + rr * 8;
                float v0 = acc[mi][nh][rr * 2 + 0] + b0;
                float v1 = acc[mi][nh][rr * 2 + 1] + b1;
                v0 = v0 > 0.f ? v0 : 0.01f * v0;
                v1 = v1 > 0.f ? v1 : 0.01f * v1;
                if (LAST) {
                    int k0 = co * 256 + h * 16 + w;
                    __nv_bfloat16 hv0 = __float2bfloat16(v0);
                    goh[k0] = hv0;
                    gol[k0] = __float2bfloat16(v0 - __bfloat162float(hv0));
                    __nv_bfloat16 hv1 = __float2bfloat16(v1);
                    goh[k0 + 256] = hv1;
                    gol[k0 + 256] = __float2bfloat16(v1 - __bfloat162float(hv1));
                } else {
                    uint32_t hp, lp;
                    split2(v0, v1, hp, lp);
                    int pb = ((h + 2) * 20 + (w + 2)) * PSTR + co * 2;
                    *(uint32_t*)(csm + pb) = hp;
                    *(uint32_t*)(csm + IMG_BYTES + pb) = lp;
                }
            }
        }
    }
    __syncthreads();
}

__global__ __launch_bounds__(256) void conv3_mma(
    const float* __restrict__ x,
    const float* __restrict__ b1, const float* __restrict__ b2,
    const float* __restrict__ b3) {
    extern __shared__ uint8_t csm[];
    uint32_t sbase = smem_to_u32(csm);
    int tid = threadIdx.x;
    int lane = tid & 31;
    int wid = tid >> 5;
    int img = blockIdx.x;
    const float* xi = x + (size_t)img * 4096;

    for (int i = tid; i < 2 * IMG_BYTES / 4; i += 256)
        ((uint32_t*)csm)[i] = 0;
    __syncthreads();
    for (int i = tid; i < 4096; i += 256) {
        int ci = i >> 8, p = i & 255;
        int h = p >> 4, w = p & 15;
        float v = xi[i];
        __nv_bfloat16 hv = __float2bfloat16(v);
        float lv = v - __bfloat162float(hv);
        int pb = ((h + 2) * 20 + (w + 2)) * PSTR + ci * 2;
        *(__nv_bfloat16*)(csm + pb) = hv;
        *(__nv_bfloat16*)(csm + IMG_BYTES + pb) = __float2bfloat16(lv);
    }
    __syncthreads();

    __nv_bfloat16* goh = g_a1h + (size_t)img * 4096;
    __nv_bfloat16* gol = g_a1l + (size_t)img * 4096;
    conv_hmma_layer<5, 2, 0>(csm, sbase, g_cw1h, g_cw1l, b1, goh, gol, tid, lane, wid);
    conv_hmma_layer<3, 1, 0>(csm, sbase, g_cw2h, g_cw2l, b2, goh, gol, tid, lane, wid);
    conv_hmma_layer<3, 1, 1>(csm, sbase, g_cw3h, g_cw3l, b3, goh, gol, tid, lane, wid);
}

// ----------------------------------------------------------------------------
// Persistent LSTM v5: 64-k slabs (8/step), cp.async depth-3, 4 buffers.
// ----------------------------------------------------------------------------
__device__ __forceinline__ float sigm(float x) { return 1.f / (1.f + expf(-x)); }

#define LW_STR   1040
#define LA_STR   144
#define LS_W_SZ  (2 * 16 * LW_STR)                 // 33280
#define LS_A_OFF LS_W_SZ
#define LS_A_BUF (2 * 128 * LA_STR)                // 36864 (hi+lo)
#define LS_M_OFF (LS_A_OFF + 4 * LS_A_BUF)         // 180736
#define LS_SMEM  (LS_M_OFF + 1024)                 // 181760

__global__ __launch_bounds__(256) void lstm_persist(
    const float* __restrict__ xg, const int* __restrict__ done,
    __nv_bfloat16* __restrict__ hAh, __nv_bfloat16* __restrict__ hAl,
    __nv_bfloat16* __restrict__ hBh, __nv_bfloat16* __restrict__ hBl,
    float* __restrict__ c_st) {
    extern __shared__ uint8_t psm[];
    float* s_m  = (float*)(psm + LS_M_OFF);
    float* s_mn = (float*)(psm + LS_M_OFF + 512);
    uint32_t sbW = smem_to_u32(psm);
    int tid = threadIdx.x, lane = tid & 31, wid = tid >> 5;
    int blk = blockIdx.x;
    int jb4 = blk * 4;

    {
        const uint4* Wh = (const uint4*)(g_wlh + (size_t)blk * 16 * 512);
        const uint4* Wl = (const uint4*)(g_wll + (size_t)blk * 16 * 512);
#pragma unroll
        for (int i = 0; i < 4; i++) {
            int i4 = tid + 256 * i;
            int r = i4 >> 6, q = i4 & 63;
            *(uint4*)(psm + r * LW_STR + q * 16) = Wh[i4];
            *(uint4*)(psm + 16 * LW_STR + r * LW_STR + q * 16) = Wl[i4];
        }
    }

    int r1 = wid * 16 + (lane >> 2);
    int L = lane & 3;
    int gq = lane >> 3;
    uint32_t arow = (uint32_t)((wid * 16 + (lane & 7) + (gq & 1) * 8) * LA_STR +
                               (gq >> 1) * 16);
    uint32_t brow = (uint32_t)(((lane & 7) + (gq >> 1) * 8) * LW_STR + (gq & 1) * 16);

    float creg[2];
#pragma unroll
    for (int rr = 0; rr < 2; rr++)
        creg[rr] = c_st[(size_t)(r1 + rr * 8) * 512 + jb4 + L];
    __syncthreads();

    for (int t = 0; t < T_STEPS; t++) {
        const __nv_bfloat16* hih = (t & 1) ? hBh : hAh;
        const __nv_bfloat16* hil = (t & 1) ? hBl : hAl;
        __nv_bfloat16* hoh = (t & 1) ? hAh : hBh;
        __nv_bfloat16* hol = (t & 1) ? hAl : hBl;

        // 64-k slab stage: 8 CP_ASYNC16/thread
        auto cpa_slab = [&](int s) {
            uint32_t base = sbW + LS_A_OFF + (uint32_t)((s & 3) * LS_A_BUF);
#pragma unroll
            for (int i = 0; i < 4; i++) {
                int idx = tid + 256 * i;
                int r = idx >> 3, ch = idx & 7;
                CP_ASYNC16(base + r * LA_STR + ch * 16,
                           hih + (size_t)r * 512 + s * 64 + ch * 8);
                CP_ASYNC16(base + 128 * LA_STR + r * LA_STR + ch * 16,
                           hil + (size_t)r * 512 + s * 64 + ch * 8);
            }
            CP_COMMIT();
        };

        cpa_slab(0);
        cpa_slab(1);
        cpa_slab(2);

        if (tid < 128) {
            s_m[tid] = done[t * 128 + tid] ? 0.f : 1.f;
            s_mn[tid] = (t + 1 < T_STEPS)
                            ? (done[(t + 1) * 128 + tid] ? 0.f : 1.f) : 1.f;
        }

        float acc[2][4];
#pragma unroll
        for (int pi = 0; pi < 2; pi++)
#pragma unroll
            for (int rr = 0; rr < 2; rr++)
#pragma unroll
                for (int cc = 0; cc < 2; cc++)
                    acc[pi][rr * 2 + cc] = xg[(size_t)(t * 128 + r1 + rr * 8) * 2048 +
                                              (cc + 2 * pi) * 512 + jb4 + L];

        for (int s = 0; s < 8; s++) {
            CP_WAIT2();
            __syncthreads();
            if (s < 5) cpa_slab(s + 3);
            else CP_COMMIT();
            uint32_t sbA = sbW + LS_A_OFF + (uint32_t)((s & 3) * LS_A_BUF);
#pragma unroll
            for (int kk2 = 0; kk2 < 4; kk2++) {
                int kb = kk2 * 32;
                uint32_t ah[4], al[4], bh4[4], bl4[4];
                ldsm4(sbA + arow + kb, ah);
                ldsm4(sbA + 128 * LA_STR + arow + kb, al);
                uint32_t bo = brow + s * 128 + kb;
                ldsm4(sbW + bo, bh4);
                ldsm4(sbW + 16 * LW_STR + bo, bl4);
#pragma unroll
                for (int pi = 0; pi < 2; pi++) {
                    float* d = acc[pi];
                    mma16816(d, ah, &bh4[pi * 2]);
                    mma16816(d, ah, &bl4[pi * 2]);
                    mma16816(d, al, &bh4[pi * 2]);
                }
            }
        }

#pragma unroll
        for (int rr = 0; rr < 2; rr++) {
            int r = r1 + rr * 8;
            float m = s_m[r];
            float mn = s_mn[r];
            int j = jb4 + L;
            float gi = acc[0][rr * 2 + 0];
            float gf = acc[0][rr * 2 + 1];
            float gg = acc[1][rr * 2 + 0];
            float go = acc[1][rr * 2 + 1];
            float cn = sigm(gf) * (creg[rr] * m) + sigm(gi) * tanhf(gg);
            float hn = sigm(go) * tanhf(cn);
            creg[rr] = cn;
            size_t fo = (size_t)(t * 128 + r) * 512 + j;
            __nv_bfloat16 fh = __float2bfloat16(hn);
            g_feath[fo] = fh;
            g_featl[fo] = __float2bfloat16(hn - __bfloat162float(fh));
            float hw = hn * mn;
            __nv_bfloat16 hh = __float2bfloat16(hw);
            hoh[(size_t)r * 512 + j] = hh;
            hol[(size_t)r * 512 + j] = __float2bfloat16(hw - __bfloat162float(hh));
        }
        grid_bar();
    }
}

// ----------------------------------------------------------------------------
// Head: warp per row; actor/critic GEMV + log_softmax/entropy/prob pack.
// ----------------------------------------------------------------------------
__global__ __launch_bounds__(256) void head_kernel(
    const float* __restrict__ lf, const float* __restrict__ aw,
    const float* __restrict__ ab, const float* __restrict__ cw,
    const float* __restrict__ cb, const int* __restrict__ action,
    float* __restrict__ out) {
    int warp = (blockIdx.x * blockDim.x + threadIdx.x) >> 5;
    int lane = threadIdx.x & 31;
    if (warp >= TBTOT) return;
    float4 f = *(const float4*)(lf + (size_t)warp * FE + lane * 4);
    float r[8];
#pragma unroll
    for (int a = 0; a < 7; a++) {
        float4 w = *(const float4*)(aw + a * FE + lane * 4);
        r[a] = f.x * w.x + f.y * w.y + f.z * w.z + f.w * w.w;
    }
    {
        float4 w = *(const float4*)(cw + lane * 4);
        r[7] = f.x * w.x + f.y * w.y + f.z * w.z + f.w * w.w;
    }
#pragma unroll
    for (int a = 0; a < 8; a++)
#pragma unroll
        for (int s = 16; s > 0; s >>= 1)
            r[a] += __shfl_xor_sync(0xffffffffu, r[a], s);

    if (lane == 0) {
        float lg[7];
        float mx = -1e30f;
#pragma unroll
        for (int a = 0; a < 7; a++) {
            lg[a] = r[a] + ab[a];
            mx = fmaxf(mx, lg[a]);
        }
        float se = 0.f;
        float e[7];
#pragma unroll
        for (int a = 0; a < 7; a++) {
            e[a] = expf(lg[a] - mx);
            se += e[a];
        }
        float lse = mx + logf(se);
        float inv = 1.f / se;
        float ent = 0.f;
        float* o = out + (size_t)warp * 10;
#pragma unroll
        for (int a = 0; a < 7; a++) {
            float p = e[a] * inv;
            float lp = lg[a] - lse;
            ent -= p * lp;
            o[3 + a] = p;
        }
        int act = action[warp];
        o[0] = lg[act] - lse;
        o[1] = ent;
        o[2] = r[7] + cb[0];
    }
}

// ----------------------------------------------------------------------------
// Launch
// ----------------------------------------------------------------------------
extern "C" void kernel_launch(void* const* d_in, const int* in_sizes, int n_in,
                              void* d_out, int out_size) {
    const float* x    = (const float*)d_in[0];
    const int* done   = (const int*)d_in[1];
    const int* z      = (const int*)d_in[2];
    const int* action = (const int*)d_in[3];
    const float* h0   = (const float*)d_in[4];
    const float* c0   = (const float*)d_in[5];
    const float* c1w = (const float*)d_in[6];  const float* c1b = (const float*)d_in[7];
    const float* c2w = (const float*)d_in[8];  const float* c2b = (const float*)d_in[9];
    const float* c3w = (const float*)d_in[10]; const float* c3b = (const float*)d_in[11];
    const float* fc1w = (const float*)d_in[12]; const float* fc1b = (const float*)d_in[13];
    const float* fc2w = (const float*)d_in[14]; const float* fc2b = (const float*)d_in[15];
    const float* wih = (const float*)d_in[16]; const float* whh = (const float*)d_in[17];
    const float* bih = (const float*)d_in[18]; const float* bhh = (const float*)d_in[19];
    const float* lfw = (const float*)d_in[20]; const float* lfb = (const float*)d_in[21];
    const float* aw = (const float*)d_in[22];  const float* ab = (const float*)d_in[23];
    const float* cw = (const float*)d_in[24];  const float* cb = (const float*)d_in[25];
    float* out = (float*)d_out;

    float *pxg, *plf, *pcst;
    __nv_bfloat16 *pa1h, *pa1l, *ph1h, *ph1l, *ph2h, *ph2l, *pfh, *pfl;
    __nv_bfloat16 *pw1h, *pw1l, *pw2h, *pw2l, *pwih_h, *pwih_l, *pwlfh, *pwlfl;
    __nv_bfloat16 *phhA, *phlA, *phhB, *phlB;
    cudaGetSymbolAddress((void**)&pa1h, g_a1h);
    cudaGetSymbolAddress((void**)&pa1l, g_a1l);
    cudaGetSymbolAddress((void**)&ph1h, g_h1h);
    cudaGetSymbolAddress((void**)&ph1l, g_h1l);
    cudaGetSymbolAddress((void**)&ph2h, g_h2h);
    cudaGetSymbolAddress((void**)&ph2l, g_h2l);
    cudaGetSymbolAddress((void**)&pxg, g_xg);
    cudaGetSymbolAddress((void**)&pfh, g_feath);
    cudaGetSymbolAddress((void**)&pfl, g_featl);
    cudaGetSymbolAddress((void**)&plf, g_lf);
    cudaGetSymbolAddress((void**)&pcst, g_cst);
    cudaGetSymbolAddress((void**)&phhA, g_hhA);
    cudaGetSymbolAddress((void**)&phlA, g_hlA);
    cudaGetSymbolAddress((void**)&phhB, g_hhB);
    cudaGetSymbolAddress((void**)&phlB, g_hlB);
    cudaGetSymbolAddress((void**)&pw1h, g_wfc1_hi);
    cudaGetSymbolAddress((void**)&pw1l, g_wfc1_lo);
    cudaGetSymbolAddress((void**)&pw2h, g_wfc2_hi);
    cudaGetSymbolAddress((void**)&pw2l, g_wfc2_lo);
    cudaGetSymbolAddress((void**)&pwih_h, g_wih_hi);
    cudaGetSymbolAddress((void**)&pwih_l, g_wih_lo);
    cudaGetSymbolAddress((void**)&pwlfh, g_wlf_hi);
    cudaGetSymbolAddress((void**)&pwlfl, g_wlf_lo);

    cudaFuncSetAttribute(tgemm2<1, 1, 0>, cudaFuncAttributeMaxDynamicSharedMemorySize, TG_SMEM);
    cudaFuncSetAttribute(tgemm2<0, 0, 0>, cudaFuncAttributeMaxDynamicSharedMemorySize, TG_SMEM);
    cudaFuncSetAttribute(tgemm2<1, 0, 1>, cudaFuncAttributeMaxDynamicSharedMemorySize, TG_SMEM);
    const int SMEM_CONV = 2 * IMG_BYTES + 2 * CW_HALF;
    cudaFuncSetAttribute(conv3_mma, cudaFuncAttributeMaxDynamicSharedMemorySize, SMEM_CONV);
    cudaFuncSetAttribute(lstm_persist, cudaFuncAttributeMaxDynamicSharedMemorySize, LS_SMEM);

    // launches ordered so #6 = tgemm2 fc1 (profiled)
    wcprep_all<<<(11008 + 255) / 256, 256>>>(c1w, c2w, c3w);                 // 1
    wprep<<<(512 * 1024 + 255) / 256, 256>>>(fc1w, pw1h, pw1l, 512 * 1024);  // 2
    wprep<<<(512 * 128 + 255) / 256, 256>>>(fc2w, pw2h, pw2l, 512 * 128);    // 3
    wprep<<<(2048 * 128 + 255) / 256, 256>>>(wih, pwih_h, pwih_l, 2048 * 128); // 4
    conv3_mma<<<TBTOT, 256, SMEM_CONV>>>(x, c1b, c2b, c3b);                  // 5
    tgemm2<1, 1, 0><<<dim3(4, 128), 256, TG_SMEM>>>(                         // 6 <- profiled
        pa1h, pa1l, pw1h, pw1l, fc1b, nullptr,
        nullptr, ph1h, ph1l, nullptr, 0, nullptr, TBTOT, 512, 4096);

    wprep_ld<<<(128 * 128 + 255) / 256, 256>>>(lfw, pwlfh, pwlfl, 128, 520);
    wlstm_prep<<<(2048 * 128 + 255) / 256, 256>>>(whh);
    pack_h0<<<(B_ENV * HID + 255) / 256, 256>>>(h0, done);
    cudaMemcpyAsync(pcst, c0, (size_t)B_ENV * HID * sizeof(float),
                    cudaMemcpyDeviceToDevice, 0);

    tgemm2<1, 1, 0><<<dim3(4, 128), 256, TG_SMEM>>>(
        ph1h, ph1l, pw2h, pw2l, fc2b, nullptr,
        nullptr, ph2h, ph2l, nullptr, 0, nullptr, TBTOT, 512, 512);
    tgemm2<0, 0, 0><<<dim3(16, 128), 256, TG_SMEM>>>(
        ph2h, ph2l, pwih_h, pwih_l, bih, bhh,
        pxg, nullptr, nullptr, nullptr, 0, nullptr, TBTOT, 2048, 512);

    lstm_persist<<<NB_LSTM, 256, LS_SMEM>>>(pxg, done, phhA, phlA, phhB, phlB,
                                            pcst);

    tgemm2<1, 0, 1><<<dim3(1, 128), 256, TG_SMEM>>>(
        pfh, pfl, pwlfh, pwlfl, lfb, nullptr,
        plf, nullptr, nullptr, lfw, 520, z, TBTOT, FE, 512);

    head_kernel<<<TBTOT / 8, 256>>>(plf, aw, ab, cw, cb, action, out);
}